// round 8
// baseline (speedup 1.0000x reference)
#include <cuda_runtime.h>
#include <cuda_bf16.h>
#include <math.h>
#include <stdint.h>

constexpr int cB = 4, cN = 8192, cH = 1024, cNH = 16, cHM = 1024;

// ---------------- scratch (device globals) ----------------
__device__ __nv_bfloat16 g_xh [(size_t)cB * cN * cH];
__device__ __nv_bfloat16 g_xl [(size_t)cB * cN * cH];
__device__ __nv_bfloat16 g_xth[(size_t)cB * cH * cN];
__device__ __nv_bfloat16 g_xtl[(size_t)cB * cH * cN];
__device__ __nv_bfloat16 g_Sh [(size_t)cB * cN * cHM];
__device__ __nv_bfloat16 g_Sl [(size_t)cB * cN * cHM];
__device__ __nv_bfloat16 g_Sth[(size_t)cB * cHM * cN];
__device__ __nv_bfloat16 g_Stl[(size_t)cB * cHM * cN];
__device__ __nv_bfloat16 g_Ath[cHM * cH];
__device__ __nv_bfloat16 g_Atl[cHM * cH];
__device__ __nv_bfloat16 g_Zth[(size_t)cB * cH * cHM];
__device__ __nv_bfloat16 g_Ztl[(size_t)cB * cH * cHM];
__device__ float g_c[cHM];
__device__ float g_Tacc[cB * cN * cNH];           // raw temp logits (atomics)
__device__ float g_norm[cB * cHM];
__device__ float g_yp[(size_t)4 * cB * cHM * cH]; // 4 K-split partials of y
__device__ float g_st[cB * cNH * 64 * 64];
__device__ float g_ost[cB * cNH * 64 * 64];

// ---------------- helpers ----------------
__device__ __forceinline__ uint32_t smem_u32(const void* p) {
    uint32_t a;
    asm("{ .reg .u64 t; cvta.to.shared.u64 t, %1; cvt.u32.u64 %0, t; }" : "=r"(a) : "l"(p));
    return a;
}
__device__ __forceinline__ void cp16(uint32_t s, const void* g) {
    asm volatile("cp.async.cg.shared.global [%0], [%1], 16;" :: "r"(s), "l"(g));
}
#define CP_COMMIT() asm volatile("cp.async.commit_group;" ::: "memory")
#define CP_WAIT1()  asm volatile("cp.async.wait_group 1;" ::: "memory")
#define CP_WAIT0()  asm volatile("cp.async.wait_group 0;" ::: "memory")

__device__ __forceinline__ void ldsm4(uint32_t* r, uint32_t a) {
    asm volatile("ldmatrix.sync.aligned.m8n8.x4.shared.b16 {%0,%1,%2,%3}, [%4];"
        : "=r"(r[0]), "=r"(r[1]), "=r"(r[2]), "=r"(r[3]) : "r"(a));
}
__device__ __forceinline__ void mma16816(float* d, const uint32_t* a,
                                         uint32_t b0, uint32_t b1) {
    asm volatile("mma.sync.aligned.m16n8k16.row.col.f32.bf16.bf16.f32 "
        "{%0,%1,%2,%3}, {%4,%5,%6,%7}, {%8,%9}, {%0,%1,%2,%3};"
        : "+f"(d[0]), "+f"(d[1]), "+f"(d[2]), "+f"(d[3])
        : "r"(a[0]), "r"(a[1]), "r"(a[2]), "r"(a[3]), "r"(b0), "r"(b1));
}
__device__ __forceinline__ void split2(float v, __nv_bfloat16& h, __nv_bfloat16& l) {
    h = __float2bfloat16(v);
    l = __float2bfloat16(v - __bfloat162float(h));
}

// ============ HMMA split-bf16 GEMM: C[m][n] = sum_k A[m][k]*B[n][k] ==========
// CTA tile 128x128, 8 warps (2x4), warp tile 64x32, Kc=64 double-buffered.
// EPI: 0 = plain store, 1 = bias + store, 3 = fused softmax epilogue.
constexpr int T_AH = 0, T_AL = 16384, T_BH = 32768, T_BL = 49152;
constexpr int BUFB = 65536;
constexpr int GSMEM = 2 * BUFB;   // 128 KB

template<int EPI>
__global__ void __launch_bounds__(256, 1)
mma_gemm(const __nv_bfloat16* __restrict__ Ah, const __nv_bfloat16* __restrict__ Al,
         const __nv_bfloat16* __restrict__ Bh, const __nv_bfloat16* __restrict__ Bl,
         float* __restrict__ C, const float* __restrict__ bias,
         const float* __restrict__ tbias,
         int Kdim, int lda, int ldb, int ldc,
         long long sA, long long sB, long long sC, long long sCk, int ksl)
{
    extern __shared__ __align__(128) char smem[];
    const int tid = threadIdx.x, wid = tid >> 5, lane = tid & 31;
    uint32_t sbase = smem_u32(smem);
    const long long zz = blockIdx.z;
    const long long batch = zz >> ksl;
    const long long kidx = zz & ((1 << ksl) - 1);
    Ah += batch * sA + kidx * (long long)Kdim;
    Al += batch * sA + kidx * (long long)Kdim;
    Bh += batch * sB + kidx * (long long)Kdim;
    Bl += batch * sB + kidx * (long long)Kdim;
    C  += batch * sC + kidx * sCk;
    const int m0 = blockIdx.y * 128, n0 = blockIdx.x * 128;

    auto issue = [&](int c) {
        const int kc = c << 6;
        uint32_t sb = sbase + (c & 1) * BUFB;
#pragma unroll
        for (int i = 0; i < 16; i++) {
            const int tile = i >> 2;
            const int idx  = ((i & 3) << 8) + tid;
            const int row  = idx >> 3, seg = idx & 7;
            uint32_t so = sb + tile * 16384 + row * 128 + ((seg ^ (row & 7)) << 4);
            const __nv_bfloat16* gp;
            if (tile == 0)      gp = Ah + (long long)(m0 + row) * lda + kc + seg * 8;
            else if (tile == 1) gp = Al + (long long)(m0 + row) * lda + kc + seg * 8;
            else if (tile == 2) gp = Bh + (long long)(n0 + row) * ldb + kc + seg * 8;
            else                gp = Bl + (long long)(n0 + row) * ldb + kc + seg * 8;
            cp16(so, gp);
        }
        CP_COMMIT();
    };

    const int NC = Kdim >> 6;
    issue(0);

    const int wm = (wid >> 2) * 64, wn = (wid & 3) * 32;
    const int arow  = wm + (lane & 15);
    const int akseg = lane >> 4;
    const int r7a   = arow & 7;
    const int brow  = wn + ((lane >> 4) << 3) + (lane & 7);
    const int bkseg = (lane >> 3) & 1;
    const int r7b   = brow & 7;

    float acc[4][4][4];
#pragma unroll
    for (int a = 0; a < 4; a++)
#pragma unroll
        for (int b = 0; b < 4; b++)
#pragma unroll
            for (int q = 0; q < 4; q++) acc[a][b][q] = 0.f;

    for (int c = 0; c < NC; c++) {
        if (c + 1 < NC) { issue(c + 1); CP_WAIT1(); } else { CP_WAIT0(); }
        __syncthreads();
        uint32_t sb = sbase + (c & 1) * BUFB;
#pragma unroll
        for (int ks = 0; ks < 4; ks++) {
            const int ks2 = ks * 2;
            uint32_t ah[4][4], alr[4][4], bh[2][4], bl[2][4];
#pragma unroll
            for (int mt = 0; mt < 4; mt++) {
                uint32_t ao = sb + T_AH + (arow + mt * 16) * 128
                            + (uint32_t)((((ks2 + akseg) ^ r7a)) << 4);
                ldsm4(ah[mt], ao);
                ldsm4(alr[mt], ao + (T_AL - T_AH));
            }
#pragma unroll
            for (int np = 0; np < 2; np++) {
                uint32_t bo = sb + T_BH + (brow + np * 16) * 128
                            + (uint32_t)((((ks2 + bkseg) ^ r7b)) << 4);
                ldsm4(bh[np], bo);
                ldsm4(bl[np], bo + (T_BL - T_BH));
            }
#pragma unroll
            for (int mt = 0; mt < 4; mt++)
#pragma unroll
                for (int nt = 0; nt < 4; nt++) {
                    const int np = nt >> 1, hb = (nt & 1) * 2;
                    mma16816(acc[mt][nt], ah[mt],  bh[np][hb], bh[np][hb + 1]);
                    mma16816(acc[mt][nt], ah[mt],  bl[np][hb], bl[np][hb + 1]);
                    mma16816(acc[mt][nt], alr[mt], bh[np][hb], bh[np][hb + 1]);
                }
        }
        __syncthreads();
    }

    const int rr = lane >> 2, cc = (lane & 3) * 2;

    if constexpr (EPI == 0 || EPI == 1) {
#pragma unroll
        for (int mt = 0; mt < 4; mt++) {
            const long long m = m0 + wm + mt * 16 + rr;
#pragma unroll
            for (int nt = 0; nt < 4; nt++) {
                const int n = n0 + wn + nt * 8 + cc;
                float bx = 0.f, by = 0.f;
                if (EPI == 1) {
                    float2 b2 = *(const float2*)(bias + n);
                    bx = b2.x; by = b2.y;
                }
                float2 v0 = make_float2(acc[mt][nt][0] + bx, acc[mt][nt][1] + by);
                float2 v1 = make_float2(acc[mt][nt][2] + bx, acc[mt][nt][3] + by);
                *(float2*)(C + m * ldc + n)       = v0;
                *(float2*)(C + (m + 8) * ldc + n) = v1;
            }
        }
    } else {
        // ---- EPI == 3: fused temp-softplus + softmax over m + norm + splits ----
        float* sf = (float*)smem;               // 128 x 133 fp32 tile
#pragma unroll
        for (int mt = 0; mt < 4; mt++) {
#pragma unroll
            for (int nt = 0; nt < 4; nt++) {
                int r = wm + mt * 16 + rr;
                int col = wn + nt * 8 + cc;
                float2 b2 = *(const float2*)(bias + n0 + col);
                sf[r * 133 + col]           = acc[mt][nt][0] + b2.x;
                sf[r * 133 + col + 1]       = acc[mt][nt][1] + b2.y;
                sf[(r + 8) * 133 + col]     = acc[mt][nt][2] + b2.x;
                sf[(r + 8) * 133 + col + 1] = acc[mt][nt][3] + b2.y;
            }
        }
        __syncthreads();
        {
            int row = tid & 127, hl = tid >> 7;
            size_t bn = (size_t)m0 + row;
            int headg = (n0 >> 6) + hl;
            float ta = g_Tacc[bn * 16 + headg] + tbias[headg];
            float sp = fmaxf(ta, 0.f) + log1pf(expf(-fabsf(ta)));
            float inv_t = 1.0f / (0.5f + sp);
            float* rp = sf + row * 133 + hl * 64;
            float mx = -1e30f;
#pragma unroll 8
            for (int i = 0; i < 64; i++) mx = fmaxf(mx, rp[i]);
            float sum = 0.f;
#pragma unroll 8
            for (int i = 0; i < 64; i++) {
                float e = expf((rp[i] - mx) * inv_t);
                rp[i] = e; sum += e;
            }
            float inv = 1.0f / sum;
#pragma unroll 8
            for (int i = 0; i < 64; i++) rp[i] *= inv;
        }
        __syncthreads();
        const int bidx = m0 >> 13;
        {
            int col = tid & 127, half = tid >> 7;
            float s = 0.f;
#pragma unroll 8
            for (int i = 0; i < 64; i++) s += sf[(half * 64 + i) * 133 + col];
            float* snorm = sf + 128 * 133;
            snorm[half * 128 + col] = s;
            __syncthreads();
            if (tid < 128)
                atomicAdd(&g_norm[bidx * 1024 + n0 + tid], snorm[tid] + snorm[128 + tid]);
        }
#pragma unroll
        for (int i = 0; i < 32; i++) {
            int p = i * 256 + tid;
            int row = p >> 6, col = (p & 63) << 1;
            float w0 = sf[row * 133 + col], w1 = sf[row * 133 + col + 1];
            __nv_bfloat16 h0, l0, h1, l1;
            split2(w0, h0, l0); split2(w1, h1, l1);
            size_t o = ((size_t)m0 + row) * 1024 + n0 + col;
            *(__nv_bfloat162*)(g_Sh + o) = __nv_bfloat162(h0, h1);
            *(__nv_bfloat162*)(g_Sl + o) = __nv_bfloat162(l0, l1);
        }
        {
            int nb = m0 & 8191;
#pragma unroll
            for (int i = 0; i < 32; i++) {
                int p = i * 256 + tid;
                int hm = p >> 6, n2 = (p & 63) << 1;
                float w0 = sf[n2 * 133 + hm], w1 = sf[(n2 + 1) * 133 + hm];
                __nv_bfloat16 h0, l0, h1, l1;
                split2(w0, h0, l0); split2(w1, h1, l1);
                size_t o = ((size_t)bidx * 1024 + n0 + hm) * 8192 + nb + n2;
                *(__nv_bfloat162*)(g_Sth + o) = __nv_bfloat162(h0, h1);
                *(__nv_bfloat162*)(g_Stl + o) = __nv_bfloat162(l0, l1);
            }
        }
    }
}

// ============ aux kernels ============
__global__ void __launch_bounds__(256)
k_zero()
{
    int i = blockIdx.x * 256 + threadIdx.x;           // 512 blocks
    ((float4*)g_Tacc)[i] = make_float4(0.f, 0.f, 0.f, 0.f);
    if (i < cB * cHM) g_norm[i] = 0.f;
}

__global__ void __launch_bounds__(256)
k_prep(const float* __restrict__ xq, const float* __restrict__ w_kv,
       const float* __restrict__ b_kv)
{
    int idx = blockIdx.x * 256 + threadIdx.x;
    int j = idx >> 10, hm = idx & 1023;
    int hbase = (hm >> 6) << 6;
    const float* xr = xq + (size_t)hm * 64;
    const float* wr = w_kv + (size_t)j * 2048 + hbase;
    float acc = 0.f;
#pragma unroll 8
    for (int d = 0; d < 64; d++) acc += xr[d] * wr[d];
    __nv_bfloat16 h, l; split2(acc, h, l);
    g_Ath[(size_t)hm * 1024 + j] = h;
    g_Atl[(size_t)hm * 1024 + j] = l;
    if (j == 0) {
        const float* br = b_kv + hbase;
        float cc = 0.f;
        for (int d = 0; d < 64; d++) cc += xr[d] * br[d];
        g_c[hm] = cc;
    }
}

// x -> (xh,xl) + (xth,xtl) transposed + temperature partial accumulation
__global__ void __launch_bounds__(256)
k_convx(const float* __restrict__ x, const float* __restrict__ w_temp)
{
    __shared__ __nv_bfloat16 sh[64][72];
    __shared__ __nv_bfloat16 sl[64][72];
    int jt = blockIdx.x, nt = blockIdx.y;
    int t = threadIdx.x;
    int r = t >> 2, c0 = (t & 3) * 16;
    size_t bn = (size_t)nt * 64 + r;
    const float* xr = x + bn * 1024 + jt * 64 + c0;
    __nv_bfloat16* dh = g_xh + bn * 1024 + jt * 64 + c0;
    __nv_bfloat16* dl = g_xl + bn * 1024 + jt * 64 + c0;
    float tacc[16];
#pragma unroll
    for (int h = 0; h < 16; h++) tacc[h] = 0.f;
#pragma unroll
    for (int i = 0; i < 16; i += 2) {
        float2 v = *(const float2*)(xr + i);
        __nv_bfloat16 h0, l0, h1, l1;
        split2(v.x, h0, l0); split2(v.y, h1, l1);
        *(__nv_bfloat162*)(dh + i) = __nv_bfloat162(h0, h1);
        *(__nv_bfloat162*)(dl + i) = __nv_bfloat162(l0, l1);
        sh[r][c0 + i] = h0; sh[r][c0 + i + 1] = h1;
        sl[r][c0 + i] = l0; sl[r][c0 + i + 1] = l1;
        const float* wt = w_temp + (size_t)(jt * 64 + c0 + i) * 16;
#pragma unroll
        for (int h4 = 0; h4 < 4; h4++) {
            float4 w0 = *(const float4*)(wt + h4 * 4);
            float4 w1 = *(const float4*)(wt + 16 + h4 * 4);
            tacc[h4 * 4 + 0] += v.x * w0.x + v.y * w1.x;
            tacc[h4 * 4 + 1] += v.x * w0.y + v.y * w1.y;
            tacc[h4 * 4 + 2] += v.x * w0.z + v.y * w1.z;
            tacc[h4 * 4 + 3] += v.x * w0.w + v.y * w1.w;
        }
    }
#pragma unroll
    for (int h = 0; h < 16; h++) {
        tacc[h] += __shfl_down_sync(0xffffffffu, tacc[h], 2, 4);
        tacc[h] += __shfl_down_sync(0xffffffffu, tacc[h], 1, 4);
    }
    if ((t & 3) == 0) {
        float* tp = g_Tacc + bn * 16;
#pragma unroll
        for (int h = 0; h < 16; h++) atomicAdd(tp + h, tacc[h]);
    }
    __syncthreads();
    int b = (nt * 64) >> 13, nn0 = (nt * 64) & 8191;
    __nv_bfloat16* th = g_xth + ((size_t)(b * 1024 + jt * 64 + r)) * 8192 + nn0 + c0;
    __nv_bfloat16* tl = g_xtl + ((size_t)(b * 1024 + jt * 64 + r)) * 8192 + nn0 + c0;
#pragma unroll
    for (int i = 0; i < 16; i += 2) {
        *(__nv_bfloat162*)(th + i) = __nv_bfloat162(sh[c0 + i][r], sh[c0 + i + 1][r]);
        *(__nv_bfloat162*)(tl + i) = __nv_bfloat162(sl[c0 + i][r], sl[c0 + i + 1][r]);
    }
}

// slice_token from 4 y-partials
__global__ void __launch_bounds__(256)
k_st(const float* __restrict__ w_kv, const float* __restrict__ b_kv)
{
    int z = blockIdx.x;
    int b = z >> 4, h = z & 15;
    constexpr size_t YPS = (size_t)cB * cHM * cH;
    const float* Yb = g_yp + ((size_t)b * 1024 + h * 64) * 1024;
    const float* Wv = w_kv + 1024 + h * 64;
    __shared__ float As[16][64];
    __shared__ float Bs[16][64];
    int t = threadIdx.x;
    int tyy = t >> 4, txx = t & 15;
    float acc[4][4] = {};
    for (int k0 = 0; k0 < 1024; k0 += 16) {
        {
            int m = t >> 2, k4 = (t & 3) << 2;
            size_t off = (size_t)m * 1024 + k0 + k4;
            float4 v0 = *(const float4*)(Yb + off);
            float4 v1 = *(const float4*)(Yb + YPS + off);
            float4 v2 = *(const float4*)(Yb + 2 * YPS + off);
            float4 v3 = *(const float4*)(Yb + 3 * YPS + off);
            As[k4 + 0][m] = v0.x + v1.x + v2.x + v3.x;
            As[k4 + 1][m] = v0.y + v1.y + v2.y + v3.y;
            As[k4 + 2][m] = v0.z + v1.z + v2.z + v3.z;
            As[k4 + 3][m] = v0.w + v1.w + v2.w + v3.w;
        }
        {
            int k = t >> 4, n4 = (t & 15) << 2;
            *(float4*)&Bs[k][n4] = *(const float4*)(Wv + (size_t)(k0 + k) * 2048 + n4);
        }
        __syncthreads();
#pragma unroll
        for (int kk = 0; kk < 16; kk++) {
            float4 a  = *(const float4*)&As[kk][tyy * 4];
            float4 bb = *(const float4*)&Bs[kk][txx * 4];
            float av[4] = {a.x, a.y, a.z, a.w};
            float bv[4] = {bb.x, bb.y, bb.z, bb.w};
#pragma unroll
            for (int i = 0; i < 4; i++)
#pragma unroll
                for (int jj = 0; jj < 4; jj++) acc[i][jj] += av[i] * bv[jj];
        }
        __syncthreads();
    }
#pragma unroll
    for (int i = 0; i < 4; i++) {
        int m = tyy * 4 + i;
        float nrm = g_norm[b * 1024 + h * 64 + m];
        float inv = 1.0f / (nrm + 1e-5f);
#pragma unroll
        for (int jj = 0; jj < 4; jj++) {
            int d = txx * 4 + jj;
            float bvv = b_kv[1024 + h * 64 + d];
            g_st[((size_t)z * 64 + m) * 64 + d] = (acc[i][jj] + nrm * bvv) * inv;
        }
    }
}

__global__ void __launch_bounds__(64)
k_qkv(const float* __restrict__ qkv_proj)
{
    int z = blockIdx.x;
    int h = (z >> 6) & 15;
    int d = threadIdx.x;
    __shared__ float st[64];
    __shared__ float ex[64];
    st[d] = g_st[(size_t)z * 64 + d];
    __syncthreads();
    const float* P = qkv_proj + (size_t)h * 64 * 192;
    float q = 0.f, k = 0.f, v = 0.f;
#pragma unroll 8
    for (int j = 0; j < 64; j++) {
        float s = st[j];
        const float* pr = P + j * 192;
        q += s * pr[d]; k += s * pr[64 + d]; v += s * pr[128 + d];
    }
    float dot = q * k * 0.125f;
    ex[d] = dot;
    __syncthreads();
    float mx = -1e30f;
    for (int j = 0; j < 64; j++) mx = fmaxf(mx, ex[j]);
    __syncthreads();
    float e = expf(dot - mx);
    ex[d] = e;
    __syncthreads();
    float sum = 0.f;
    for (int j = 0; j < 64; j++) sum += ex[j];
    g_ost[(size_t)z * 64 + d] = (e / sum) * v;
}

__global__ void __launch_bounds__(256)
k_zmat(const float* __restrict__ w_out)
{
    int z = blockIdx.y, jc = blockIdx.x;
    int b = z >> 4, h = z & 15;
    __shared__ float As[64][64];
    __shared__ float Bs[64][64];
    int t = threadIdx.x;
#pragma unroll
    for (int r = 0; r < 4; r++) {
        int lin = t + r * 256;
        int row = lin >> 4;
        int c4  = (lin & 15) << 2;
        float4 v = *(const float4*)(g_ost + ((size_t)z * 64 + row) * 64 + c4);
        As[c4 + 0][row] = v.x; As[c4 + 1][row] = v.y;
        As[c4 + 2][row] = v.z; As[c4 + 3][row] = v.w;
        *(float4*)&Bs[row][c4] =
            *(const float4*)(w_out + (size_t)(h * 64 + row) * 1024 + jc * 64 + c4);
    }
    __syncthreads();
    int tyy = t >> 4, txx = t & 15;
    float acc[4][4] = {};
#pragma unroll
    for (int kk = 0; kk < 64; kk++) {
        float4 a  = *(const float4*)&As[kk][tyy * 4];
        float4 bb = *(const float4*)&Bs[kk][txx * 4];
        float av[4] = {a.x, a.y, a.z, a.w};
        float bv[4] = {bb.x, bb.y, bb.z, bb.w};
#pragma unroll
        for (int i = 0; i < 4; i++)
#pragma unroll
            for (int jj = 0; jj < 4; jj++) acc[i][jj] += av[i] * bv[jj];
    }
#pragma unroll
    for (int i = 0; i < 4; i++) {
        int hm = h * 64 + tyy * 4 + i;
#pragma unroll
        for (int jj = 0; jj < 4; jj++) {
            int j = jc * 64 + txx * 4 + jj;
            __nv_bfloat16 hh, ll; split2(acc[i][jj], hh, ll);
            size_t o = ((size_t)b * 1024 + j) * 1024 + hm;
            g_Zth[o] = hh; g_Ztl[o] = ll;
        }
    }
}

// ---------------------------------------------------------------------------
extern "C" void kernel_launch(void* const* d_in, const int* in_sizes, int n_in,
                              void* d_out, int out_size)
{
    (void)in_sizes; (void)n_in; (void)out_size;
    const float* x      = (const float*)d_in[0];
    const float* w_kv   = (const float*)d_in[2];
    const float* b_kv   = (const float*)d_in[3];
    const float* w_temp = (const float*)d_in[4];
    const float* b_temp = (const float*)d_in[5];
    const float* xq     = (const float*)d_in[6];
    const float* qkv_p  = (const float*)d_in[7];
    const float* w_out  = (const float*)d_in[8];
    const float* b_out  = (const float*)d_in[9];
    float* out = (float*)d_out;

    float *pc, *pyp;
    __nv_bfloat16 *pxh, *pxl, *pxth, *pxtl, *pSh, *pSl, *pSth, *pStl, *pAth, *pAtl, *pZth, *pZtl;
    cudaGetSymbolAddress((void**)&pc,  g_c);
    cudaGetSymbolAddress((void**)&pyp, g_yp);
    cudaGetSymbolAddress((void**)&pxh, g_xh);   cudaGetSymbolAddress((void**)&pxl, g_xl);
    cudaGetSymbolAddress((void**)&pxth, g_xth); cudaGetSymbolAddress((void**)&pxtl, g_xtl);
    cudaGetSymbolAddress((void**)&pSh, g_Sh);   cudaGetSymbolAddress((void**)&pSl, g_Sl);
    cudaGetSymbolAddress((void**)&pSth, g_Sth); cudaGetSymbolAddress((void**)&pStl, g_Stl);
    cudaGetSymbolAddress((void**)&pAth, g_Ath); cudaGetSymbolAddress((void**)&pAtl, g_Atl);
    cudaGetSymbolAddress((void**)&pZth, g_Zth); cudaGetSymbolAddress((void**)&pZtl, g_Ztl);

    cudaFuncSetAttribute(mma_gemm<0>, cudaFuncAttributeMaxDynamicSharedMemorySize, GSMEM);
    cudaFuncSetAttribute(mma_gemm<1>, cudaFuncAttributeMaxDynamicSharedMemorySize, GSMEM);
    cudaFuncSetAttribute(mma_gemm<3>, cudaFuncAttributeMaxDynamicSharedMemorySize, GSMEM);

    k_zero<<<512, 256>>>();
    k_prep<<<4096, 256>>>(xq, w_kv, b_kv);
    k_convx<<<dim3(16, 512), 256>>>(x, w_temp);
    // scores + fused softplus/softmax/norm/split (M=32768,N=1024,K=1024)
    mma_gemm<3><<<dim3(8, 256, 1), 256, GSMEM>>>(
        pxh, pxl, pAth, pAtl, nullptr, pc, b_temp,
        1024, 1024, 1024, 0, 0, 0, 0, 0, 0);
    // y[b] = S[b]^T @ x[b] (M=1024,N=1024,K=8192), K-split x4, partial buffers
    mma_gemm<0><<<dim3(8, 8, cB * 4), 256, GSMEM>>>(
        pSth, pStl, pxth, pxtl, pyp, nullptr, nullptr,
        2048, 8192, 8192, 1024,
        (long long)cHM * cN, (long long)cH * cN,
        (long long)cHM * cH, (long long)cB * cHM * cH, 2);
    k_st<<<cB * cNH, 256>>>(w_kv, b_kv);
    k_qkv<<<cB * cNH * 64, 64>>>(qkv_p);
    k_zmat<<<dim3(16, cB * cNH), 256>>>(w_out);
    // out[b] = S[b] @ Zt[b]^T + b_out (M=8192,N=1024,K=1024)
    mma_gemm<1><<<dim3(8, 64, cB), 256, GSMEM>>>(
        pSh, pSl, pZth, pZtl, out, b_out, nullptr,
        1024, 1024, 1024, 1024,
        (long long)cN * cHM, (long long)cH * cHM,
        (long long)cN * cH, 0, 0);
}

// round 9
// speedup vs baseline: 1.0844x; 1.0844x over previous
#include <cuda_runtime.h>
#include <cuda_bf16.h>
#include <math.h>
#include <stdint.h>

constexpr int cB = 4, cN = 8192, cH = 1024, cNH = 16, cHM = 1024;

// ---------------- scratch (device globals) ----------------
__device__ __nv_bfloat16 g_xh [(size_t)cB * cN * cH];
__device__ __nv_bfloat16 g_xl [(size_t)cB * cN * cH];
__device__ __nv_bfloat16 g_xth[(size_t)cB * cH * cN];
__device__ __nv_bfloat16 g_xtl[(size_t)cB * cH * cN];
__device__ __nv_bfloat16 g_Sh [(size_t)cB * cN * cHM];
__device__ __nv_bfloat16 g_Sl [(size_t)cB * cN * cHM];
__device__ __nv_bfloat16 g_Sth[(size_t)cB * cHM * cN];
__device__ __nv_bfloat16 g_Stl[(size_t)cB * cHM * cN];
__device__ __nv_bfloat16 g_Ath[cHM * cH];
__device__ __nv_bfloat16 g_Atl[cHM * cH];
__device__ __nv_bfloat16 g_Zth[(size_t)cB * cH * cHM];
__device__ __nv_bfloat16 g_Ztl[(size_t)cB * cH * cHM];
__device__ __nv_bfloat16 g_wth[cNH * cH];          // w_temp^T hi  [16][1024]
__device__ __nv_bfloat16 g_wtl[cNH * cH];          // w_temp^T lo
__device__ float g_c[cHM];
__device__ float g_T[cB * cN * cNH];               // final temperature
__device__ float g_norm[cB * cHM];
__device__ float g_yp[(size_t)4 * cB * cHM * cH];  // 4 K-split partials of y
__device__ float g_st[cB * cNH * 64 * 64];
__device__ float g_ost[cB * cNH * 64 * 64];

// ---------------- helpers ----------------
__device__ __forceinline__ uint32_t smem_u32(const void* p) {
    uint32_t a;
    asm("{ .reg .u64 t; cvta.to.shared.u64 t, %1; cvt.u32.u64 %0, t; }" : "=r"(a) : "l"(p));
    return a;
}
__device__ __forceinline__ void cp16(uint32_t s, const void* g) {
    asm volatile("cp.async.cg.shared.global [%0], [%1], 16;" :: "r"(s), "l"(g));
}
#define CP_COMMIT() asm volatile("cp.async.commit_group;" ::: "memory")
#define CP_WAIT1()  asm volatile("cp.async.wait_group 1;" ::: "memory")
#define CP_WAIT0()  asm volatile("cp.async.wait_group 0;" ::: "memory")

__device__ __forceinline__ void ldsm4(uint32_t* r, uint32_t a) {
    asm volatile("ldmatrix.sync.aligned.m8n8.x4.shared.b16 {%0,%1,%2,%3}, [%4];"
        : "=r"(r[0]), "=r"(r[1]), "=r"(r[2]), "=r"(r[3]) : "r"(a));
}
__device__ __forceinline__ void mma16816(float* d, const uint32_t* a,
                                         uint32_t b0, uint32_t b1) {
    asm volatile("mma.sync.aligned.m16n8k16.row.col.f32.bf16.bf16.f32 "
        "{%0,%1,%2,%3}, {%4,%5,%6,%7}, {%8,%9}, {%0,%1,%2,%3};"
        : "+f"(d[0]), "+f"(d[1]), "+f"(d[2]), "+f"(d[3])
        : "r"(a[0]), "r"(a[1]), "r"(a[2]), "r"(a[3]), "r"(b0), "r"(b1));
}
__device__ __forceinline__ void split2(float v, __nv_bfloat16& h, __nv_bfloat16& l) {
    h = __float2bfloat16(v);
    l = __float2bfloat16(v - __bfloat162float(h));
}

// ============ HMMA split-bf16 GEMM: C[m][n] = sum_k A[m][k]*B[n][k] ==========
// CTA tile 128x128, 8 warps (2x4), warp tile 64x32, Kc=64 double-buffered.
// EPI: 0 = plain store (K-split partials), 1 = bias + store, 3 = fused softmax.
constexpr int T_AH = 0, T_AL = 16384, T_BH = 32768, T_BL = 49152;
constexpr int BUFB = 65536;
constexpr int GSMEM = 2 * BUFB;   // 128 KB

template<int EPI>
__global__ void __launch_bounds__(256, 1)
mma_gemm(const __nv_bfloat16* __restrict__ Ah, const __nv_bfloat16* __restrict__ Al,
         const __nv_bfloat16* __restrict__ Bh, const __nv_bfloat16* __restrict__ Bl,
         float* __restrict__ C, const float* __restrict__ bias,
         int Kdim, int lda, int ldb, int ldc,
         long long sA, long long sB, long long sC, long long sCk, int ksl)
{
    extern __shared__ __align__(128) char smem[];
    const int tid = threadIdx.x, wid = tid >> 5, lane = tid & 31;
    uint32_t sbase = smem_u32(smem);
    const long long zz = blockIdx.z;
    const long long batch = zz >> ksl;
    const long long kidx = zz & ((1 << ksl) - 1);
    Ah += batch * sA + kidx * (long long)Kdim;
    Al += batch * sA + kidx * (long long)Kdim;
    Bh += batch * sB + kidx * (long long)Kdim;
    Bl += batch * sB + kidx * (long long)Kdim;
    C  += batch * sC + kidx * sCk;
    const int m0 = blockIdx.y * 128, n0 = blockIdx.x * 128;

    auto issue = [&](int c) {
        const int kc = c << 6;
        uint32_t sb = sbase + (c & 1) * BUFB;
#pragma unroll
        for (int i = 0; i < 16; i++) {
            const int tile = i >> 2;
            const int idx  = ((i & 3) << 8) + tid;
            const int row  = idx >> 3, seg = idx & 7;
            uint32_t so = sb + tile * 16384 + row * 128 + ((seg ^ (row & 7)) << 4);
            const __nv_bfloat16* gp;
            if (tile == 0)      gp = Ah + (long long)(m0 + row) * lda + kc + seg * 8;
            else if (tile == 1) gp = Al + (long long)(m0 + row) * lda + kc + seg * 8;
            else if (tile == 2) gp = Bh + (long long)(n0 + row) * ldb + kc + seg * 8;
            else                gp = Bl + (long long)(n0 + row) * ldb + kc + seg * 8;
            cp16(so, gp);
        }
        CP_COMMIT();
    };

    const int NC = Kdim >> 6;
    issue(0);

    const int wm = (wid >> 2) * 64, wn = (wid & 3) * 32;
    const int arow  = wm + (lane & 15);
    const int akseg = lane >> 4;
    const int r7a   = arow & 7;
    const int brow  = wn + ((lane >> 4) << 3) + (lane & 7);
    const int bkseg = (lane >> 3) & 1;
    const int r7b   = brow & 7;

    float acc[4][4][4];
#pragma unroll
    for (int a = 0; a < 4; a++)
#pragma unroll
        for (int b = 0; b < 4; b++)
#pragma unroll
            for (int q = 0; q < 4; q++) acc[a][b][q] = 0.f;

    for (int c = 0; c < NC; c++) {
        if (c + 1 < NC) { issue(c + 1); CP_WAIT1(); } else { CP_WAIT0(); }
        __syncthreads();
        uint32_t sb = sbase + (c & 1) * BUFB;
#pragma unroll
        for (int ks = 0; ks < 4; ks++) {
            const int ks2 = ks * 2;
            uint32_t ah[4][4], alr[4][4], bh[2][4], bl[2][4];
#pragma unroll
            for (int mt = 0; mt < 4; mt++) {
                uint32_t ao = sb + T_AH + (arow + mt * 16) * 128
                            + (uint32_t)((((ks2 + akseg) ^ r7a)) << 4);
                ldsm4(ah[mt], ao);
                ldsm4(alr[mt], ao + (T_AL - T_AH));
            }
#pragma unroll
            for (int np = 0; np < 2; np++) {
                uint32_t bo = sb + T_BH + (brow + np * 16) * 128
                            + (uint32_t)((((ks2 + bkseg) ^ r7b)) << 4);
                ldsm4(bh[np], bo);
                ldsm4(bl[np], bo + (T_BL - T_BH));
            }
#pragma unroll
            for (int mt = 0; mt < 4; mt++)
#pragma unroll
                for (int nt = 0; nt < 4; nt++) {
                    const int np = nt >> 1, hb = (nt & 1) * 2;
                    mma16816(acc[mt][nt], ah[mt],  bh[np][hb], bh[np][hb + 1]);
                    mma16816(acc[mt][nt], ah[mt],  bl[np][hb], bl[np][hb + 1]);
                    mma16816(acc[mt][nt], alr[mt], bh[np][hb], bh[np][hb + 1]);
                }
        }
        __syncthreads();
    }

    const int rr = lane >> 2, cc = (lane & 3) * 2;

    if constexpr (EPI == 0 || EPI == 1) {
#pragma unroll
        for (int mt = 0; mt < 4; mt++) {
            const long long m = m0 + wm + mt * 16 + rr;
#pragma unroll
            for (int nt = 0; nt < 4; nt++) {
                const int n = n0 + wn + nt * 8 + cc;
                float bx = 0.f, by = 0.f;
                if (EPI == 1) {
                    float2 b2 = *(const float2*)(bias + n);
                    bx = b2.x; by = b2.y;
                }
                float2 v0 = make_float2(acc[mt][nt][0] + bx, acc[mt][nt][1] + by);
                float2 v1 = make_float2(acc[mt][nt][2] + bx, acc[mt][nt][3] + by);
                *(float2*)(C + m * ldc + n)       = v0;
                *(float2*)(C + (m + 8) * ldc + n) = v1;
            }
        }
    } else {
        // ---- EPI == 3: fused softmax over m + norm + dual-layout bf16 split ----
        float* sf = (float*)smem;               // 128 x 133 fp32 tile
#pragma unroll
        for (int mt = 0; mt < 4; mt++) {
#pragma unroll
            for (int nt = 0; nt < 4; nt++) {
                int r = wm + mt * 16 + rr;
                int col = wn + nt * 8 + cc;
                float2 b2 = *(const float2*)(bias + n0 + col);
                sf[r * 133 + col]           = acc[mt][nt][0] + b2.x;
                sf[r * 133 + col + 1]       = acc[mt][nt][1] + b2.y;
                sf[(r + 8) * 133 + col]     = acc[mt][nt][2] + b2.x;
                sf[(r + 8) * 133 + col + 1] = acc[mt][nt][3] + b2.y;
            }
        }
        __syncthreads();
        {
            int row = tid & 127, hl = tid >> 7;
            size_t bn = (size_t)m0 + row;
            int headg = (n0 >> 6) + hl;
            float inv_t = 1.0f / g_T[bn * 16 + headg];
            float* rp = sf + row * 133 + hl * 64;
            float mx = -1e30f;
#pragma unroll 8
            for (int i = 0; i < 64; i++) mx = fmaxf(mx, rp[i]);
            float sum = 0.f;
#pragma unroll 8
            for (int i = 0; i < 64; i++) {
                float e = expf((rp[i] - mx) * inv_t);
                rp[i] = e; sum += e;
            }
            float inv = 1.0f / sum;
#pragma unroll 8
            for (int i = 0; i < 64; i++) rp[i] *= inv;
        }
        __syncthreads();
        const int bidx = m0 >> 13;
        {
            int col = tid & 127, half = tid >> 7;
            float s = 0.f;
#pragma unroll 8
            for (int i = 0; i < 64; i++) s += sf[(half * 64 + i) * 133 + col];
            float* snorm = sf + 128 * 133;
            snorm[half * 128 + col] = s;
            __syncthreads();
            if (tid < 128)
                atomicAdd(&g_norm[bidx * 1024 + n0 + tid], snorm[tid] + snorm[128 + tid]);
        }
#pragma unroll
        for (int i = 0; i < 32; i++) {
            int p = i * 256 + tid;
            int row = p >> 6, col = (p & 63) << 1;
            float w0 = sf[row * 133 + col], w1 = sf[row * 133 + col + 1];
            __nv_bfloat16 h0, l0, h1, l1;
            split2(w0, h0, l0); split2(w1, h1, l1);
            size_t o = ((size_t)m0 + row) * 1024 + n0 + col;
            *(__nv_bfloat162*)(g_Sh + o) = __nv_bfloat162(h0, h1);
            *(__nv_bfloat162*)(g_Sl + o) = __nv_bfloat162(l0, l1);
        }
        {
            int nb = m0 & 8191;
#pragma unroll
            for (int i = 0; i < 32; i++) {
                int p = i * 256 + tid;
                int hm = p >> 6, n2 = (p & 63) << 1;
                float w0 = sf[n2 * 133 + hm], w1 = sf[(n2 + 1) * 133 + hm];
                __nv_bfloat16 h0, l0, h1, l1;
                split2(w0, h0, l0); split2(w1, h1, l1);
                size_t o = ((size_t)bidx * 1024 + n0 + hm) * 8192 + nb + n2;
                *(__nv_bfloat162*)(g_Sth + o) = __nv_bfloat162(h0, h1);
                *(__nv_bfloat162*)(g_Stl + o) = __nv_bfloat162(l0, l1);
            }
        }
    }
}

// ============ temperature GEMM: T = softplus(x @ w_temp + b_temp) + 0.5 ======
// [32768 x 1024] @ [1024 x 16]; A = xh/xl, B = wth/wtl (K-major, [16][1024]).
// Grid 256 CTAs (128 rows each), 8 warps x 16 rows, B fully resident in SMEM.
constexpr int TG_AH = 0, TG_AL = 16384;
constexpr int TG_BUF = 32768;                 // per-buffer size (hi+lo A chunk)
constexpr int TG_BH = 65536, TG_BL = 98304;   // full B hi/lo (32KB each)
constexpr int TGSMEM = 131072;

__global__ void __launch_bounds__(256, 1)
k_tempmma(const __nv_bfloat16* __restrict__ xh, const __nv_bfloat16* __restrict__ xl,
          const float* __restrict__ b_temp)
{
    extern __shared__ __align__(128) char smem[];
    const int tid = threadIdx.x, wid = tid >> 5, lane = tid & 31;
    uint32_t sbase = smem_u32(smem);
    const int m0 = blockIdx.x * 128;

    // load full B (16 rows x 1024 k, hi+lo), chunked layout matching A swizzle
#pragma unroll
    for (int q = 0; q < 8; q++) {
        int i = q * 256 + tid;                 // 0..2047 uint4s
        int c = i >> 7, r = (i >> 3) & 15, seg = i & 7;
        uint32_t so = sbase + TG_BH + c * 2048 + r * 128 + ((seg ^ (r & 7)) << 4);
        const __nv_bfloat16* gh = g_wth + r * 1024 + c * 64 + seg * 8;
        cp16(so, gh);
        cp16(so + (TG_BL - TG_BH), g_wtl + r * 1024 + c * 64 + seg * 8);
    }

    auto issueA = [&](int c) {
        uint32_t sb = sbase + (c & 1) * TG_BUF;
        const int kc = c << 6;
#pragma unroll
        for (int q = 0; q < 4; q++) {
            int i = q * 256 + tid;             // 0..1023
            int row = i >> 3, seg = i & 7;
            uint32_t so = sb + row * 128 + ((seg ^ (row & 7)) << 4);
            cp16(so,                 xh + (long long)(m0 + row) * 1024 + kc + seg * 8);
            cp16(so + (TG_AL - TG_AH), xl + (long long)(m0 + row) * 1024 + kc + seg * 8);
        }
        CP_COMMIT();
    };
    issueA(0);   // group 0 = B + A0

    const int wm = wid * 16;
    const int arow  = wm + (lane & 15);
    const int akseg = lane >> 4;
    const int r7a   = arow & 7;
    const int brow  = ((lane >> 4) << 3) + (lane & 7);   // 0..15
    const int bkseg = (lane >> 3) & 1;
    const int r7b   = brow & 7;

    float acc[2][4];
#pragma unroll
    for (int nt = 0; nt < 2; nt++)
#pragma unroll
        for (int q = 0; q < 4; q++) acc[nt][q] = 0.f;

    for (int c = 0; c < 16; c++) {
        if (c + 1 < 16) { issueA(c + 1); CP_WAIT1(); } else { CP_WAIT0(); }
        __syncthreads();
        uint32_t sa = sbase + (c & 1) * TG_BUF;
        uint32_t sbb = sbase + TG_BH + c * 2048;
#pragma unroll
        for (int ks = 0; ks < 4; ks++) {
            const int ks2 = ks * 2;
            uint32_t ah[4], alr[4], bh[4], bl[4];
            uint32_t ao = sa + arow * 128 + (uint32_t)((((ks2 + akseg) ^ r7a)) << 4);
            ldsm4(ah, ao);
            ldsm4(alr, ao + (TG_AL - TG_AH));
            uint32_t bo = sbb + brow * 128 + (uint32_t)((((ks2 + bkseg) ^ r7b)) << 4);
            ldsm4(bh, bo);
            ldsm4(bl, bo + (TG_BL - TG_BH));
#pragma unroll
            for (int nt = 0; nt < 2; nt++) {
                const int hb = nt * 2;
                mma16816(acc[nt], ah,  bh[hb], bh[hb + 1]);
                mma16816(acc[nt], ah,  bl[hb], bl[hb + 1]);
                mma16816(acc[nt], alr, bh[hb], bh[hb + 1]);
            }
        }
        __syncthreads();
    }

    const int rr = lane >> 2, cc = (lane & 3) * 2;
    const long long r0 = m0 + wm + rr, r1 = r0 + 8;
#pragma unroll
    for (int nt = 0; nt < 2; nt++) {
        int head = nt * 8 + cc;
        float b0 = b_temp[head], b1 = b_temp[head + 1];
        float v[4] = {acc[nt][0] + b0, acc[nt][1] + b1,
                      acc[nt][2] + b0, acc[nt][3] + b1};
#pragma unroll
        for (int q = 0; q < 4; q++) {
            float s = v[q];
            v[q] = 0.5f + fmaxf(s, 0.f) + log1pf(expf(-fabsf(s)));
        }
        g_T[r0 * 16 + head]     = v[0];
        g_T[r0 * 16 + head + 1] = v[1];
        g_T[r1 * 16 + head]     = v[2];
        g_T[r1 * 16 + head + 1] = v[3];
    }
}

// ============ aux kernels ============
__global__ void k_zero()
{
    int i = blockIdx.x * 256 + threadIdx.x;
    if (i < cB * cHM) g_norm[i] = 0.f;
}

// wth[h][j] = hi(w_temp[j][h]); wtl = lo
__global__ void __launch_bounds__(256)
k_wsplit(const float* __restrict__ w_temp)
{
    int idx = blockIdx.x * 256 + threadIdx.x;    // 16384
    int h = idx >> 10, j = idx & 1023;
    __nv_bfloat16 hh, ll;
    split2(w_temp[j * 16 + h], hh, ll);
    g_wth[idx] = hh;
    g_wtl[idx] = ll;
}

__global__ void __launch_bounds__(256)
k_prep(const float* __restrict__ xq, const float* __restrict__ w_kv,
       const float* __restrict__ b_kv)
{
    int idx = blockIdx.x * 256 + threadIdx.x;
    int j = idx >> 10, hm = idx & 1023;
    int hbase = (hm >> 6) << 6;
    const float* xr = xq + (size_t)hm * 64;
    const float* wr = w_kv + (size_t)j * 2048 + hbase;
    float acc = 0.f;
#pragma unroll 8
    for (int d = 0; d < 64; d++) acc += xr[d] * wr[d];
    __nv_bfloat16 h, l; split2(acc, h, l);
    g_Ath[(size_t)hm * 1024 + j] = h;
    g_Atl[(size_t)hm * 1024 + j] = l;
    if (j == 0) {
        const float* br = b_kv + hbase;
        float cc = 0.f;
        for (int d = 0; d < 64; d++) cc += xr[d] * br[d];
        g_c[hm] = cc;
    }
}

// x -> (xh,xl) + (xth,xtl) transposed  (round-6 clean version)
__global__ void __launch_bounds__(256)
k_convx(const float* __restrict__ x)
{
    __shared__ __nv_bfloat16 sh[64][72];
    __shared__ __nv_bfloat16 sl[64][72];
    int jt = blockIdx.x, nt = blockIdx.y;
    int t = threadIdx.x;
    int r = t >> 2, c0 = (t & 3) * 16;
    size_t bn = (size_t)nt * 64 + r;
    const float* xr = x + bn * 1024 + jt * 64 + c0;
    __nv_bfloat16* dh = g_xh + bn * 1024 + jt * 64 + c0;
    __nv_bfloat16* dl = g_xl + bn * 1024 + jt * 64 + c0;
#pragma unroll
    for (int i = 0; i < 16; i += 2) {
        float2 v = *(const float2*)(xr + i);
        __nv_bfloat16 h0, l0, h1, l1;
        split2(v.x, h0, l0); split2(v.y, h1, l1);
        *(__nv_bfloat162*)(dh + i) = __nv_bfloat162(h0, h1);
        *(__nv_bfloat162*)(dl + i) = __nv_bfloat162(l0, l1);
        sh[r][c0 + i] = h0; sh[r][c0 + i + 1] = h1;
        sl[r][c0 + i] = l0; sl[r][c0 + i + 1] = l1;
    }
    __syncthreads();
    int b = (nt * 64) >> 13, nn0 = (nt * 64) & 8191;
    __nv_bfloat16* th = g_xth + ((size_t)(b * 1024 + jt * 64 + r)) * 8192 + nn0 + c0;
    __nv_bfloat16* tl = g_xtl + ((size_t)(b * 1024 + jt * 64 + r)) * 8192 + nn0 + c0;
#pragma unroll
    for (int i = 0; i < 16; i += 2) {
        *(__nv_bfloat162*)(th + i) = __nv_bfloat162(sh[c0 + i][r], sh[c0 + i + 1][r]);
        *(__nv_bfloat162*)(tl + i) = __nv_bfloat162(sl[c0 + i][r], sl[c0 + i + 1][r]);
    }
}

// slice_token from 4 y-partials
__global__ void __launch_bounds__(256)
k_st(const float* __restrict__ w_kv, const float* __restrict__ b_kv)
{
    int z = blockIdx.x;
    int b = z >> 4, h = z & 15;
    constexpr size_t YPS = (size_t)cB * cHM * cH;
    const float* Yb = g_yp + ((size_t)b * 1024 + h * 64) * 1024;
    const float* Wv = w_kv + 1024 + h * 64;
    __shared__ float As[16][64];
    __shared__ float Bs[16][64];
    int t = threadIdx.x;
    int tyy = t >> 4, txx = t & 15;
    float acc[4][4] = {};
    for (int k0 = 0; k0 < 1024; k0 += 16) {
        {
            int m = t >> 2, k4 = (t & 3) << 2;
            size_t off = (size_t)m * 1024 + k0 + k4;
            float4 v0 = *(const float4*)(Yb + off);
            float4 v1 = *(const float4*)(Yb + YPS + off);
            float4 v2 = *(const float4*)(Yb + 2 * YPS + off);
            float4 v3 = *(const float4*)(Yb + 3 * YPS + off);
            As[k4 + 0][m] = v0.x + v1.x + v2.x + v3.x;
            As[k4 + 1][m] = v0.y + v1.y + v2.y + v3.y;
            As[k4 + 2][m] = v0.z + v1.z + v2.z + v3.z;
            As[k4 + 3][m] = v0.w + v1.w + v2.w + v3.w;
        }
        {
            int k = t >> 4, n4 = (t & 15) << 2;
            *(float4*)&Bs[k][n4] = *(const float4*)(Wv + (size_t)(k0 + k) * 2048 + n4);
        }
        __syncthreads();
#pragma unroll
        for (int kk = 0; kk < 16; kk++) {
            float4 a  = *(const float4*)&As[kk][tyy * 4];
            float4 bb = *(const float4*)&Bs[kk][txx * 4];
            float av[4] = {a.x, a.y, a.z, a.w};
            float bv[4] = {bb.x, bb.y, bb.z, bb.w};
#pragma unroll
            for (int i = 0; i < 4; i++)
#pragma unroll
                for (int jj = 0; jj < 4; jj++) acc[i][jj] += av[i] * bv[jj];
        }
        __syncthreads();
    }
#pragma unroll
    for (int i = 0; i < 4; i++) {
        int m = tyy * 4 + i;
        float nrm = g_norm[b * 1024 + h * 64 + m];
        float inv = 1.0f / (nrm + 1e-5f);
#pragma unroll
        for (int jj = 0; jj < 4; jj++) {
            int d = txx * 4 + jj;
            float bvv = b_kv[1024 + h * 64 + d];
            g_st[((size_t)z * 64 + m) * 64 + d] = (acc[i][jj] + nrm * bvv) * inv;
        }
    }
}

__global__ void __launch_bounds__(64)
k_qkv(const float* __restrict__ qkv_proj)
{
    int z = blockIdx.x;
    int h = (z >> 6) & 15;
    int d = threadIdx.x;
    __shared__ float st[64];
    __shared__ float ex[64];
    st[d] = g_st[(size_t)z * 64 + d];
    __syncthreads();
    const float* P = qkv_proj + (size_t)h * 64 * 192;
    float q = 0.f, k = 0.f, v = 0.f;
#pragma unroll 8
    for (int j = 0; j < 64; j++) {
        float s = st[j];
        const float* pr = P + j * 192;
        q += s * pr[d]; k += s * pr[64 + d]; v += s * pr[128 + d];
    }
    float dot = q * k * 0.125f;
    ex[d] = dot;
    __syncthreads();
    float mx = -1e30f;
    for (int j = 0; j < 64; j++) mx = fmaxf(mx, ex[j]);
    __syncthreads();
    float e = expf(dot - mx);
    ex[d] = e;
    __syncthreads();
    float sum = 0.f;
    for (int j = 0; j < 64; j++) sum += ex[j];
    g_ost[(size_t)z * 64 + d] = (e / sum) * v;
}

__global__ void __launch_bounds__(256)
k_zmat(const float* __restrict__ w_out)
{
    int z = blockIdx.y, jc = blockIdx.x;
    int b = z >> 4, h = z & 15;
    __shared__ float As[64][64];
    __shared__ float Bs[64][64];
    int t = threadIdx.x;
#pragma unroll
    for (int r = 0; r < 4; r++) {
        int lin = t + r * 256;
        int row = lin >> 4;
        int c4  = (lin & 15) << 2;
        float4 v = *(const float4*)(g_ost + ((size_t)z * 64 + row) * 64 + c4);
        As[c4 + 0][row] = v.x; As[c4 + 1][row] = v.y;
        As[c4 + 2][row] = v.z; As[c4 + 3][row] = v.w;
        *(float4*)&Bs[row][c4] =
            *(const float4*)(w_out + (size_t)(h * 64 + row) * 1024 + jc * 64 + c4);
    }
    __syncthreads();
    int tyy = t >> 4, txx = t & 15;
    float acc[4][4] = {};
#pragma unroll
    for (int kk = 0; kk < 64; kk++) {
        float4 a  = *(const float4*)&As[kk][tyy * 4];
        float4 bb = *(const float4*)&Bs[kk][txx * 4];
        float av[4] = {a.x, a.y, a.z, a.w};
        float bv[4] = {bb.x, bb.y, bb.z, bb.w};
#pragma unroll
        for (int i = 0; i < 4; i++)
#pragma unroll
            for (int jj = 0; jj < 4; jj++) acc[i][jj] += av[i] * bv[jj];
    }
#pragma unroll
    for (int i = 0; i < 4; i++) {
        int hm = h * 64 + tyy * 4 + i;
#pragma unroll
        for (int jj = 0; jj < 4; jj++) {
            int j = jc * 64 + txx * 4 + jj;
            __nv_bfloat16 hh, ll; split2(acc[i][jj], hh, ll);
            size_t o = ((size_t)b * 1024 + j) * 1024 + hm;
            g_Zth[o] = hh; g_Ztl[o] = ll;
        }
    }
}

// ---------------------------------------------------------------------------
extern "C" void kernel_launch(void* const* d_in, const int* in_sizes, int n_in,
                              void* d_out, int out_size)
{
    (void)in_sizes; (void)n_in; (void)out_size;
    const float* x      = (const float*)d_in[0];
    const float* w_kv   = (const float*)d_in[2];
    const float* b_kv   = (const float*)d_in[3];
    const float* w_temp = (const float*)d_in[4];
    const float* b_temp = (const float*)d_in[5];
    const float* xq     = (const float*)d_in[6];
    const float* qkv_p  = (const float*)d_in[7];
    const float* w_out  = (const float*)d_in[8];
    const float* b_out  = (const float*)d_in[9];
    float* out = (float*)d_out;

    float *pc, *pyp;
    __nv_bfloat16 *pxh, *pxl, *pxth, *pxtl, *pSh, *pSl, *pSth, *pStl, *pAth, *pAtl, *pZth, *pZtl;
    cudaGetSymbolAddress((void**)&pc,  g_c);
    cudaGetSymbolAddress((void**)&pyp, g_yp);
    cudaGetSymbolAddress((void**)&pxh, g_xh);   cudaGetSymbolAddress((void**)&pxl, g_xl);
    cudaGetSymbolAddress((void**)&pxth, g_xth); cudaGetSymbolAddress((void**)&pxtl, g_xtl);
    cudaGetSymbolAddress((void**)&pSh, g_Sh);   cudaGetSymbolAddress((void**)&pSl, g_Sl);
    cudaGetSymbolAddress((void**)&pSth, g_Sth); cudaGetSymbolAddress((void**)&pStl, g_Stl);
    cudaGetSymbolAddress((void**)&pAth, g_Ath); cudaGetSymbolAddress((void**)&pAtl, g_Atl);
    cudaGetSymbolAddress((void**)&pZth, g_Zth); cudaGetSymbolAddress((void**)&pZtl, g_Ztl);

    cudaFuncSetAttribute(mma_gemm<0>, cudaFuncAttributeMaxDynamicSharedMemorySize, GSMEM);
    cudaFuncSetAttribute(mma_gemm<1>, cudaFuncAttributeMaxDynamicSharedMemorySize, GSMEM);
    cudaFuncSetAttribute(mma_gemm<3>, cudaFuncAttributeMaxDynamicSharedMemorySize, GSMEM);
    cudaFuncSetAttribute(k_tempmma,   cudaFuncAttributeMaxDynamicSharedMemorySize, TGSMEM);

    k_zero<<<16, 256>>>();
    k_wsplit<<<64, 256>>>(w_temp);
    k_prep<<<4096, 256>>>(xq, w_kv, b_kv);
    k_convx<<<dim3(16, 512), 256>>>(x);
    // temperature via HMMA (reads g_xh/g_xl from k_convx)
    k_tempmma<<<256, 256, TGSMEM>>>(pxh, pxl, b_temp);
    // scores + fused softmax/norm/split (M=32768,N=1024,K=1024)
    mma_gemm<3><<<dim3(8, 256, 1), 256, GSMEM>>>(
        pxh, pxl, pAth, pAtl, nullptr, pc,
        1024, 1024, 1024, 0, 0, 0, 0, 0, 0);
    // y[b] = S[b]^T @ x[b] (M=1024,N=1024,K=8192), K-split x4, partial buffers
    mma_gemm<0><<<dim3(8, 8, cB * 4), 256, GSMEM>>>(
        pSth, pStl, pxth, pxtl, pyp, nullptr,
        2048, 8192, 8192, 1024,
        (long long)cHM * cN, (long long)cH * cN,
        (long long)cHM * cH, (long long)cB * cHM * cH, 2);
    k_st<<<cB * cNH, 256>>>(w_kv, b_kv);
    k_qkv<<<cB * cNH * 64, 64>>>(qkv_p);
    k_zmat<<<dim3(16, cB * cNH), 256>>>(w_out);
    // out[b] = S[b] @ Zt[b]^T + b_out (M=8192,N=1024,K=1024)
    mma_gemm<1><<<dim3(8, 64, cB), 256, GSMEM>>>(
        pSh, pSl, pZth, pZtl, out, b_out,
        1024, 1024, 1024, 1024,
        (long long)cN * cHM, (long long)cH * cHM,
        (long long)cN * cH, 0, 0);
}

// round 10
// speedup vs baseline: 1.1924x; 1.0996x over previous
#include <cuda_runtime.h>
#include <cuda_bf16.h>
#include <math.h>
#include <stdint.h>

constexpr int cB = 4, cN = 8192, cH = 1024, cNH = 16, cHM = 1024;

// ---------------- scratch (device globals) ----------------
__device__ __nv_bfloat16 g_xh [(size_t)cB * cN * cH];
__device__ __nv_bfloat16 g_xl [(size_t)cB * cN * cH];
__device__ __nv_bfloat16 g_xth[(size_t)cB * cH * cN];
__device__ __nv_bfloat16 g_xtl[(size_t)cB * cH * cN];
__device__ __nv_bfloat16 g_Sh [(size_t)cB * cN * cHM];
__device__ __nv_bfloat16 g_Sl [(size_t)cB * cN * cHM];
__device__ __nv_bfloat16 g_Sth[(size_t)cB * cHM * cN];
__device__ __nv_bfloat16 g_Stl[(size_t)cB * cHM * cN];
__device__ __nv_bfloat16 g_Ath[cHM * cH];
__device__ __nv_bfloat16 g_Atl[cHM * cH];
__device__ __nv_bfloat16 g_Zth[(size_t)cB * cH * cHM];
__device__ __nv_bfloat16 g_Ztl[(size_t)cB * cH * cHM];
__device__ __nv_bfloat16 g_wth[cNH * cH];          // w_temp^T hi  [16][1024]
__device__ __nv_bfloat16 g_wtl[cNH * cH];          // w_temp^T lo
__device__ float g_c[cHM];
__device__ float g_T[cB * cN * cNH];               // final temperature
__device__ float g_norm[cB * cHM];
__device__ float g_yp[(size_t)4 * cB * cHM * cH];  // 4 K-split partials of y
__device__ float g_st[cB * cNH * 64 * 64];
__device__ float g_ost[cB * cNH * 64 * 64];

// ---------------- helpers ----------------
__device__ __forceinline__ uint32_t smem_u32(const void* p) {
    uint32_t a;
    asm("{ .reg .u64 t; cvta.to.shared.u64 t, %1; cvt.u32.u64 %0, t; }" : "=r"(a) : "l"(p));
    return a;
}
__device__ __forceinline__ void cp16(uint32_t s, const void* g) {
    asm volatile("cp.async.cg.shared.global [%0], [%1], 16;" :: "r"(s), "l"(g));
}
#define CP_COMMIT() asm volatile("cp.async.commit_group;" ::: "memory")
#define CP_WAIT1()  asm volatile("cp.async.wait_group 1;" ::: "memory")
#define CP_WAIT0()  asm volatile("cp.async.wait_group 0;" ::: "memory")

__device__ __forceinline__ void ldsm4(uint32_t* r, uint32_t a) {
    asm volatile("ldmatrix.sync.aligned.m8n8.x4.shared.b16 {%0,%1,%2,%3}, [%4];"
        : "=r"(r[0]), "=r"(r[1]), "=r"(r[2]), "=r"(r[3]) : "r"(a));
}
__device__ __forceinline__ void mma16816(float* d, const uint32_t* a,
                                         uint32_t b0, uint32_t b1) {
    asm volatile("mma.sync.aligned.m16n8k16.row.col.f32.bf16.bf16.f32 "
        "{%0,%1,%2,%3}, {%4,%5,%6,%7}, {%8,%9}, {%0,%1,%2,%3};"
        : "+f"(d[0]), "+f"(d[1]), "+f"(d[2]), "+f"(d[3])
        : "r"(a[0]), "r"(a[1]), "r"(a[2]), "r"(a[3]), "r"(b0), "r"(b1));
}
__device__ __forceinline__ void split2(float v, __nv_bfloat16& h, __nv_bfloat16& l) {
    h = __float2bfloat16(v);
    l = __float2bfloat16(v - __bfloat162float(h));
}

// ============ HMMA split-bf16 GEMM: C[m][n] = sum_k A[m][k]*B[n][k] ==========
// CTA tile 128x128, 8 warps (2x4), warp tile 64x32, Kc=64 double-buffered.
// EPI: 0 = plain store (K-split partials), 1 = bias + store, 3 = fused softmax.
constexpr int T_AH = 0, T_AL = 16384, T_BH = 32768, T_BL = 49152;
constexpr int BUFB = 65536;
constexpr int GSMEM = 2 * BUFB;   // 128 KB

template<int EPI>
__global__ void __launch_bounds__(256, 1)
mma_gemm(const __nv_bfloat16* __restrict__ Ah, const __nv_bfloat16* __restrict__ Al,
         const __nv_bfloat16* __restrict__ Bh, const __nv_bfloat16* __restrict__ Bl,
         float* __restrict__ C, const float* __restrict__ bias,
         int Kdim, int lda, int ldb, int ldc,
         long long sA, long long sB, long long sC, long long sCk, int ksl)
{
    extern __shared__ __align__(128) char smem[];
    const int tid = threadIdx.x, wid = tid >> 5, lane = tid & 31;
    uint32_t sbase = smem_u32(smem);
    const long long zz = blockIdx.z;
    const long long batch = zz >> ksl;
    const long long kidx = zz & ((1 << ksl) - 1);
    Ah += batch * sA + kidx * (long long)Kdim;
    Al += batch * sA + kidx * (long long)Kdim;
    Bh += batch * sB + kidx * (long long)Kdim;
    Bl += batch * sB + kidx * (long long)Kdim;
    C  += batch * sC + kidx * sCk;
    const int m0 = blockIdx.y * 128, n0 = blockIdx.x * 128;

    auto issue = [&](int c) {
        const int kc = c << 6;
        uint32_t sb = sbase + (c & 1) * BUFB;
#pragma unroll
        for (int i = 0; i < 16; i++) {
            const int tile = i >> 2;
            const int idx  = ((i & 3) << 8) + tid;
            const int row  = idx >> 3, seg = idx & 7;
            uint32_t so = sb + tile * 16384 + row * 128 + ((seg ^ (row & 7)) << 4);
            const __nv_bfloat16* gp;
            if (tile == 0)      gp = Ah + (long long)(m0 + row) * lda + kc + seg * 8;
            else if (tile == 1) gp = Al + (long long)(m0 + row) * lda + kc + seg * 8;
            else if (tile == 2) gp = Bh + (long long)(n0 + row) * ldb + kc + seg * 8;
            else                gp = Bl + (long long)(n0 + row) * ldb + kc + seg * 8;
            cp16(so, gp);
        }
        CP_COMMIT();
    };

    const int NC = Kdim >> 6;
    issue(0);

    const int wm = (wid >> 2) * 64, wn = (wid & 3) * 32;
    const int arow  = wm + (lane & 15);
    const int akseg = lane >> 4;
    const int r7a   = arow & 7;
    const int brow  = wn + ((lane >> 4) << 3) + (lane & 7);
    const int bkseg = (lane >> 3) & 1;
    const int r7b   = brow & 7;

    float acc[4][4][4];
#pragma unroll
    for (int a = 0; a < 4; a++)
#pragma unroll
        for (int b = 0; b < 4; b++)
#pragma unroll
            for (int q = 0; q < 4; q++) acc[a][b][q] = 0.f;

    for (int c = 0; c < NC; c++) {
        if (c + 1 < NC) { issue(c + 1); CP_WAIT1(); } else { CP_WAIT0(); }
        __syncthreads();
        uint32_t sb = sbase + (c & 1) * BUFB;
#pragma unroll
        for (int ks = 0; ks < 4; ks++) {
            const int ks2 = ks * 2;
            uint32_t ah[4][4], alr[4][4], bh[2][4], bl[2][4];
#pragma unroll
            for (int mt = 0; mt < 4; mt++) {
                uint32_t ao = sb + T_AH + (arow + mt * 16) * 128
                            + (uint32_t)((((ks2 + akseg) ^ r7a)) << 4);
                ldsm4(ah[mt], ao);
                ldsm4(alr[mt], ao + (T_AL - T_AH));
            }
#pragma unroll
            for (int np = 0; np < 2; np++) {
                uint32_t bo = sb + T_BH + (brow + np * 16) * 128
                            + (uint32_t)((((ks2 + bkseg) ^ r7b)) << 4);
                ldsm4(bh[np], bo);
                ldsm4(bl[np], bo + (T_BL - T_BH));
            }
#pragma unroll
            for (int mt = 0; mt < 4; mt++)
#pragma unroll
                for (int nt = 0; nt < 4; nt++) {
                    const int np = nt >> 1, hb = (nt & 1) * 2;
                    mma16816(acc[mt][nt], ah[mt],  bh[np][hb], bh[np][hb + 1]);
                    mma16816(acc[mt][nt], ah[mt],  bl[np][hb], bl[np][hb + 1]);
                    mma16816(acc[mt][nt], alr[mt], bh[np][hb], bh[np][hb + 1]);
                }
        }
        __syncthreads();
    }

    const int rr = lane >> 2, cc = (lane & 3) * 2;

    if constexpr (EPI == 0 || EPI == 1) {
#pragma unroll
        for (int mt = 0; mt < 4; mt++) {
            const long long m = m0 + wm + mt * 16 + rr;
#pragma unroll
            for (int nt = 0; nt < 4; nt++) {
                const int n = n0 + wn + nt * 8 + cc;
                float bx = 0.f, by = 0.f;
                if (EPI == 1) {
                    float2 b2 = *(const float2*)(bias + n);
                    bx = b2.x; by = b2.y;
                }
                float2 v0 = make_float2(acc[mt][nt][0] + bx, acc[mt][nt][1] + by);
                float2 v1 = make_float2(acc[mt][nt][2] + bx, acc[mt][nt][3] + by);
                *(float2*)(C + m * ldc + n)       = v0;
                *(float2*)(C + (m + 8) * ldc + n) = v1;
            }
        }
    } else {
        // ---- EPI == 3: fused softmax over m + norm + dual-layout bf16 split ----
        float* sf = (float*)smem;               // 128 x 133 fp32 tile
#pragma unroll
        for (int mt = 0; mt < 4; mt++) {
#pragma unroll
            for (int nt = 0; nt < 4; nt++) {
                int r = wm + mt * 16 + rr;
                int col = wn + nt * 8 + cc;
                float2 b2 = *(const float2*)(bias + n0 + col);
                sf[r * 133 + col]           = acc[mt][nt][0] + b2.x;
                sf[r * 133 + col + 1]       = acc[mt][nt][1] + b2.y;
                sf[(r + 8) * 133 + col]     = acc[mt][nt][2] + b2.x;
                sf[(r + 8) * 133 + col + 1] = acc[mt][nt][3] + b2.y;
            }
        }
        __syncthreads();
        {
            int row = tid & 127, hl = tid >> 7;
            size_t bn = (size_t)m0 + row;
            int headg = (n0 >> 6) + hl;
            float inv_t = 1.0f / g_T[bn * 16 + headg];
            float* rp = sf + row * 133 + hl * 64;
            float mx = -1e30f;
#pragma unroll 8
            for (int i = 0; i < 64; i++) mx = fmaxf(mx, rp[i]);
            float sum = 0.f;
#pragma unroll 8
            for (int i = 0; i < 64; i++) {
                float e = expf((rp[i] - mx) * inv_t);
                rp[i] = e; sum += e;
            }
            float inv = 1.0f / sum;
#pragma unroll 8
            for (int i = 0; i < 64; i++) rp[i] *= inv;
        }
        __syncthreads();
        const int bidx = m0 >> 13;
        {
            int col = tid & 127, half = tid >> 7;
            float s = 0.f;
#pragma unroll 8
            for (int i = 0; i < 64; i++) s += sf[(half * 64 + i) * 133 + col];
            float* snorm = sf + 128 * 133;
            snorm[half * 128 + col] = s;
            __syncthreads();
            if (tid < 128)
                atomicAdd(&g_norm[bidx * 1024 + n0 + tid], snorm[tid] + snorm[128 + tid]);
        }
#pragma unroll
        for (int i = 0; i < 32; i++) {
            int p = i * 256 + tid;
            int row = p >> 6, col = (p & 63) << 1;
            float w0 = sf[row * 133 + col], w1 = sf[row * 133 + col + 1];
            __nv_bfloat16 h0, l0, h1, l1;
            split2(w0, h0, l0); split2(w1, h1, l1);
            size_t o = ((size_t)m0 + row) * 1024 + n0 + col;
            *(__nv_bfloat162*)(g_Sh + o) = __nv_bfloat162(h0, h1);
            *(__nv_bfloat162*)(g_Sl + o) = __nv_bfloat162(l0, l1);
        }
        {
            int nb = m0 & 8191;
#pragma unroll
            for (int i = 0; i < 32; i++) {
                int p = i * 256 + tid;
                int hm = p >> 6, n2 = (p & 63) << 1;
                float w0 = sf[n2 * 133 + hm], w1 = sf[(n2 + 1) * 133 + hm];
                __nv_bfloat16 h0, l0, h1, l1;
                split2(w0, h0, l0); split2(w1, h1, l1);
                size_t o = ((size_t)bidx * 1024 + n0 + hm) * 8192 + nb + n2;
                *(__nv_bfloat162*)(g_Sth + o) = __nv_bfloat162(h0, h1);
                *(__nv_bfloat162*)(g_Stl + o) = __nv_bfloat162(l0, l1);
            }
        }
    }
}

// ============ temperature GEMM: T = softplus(x @ w_temp + b_temp) + 0.5 ======
constexpr int TG_AH = 0, TG_AL = 16384;
constexpr int TG_BUF = 32768;
constexpr int TG_BH = 65536, TG_BL = 98304;
constexpr int TGSMEM = 131072;

__global__ void __launch_bounds__(256, 1)
k_tempmma(const __nv_bfloat16* __restrict__ xh, const __nv_bfloat16* __restrict__ xl,
          const float* __restrict__ b_temp)
{
    extern __shared__ __align__(128) char smem[];
    const int tid = threadIdx.x, wid = tid >> 5, lane = tid & 31;
    uint32_t sbase = smem_u32(smem);
    const int m0 = blockIdx.x * 128;

#pragma unroll
    for (int q = 0; q < 8; q++) {
        int i = q * 256 + tid;
        int c = i >> 7, r = (i >> 3) & 15, seg = i & 7;
        uint32_t so = sbase + TG_BH + c * 2048 + r * 128 + ((seg ^ (r & 7)) << 4);
        cp16(so, g_wth + r * 1024 + c * 64 + seg * 8);
        cp16(so + (TG_BL - TG_BH), g_wtl + r * 1024 + c * 64 + seg * 8);
    }

    auto issueA = [&](int c) {
        uint32_t sb = sbase + (c & 1) * TG_BUF;
        const int kc = c << 6;
#pragma unroll
        for (int q = 0; q < 4; q++) {
            int i = q * 256 + tid;
            int row = i >> 3, seg = i & 7;
            uint32_t so = sb + row * 128 + ((seg ^ (row & 7)) << 4);
            cp16(so,                   xh + (long long)(m0 + row) * 1024 + kc + seg * 8);
            cp16(so + (TG_AL - TG_AH), xl + (long long)(m0 + row) * 1024 + kc + seg * 8);
        }
        CP_COMMIT();
    };
    issueA(0);

    const int wm = wid * 16;
    const int arow  = wm + (lane & 15);
    const int akseg = lane >> 4;
    const int r7a   = arow & 7;
    const int brow  = ((lane >> 4) << 3) + (lane & 7);
    const int bkseg = (lane >> 3) & 1;
    const int r7b   = brow & 7;

    float acc[2][4];
#pragma unroll
    for (int nt = 0; nt < 2; nt++)
#pragma unroll
        for (int q = 0; q < 4; q++) acc[nt][q] = 0.f;

    for (int c = 0; c < 16; c++) {
        if (c + 1 < 16) { issueA(c + 1); CP_WAIT1(); } else { CP_WAIT0(); }
        __syncthreads();
        uint32_t sa = sbase + (c & 1) * TG_BUF;
        uint32_t sbb = sbase + TG_BH + c * 2048;
#pragma unroll
        for (int ks = 0; ks < 4; ks++) {
            const int ks2 = ks * 2;
            uint32_t ah[4], alr[4], bh[4], bl[4];
            uint32_t ao = sa + arow * 128 + (uint32_t)((((ks2 + akseg) ^ r7a)) << 4);
            ldsm4(ah, ao);
            ldsm4(alr, ao + (TG_AL - TG_AH));
            uint32_t bo = sbb + brow * 128 + (uint32_t)((((ks2 + bkseg) ^ r7b)) << 4);
            ldsm4(bh, bo);
            ldsm4(bl, bo + (TG_BL - TG_BH));
#pragma unroll
            for (int nt = 0; nt < 2; nt++) {
                const int hb = nt * 2;
                mma16816(acc[nt], ah,  bh[hb], bh[hb + 1]);
                mma16816(acc[nt], ah,  bl[hb], bl[hb + 1]);
                mma16816(acc[nt], alr, bh[hb], bh[hb + 1]);
            }
        }
        __syncthreads();
    }

    const int rr = lane >> 2, cc = (lane & 3) * 2;
    const long long r0 = m0 + wm + rr, r1 = r0 + 8;
#pragma unroll
    for (int nt = 0; nt < 2; nt++) {
        int head = nt * 8 + cc;
        float b0 = b_temp[head], b1 = b_temp[head + 1];
        float v[4] = {acc[nt][0] + b0, acc[nt][1] + b1,
                      acc[nt][2] + b0, acc[nt][3] + b1};
#pragma unroll
        for (int q = 0; q < 4; q++) {
            float s = v[q];
            v[q] = 0.5f + fmaxf(s, 0.f) + log1pf(expf(-fabsf(s)));
        }
        g_T[r0 * 16 + head]     = v[0];
        g_T[r0 * 16 + head + 1] = v[1];
        g_T[r1 * 16 + head]     = v[2];
        g_T[r1 * 16 + head + 1] = v[3];
    }
}

// ============ aux kernels ============
__global__ void k_zero()
{
    int i = blockIdx.x * 256 + threadIdx.x;
    if (i < cB * cHM) g_norm[i] = 0.f;
}

__global__ void __launch_bounds__(256)
k_wsplit(const float* __restrict__ w_temp)
{
    int idx = blockIdx.x * 256 + threadIdx.x;
    int h = idx >> 10, j = idx & 1023;
    __nv_bfloat16 hh, ll;
    split2(w_temp[j * 16 + h], hh, ll);
    g_wth[idx] = hh;
    g_wtl[idx] = ll;
}

__global__ void __launch_bounds__(256)
k_prep(const float* __restrict__ xq, const float* __restrict__ w_kv,
       const float* __restrict__ b_kv)
{
    int idx = blockIdx.x * 256 + threadIdx.x;
    int j = idx >> 10, hm = idx & 1023;
    int hbase = (hm >> 6) << 6;
    const float* xr = xq + (size_t)hm * 64;
    const float* wr = w_kv + (size_t)j * 2048 + hbase;
    float acc = 0.f;
#pragma unroll 8
    for (int d = 0; d < 64; d++) acc += xr[d] * wr[d];
    __nv_bfloat16 h, l; split2(acc, h, l);
    g_Ath[(size_t)hm * 1024 + j] = h;
    g_Atl[(size_t)hm * 1024 + j] = l;
    if (j == 0) {
        const float* br = b_kv + hbase;
        float cc = 0.f;
        for (int d = 0; d < 64; d++) cc += xr[d] * br[d];
        g_c[hm] = cc;
    }
}

// x -> (xh,xl) + (xth,xtl): fully coalesced version.
// Tile 64 n-rows x 64 j-cols staged in fp32 SMEM (pitch 67).
__global__ void __launch_bounds__(256)
k_convx(const float* __restrict__ x)
{
    __shared__ float xs[64][67];
    const int jt = blockIdx.x, nt = blockIdx.y;
    const int t = threadIdx.x;
    // Phase 1: coalesced float4 loads
#pragma unroll
    for (int q = 0; q < 4; q++) {
        int lin = q * 256 + t;
        int row = lin >> 4, c4 = (lin & 15) << 2;
        float4 v = *(const float4*)(x + ((size_t)nt * 64 + row) * 1024 + jt * 64 + c4);
        xs[row][c4 + 0] = v.x; xs[row][c4 + 1] = v.y;
        xs[row][c4 + 2] = v.z; xs[row][c4 + 3] = v.w;
    }
    __syncthreads();
    // Phase 2: straight writes, 128B contiguous per warp
#pragma unroll
    for (int q = 0; q < 8; q++) {
        int lin = q * 256 + t;
        int row = lin >> 5, col = (lin & 31) << 1;
        float w0 = xs[row][col], w1 = xs[row][col + 1];
        __nv_bfloat16 h0, l0, h1, l1;
        split2(w0, h0, l0); split2(w1, h1, l1);
        size_t o = ((size_t)nt * 64 + row) * 1024 + jt * 64 + col;
        *(__nv_bfloat162*)(g_xh + o) = __nv_bfloat162(h0, h1);
        *(__nv_bfloat162*)(g_xl + o) = __nv_bfloat162(l0, l1);
    }
    // Phase 3: transposed writes, 128B contiguous per warp
    const int b = (nt * 64) >> 13, nn0 = (nt * 64) & 8191;
#pragma unroll
    for (int q = 0; q < 8; q++) {
        int lin = q * 256 + t;
        int j = lin >> 5, n2 = (lin & 31) << 1;
        float w0 = xs[n2][j], w1 = xs[n2 + 1][j];
        __nv_bfloat16 h0, l0, h1, l1;
        split2(w0, h0, l0); split2(w1, h1, l1);
        size_t o = ((size_t)(b * 1024 + jt * 64 + j)) * 8192 + nn0 + n2;
        *(__nv_bfloat162*)(g_xth + o) = __nv_bfloat162(h0, h1);
        *(__nv_bfloat162*)(g_xtl + o) = __nv_bfloat162(l0, l1);
    }
}

// slice_token from 4 y-partials
__global__ void __launch_bounds__(256)
k_st(const float* __restrict__ w_kv, const float* __restrict__ b_kv)
{
    int z = blockIdx.x;
    int b = z >> 4, h = z & 15;
    constexpr size_t YPS = (size_t)cB * cHM * cH;
    const float* Yb = g_yp + ((size_t)b * 1024 + h * 64) * 1024;
    const float* Wv = w_kv + 1024 + h * 64;
    __shared__ float As[16][64];
    __shared__ float Bs[16][64];
    int t = threadIdx.x;
    int tyy = t >> 4, txx = t & 15;
    float acc[4][4] = {};
    for (int k0 = 0; k0 < 1024; k0 += 16) {
        {
            int m = t >> 2, k4 = (t & 3) << 2;
            size_t off = (size_t)m * 1024 + k0 + k4;
            float4 v0 = *(const float4*)(Yb + off);
            float4 v1 = *(const float4*)(Yb + YPS + off);
            float4 v2 = *(const float4*)(Yb + 2 * YPS + off);
            float4 v3 = *(const float4*)(Yb + 3 * YPS + off);
            As[k4 + 0][m] = v0.x + v1.x + v2.x + v3.x;
            As[k4 + 1][m] = v0.y + v1.y + v2.y + v3.y;
            As[k4 + 2][m] = v0.z + v1.z + v2.z + v3.z;
            As[k4 + 3][m] = v0.w + v1.w + v2.w + v3.w;
        }
        {
            int k = t >> 4, n4 = (t & 15) << 2;
            *(float4*)&Bs[k][n4] = *(const float4*)(Wv + (size_t)(k0 + k) * 2048 + n4);
        }
        __syncthreads();
#pragma unroll
        for (int kk = 0; kk < 16; kk++) {
            float4 a  = *(const float4*)&As[kk][tyy * 4];
            float4 bb = *(const float4*)&Bs[kk][txx * 4];
            float av[4] = {a.x, a.y, a.z, a.w};
            float bv[4] = {bb.x, bb.y, bb.z, bb.w};
#pragma unroll
            for (int i = 0; i < 4; i++)
#pragma unroll
                for (int jj = 0; jj < 4; jj++) acc[i][jj] += av[i] * bv[jj];
        }
        __syncthreads();
    }
#pragma unroll
    for (int i = 0; i < 4; i++) {
        int m = tyy * 4 + i;
        float nrm = g_norm[b * 1024 + h * 64 + m];
        float inv = 1.0f / (nrm + 1e-5f);
#pragma unroll
        for (int jj = 0; jj < 4; jj++) {
            int d = txx * 4 + jj;
            float bvv = b_kv[1024 + h * 64 + d];
            g_st[((size_t)z * 64 + m) * 64 + d] = (acc[i][jj] + nrm * bvv) * inv;
        }
    }
}

__global__ void __launch_bounds__(64)
k_qkv(const float* __restrict__ qkv_proj)
{
    int z = blockIdx.x;
    int h = (z >> 6) & 15;
    int d = threadIdx.x;
    __shared__ float st[64];
    __shared__ float ex[64];
    st[d] = g_st[(size_t)z * 64 + d];
    __syncthreads();
    const float* P = qkv_proj + (size_t)h * 64 * 192;
    float q = 0.f, k = 0.f, v = 0.f;
#pragma unroll 8
    for (int j = 0; j < 64; j++) {
        float s = st[j];
        const float* pr = P + j * 192;
        q += s * pr[d]; k += s * pr[64 + d]; v += s * pr[128 + d];
    }
    float dot = q * k * 0.125f;
    ex[d] = dot;
    __syncthreads();
    float mx = -1e30f;
    for (int j = 0; j < 64; j++) mx = fmaxf(mx, ex[j]);
    __syncthreads();
    float e = expf(dot - mx);
    ex[d] = e;
    __syncthreads();
    float sum = 0.f;
    for (int j = 0; j < 64; j++) sum += ex[j];
    g_ost[(size_t)z * 64 + d] = (e / sum) * v;
}

__global__ void __launch_bounds__(256)
k_zmat(const float* __restrict__ w_out)
{
    int z = blockIdx.y, jc = blockIdx.x;
    int b = z >> 4, h = z & 15;
    __shared__ float As[64][64];
    __shared__ float Bs[64][64];
    int t = threadIdx.x;
#pragma unroll
    for (int r = 0; r < 4; r++) {
        int lin = t + r * 256;
        int row = lin >> 4;
        int c4  = (lin & 15) << 2;
        float4 v = *(const float4*)(g_ost + ((size_t)z * 64 + row) * 64 + c4);
        As[c4 + 0][row] = v.x; As[c4 + 1][row] = v.y;
        As[c4 + 2][row] = v.z; As[c4 + 3][row] = v.w;
        *(float4*)&Bs[row][c4] =
            *(const float4*)(w_out + (size_t)(h * 64 + row) * 1024 + jc * 64 + c4);
    }
    __syncthreads();
    int tyy = t >> 4, txx = t & 15;
    float acc[4][4] = {};
#pragma unroll
    for (int kk = 0; kk < 64; kk++) {
        float4 a  = *(const float4*)&As[kk][tyy * 4];
        float4 bb = *(const float4*)&Bs[kk][txx * 4];
        float av[4] = {a.x, a.y, a.z, a.w};
        float bv[4] = {bb.x, bb.y, bb.z, bb.w};
#pragma unroll
        for (int i = 0; i < 4; i++)
#pragma unroll
            for (int jj = 0; jj < 4; jj++) acc[i][jj] += av[i] * bv[jj];
    }
#pragma unroll
    for (int i = 0; i < 4; i++) {
        int hm = h * 64 + tyy * 4 + i;
#pragma unroll
        for (int jj = 0; jj < 4; jj++) {
            int j = jc * 64 + txx * 4 + jj;
            __nv_bfloat16 hh, ll; split2(acc[i][jj], hh, ll);
            size_t o = ((size_t)b * 1024 + j) * 1024 + hm;
            g_Zth[o] = hh; g_Ztl[o] = ll;
        }
    }
}

// ---------------------------------------------------------------------------
extern "C" void kernel_launch(void* const* d_in, const int* in_sizes, int n_in,
                              void* d_out, int out_size)
{
    (void)in_sizes; (void)n_in; (void)out_size;
    const float* x      = (const float*)d_in[0];
    const float* w_kv   = (const float*)d_in[2];
    const float* b_kv   = (const float*)d_in[3];
    const float* w_temp = (const float*)d_in[4];
    const float* b_temp = (const float*)d_in[5];
    const float* xq     = (const float*)d_in[6];
    const float* qkv_p  = (const float*)d_in[7];
    const float* w_out  = (const float*)d_in[8];
    const float* b_out  = (const float*)d_in[9];
    float* out = (float*)d_out;

    float *pc, *pyp;
    __nv_bfloat16 *pxh, *pxl, *pxth, *pxtl, *pSh, *pSl, *pSth, *pStl, *pAth, *pAtl, *pZth, *pZtl;
    cudaGetSymbolAddress((void**)&pc,  g_c);
    cudaGetSymbolAddress((void**)&pyp, g_yp);
    cudaGetSymbolAddress((void**)&pxh, g_xh);   cudaGetSymbolAddress((void**)&pxl, g_xl);
    cudaGetSymbolAddress((void**)&pxth, g_xth); cudaGetSymbolAddress((void**)&pxtl, g_xtl);
    cudaGetSymbolAddress((void**)&pSh, g_Sh);   cudaGetSymbolAddress((void**)&pSl, g_Sl);
    cudaGetSymbolAddress((void**)&pSth, g_Sth); cudaGetSymbolAddress((void**)&pStl, g_Stl);
    cudaGetSymbolAddress((void**)&pAth, g_Ath); cudaGetSymbolAddress((void**)&pAtl, g_Atl);
    cudaGetSymbolAddress((void**)&pZth, g_Zth); cudaGetSymbolAddress((void**)&pZtl, g_Ztl);

    cudaFuncSetAttribute(mma_gemm<0>, cudaFuncAttributeMaxDynamicSharedMemorySize, GSMEM);
    cudaFuncSetAttribute(mma_gemm<1>, cudaFuncAttributeMaxDynamicSharedMemorySize, GSMEM);
    cudaFuncSetAttribute(mma_gemm<3>, cudaFuncAttributeMaxDynamicSharedMemorySize, GSMEM);
    cudaFuncSetAttribute(k_tempmma,   cudaFuncAttributeMaxDynamicSharedMemorySize, TGSMEM);

    k_zero<<<16, 256>>>();
    k_wsplit<<<64, 256>>>(w_temp);
    k_prep<<<4096, 256>>>(xq, w_kv, b_kv);
    k_convx<<<dim3(16, 512), 256>>>(x);
    // temperature via HMMA (reads g_xh/g_xl from k_convx)
    k_tempmma<<<256, 256, TGSMEM>>>(pxh, pxl, b_temp);
    // scores + fused softmax/norm/split (M=32768,N=1024,K=1024)
    mma_gemm<3><<<dim3(8, 256, 1), 256, GSMEM>>>(
        pxh, pxl, pAth, pAtl, nullptr, pc,
        1024, 1024, 1024, 0, 0, 0, 0, 0, 0);
    // y[b] = S[b]^T @ x[b] (M=1024,N=1024,K=8192), K-split x4, partial buffers
    mma_gemm<0><<<dim3(8, 8, cB * 4), 256, GSMEM>>>(
        pSth, pStl, pxth, pxtl, pyp, nullptr,
        2048, 8192, 8192, 1024,
        (long long)cHM * cN, (long long)cH * cN,
        (long long)cHM * cH, (long long)cB * cHM * cH, 2);
    k_st<<<cB * cNH, 256>>>(w_kv, b_kv);
    k_qkv<<<cB * cNH * 64, 64>>>(qkv_p);
    k_zmat<<<dim3(16, cB * cNH), 256>>>(w_out);
    // out[b] = S[b] @ Zt[b]^T + b_out (M=8192,N=1024,K=1024)
    mma_gemm<1><<<dim3(8, 64, cB), 256, GSMEM>>>(
        pSh, pSl, pZth, pZtl, out, b_out,
        1024, 1024, 1024, 1024,
        (long long)cN * cHM, (long long)cH * cHM,
        (long long)cN * cH, 0, 0);
}

// round 11
// speedup vs baseline: 1.1962x; 1.0031x over previous
#include <cuda_runtime.h>
#include <cuda_bf16.h>
#include <math.h>
#include <stdint.h>

constexpr int cB = 4, cN = 8192, cH = 1024, cNH = 16, cHM = 1024;

// ---------------- scratch (device globals) ----------------
__device__ __nv_bfloat16 g_xh [(size_t)cB * cN * cH];
__device__ __nv_bfloat16 g_xl [(size_t)cB * cN * cH];
__device__ __nv_bfloat16 g_xth[(size_t)cB * cH * cN];
__device__ __nv_bfloat16 g_xtl[(size_t)cB * cH * cN];
__device__ __nv_bfloat16 g_Sh [(size_t)cB * cN * cHM];
__device__ __nv_bfloat16 g_Sl [(size_t)cB * cN * cHM];
__device__ __nv_bfloat16 g_Sth[(size_t)cB * cHM * cN];
__device__ __nv_bfloat16 g_Stl[(size_t)cB * cHM * cN];
__device__ __nv_bfloat16 g_Ath[cHM * cH];
__device__ __nv_bfloat16 g_Atl[cHM * cH];
__device__ __nv_bfloat16 g_Zth[(size_t)cB * cH * cHM];
__device__ __nv_bfloat16 g_Ztl[(size_t)cB * cH * cHM];
__device__ __nv_bfloat16 g_wth[cNH * cH];
__device__ __nv_bfloat16 g_wtl[cNH * cH];
__device__ float g_c[cHM];
__device__ float g_T[cB * cN * cNH];
__device__ float g_norm[cB * cHM];
__device__ float g_yp[(size_t)8 * cB * cHM * cH];   // 8 K-split partials of y
__device__ float g_st[cB * cNH * 64 * 64];
__device__ float g_ost[cB * cNH * 64 * 64];

// ---------------- helpers ----------------
__device__ __forceinline__ uint32_t smem_u32(const void* p) {
    uint32_t a;
    asm("{ .reg .u64 t; cvta.to.shared.u64 t, %1; cvt.u32.u64 %0, t; }" : "=r"(a) : "l"(p));
    return a;
}
__device__ __forceinline__ void cp16(uint32_t s, const void* g) {
    asm volatile("cp.async.cg.shared.global [%0], [%1], 16;" :: "r"(s), "l"(g));
}
#define CP_COMMIT() asm volatile("cp.async.commit_group;" ::: "memory")
#define CP_WAIT1()  asm volatile("cp.async.wait_group 1;" ::: "memory")
#define CP_WAIT0()  asm volatile("cp.async.wait_group 0;" ::: "memory")

__device__ __forceinline__ void ldsm4(uint32_t* r, uint32_t a) {
    asm volatile("ldmatrix.sync.aligned.m8n8.x4.shared.b16 {%0,%1,%2,%3}, [%4];"
        : "=r"(r[0]), "=r"(r[1]), "=r"(r[2]), "=r"(r[3]) : "r"(a));
}
__device__ __forceinline__ void mma16816(float* d, const uint32_t* a,
                                         uint32_t b0, uint32_t b1) {
    asm volatile("mma.sync.aligned.m16n8k16.row.col.f32.bf16.bf16.f32 "
        "{%0,%1,%2,%3}, {%4,%5,%6,%7}, {%8,%9}, {%0,%1,%2,%3};"
        : "+f"(d[0]), "+f"(d[1]), "+f"(d[2]), "+f"(d[3])
        : "r"(a[0]), "r"(a[1]), "r"(a[2]), "r"(a[3]), "r"(b0), "r"(b1));
}
__device__ __forceinline__ void split2(float v, __nv_bfloat16& h, __nv_bfloat16& l) {
    h = __float2bfloat16(v);
    l = __float2bfloat16(v - __bfloat162float(h));
}

// ============ HMMA split-bf16 GEMM: C[m][n] = sum_k A[m][k]*B[n][k] ==========
// CTA tile 128x256, 8 warps (2x4), warp tile 64x64, Kc=64 double-buffered.
// EPI: 0 = plain store (K-split partials), 1 = bias + store, 3 = fused softmax.
constexpr int T_AH = 0, T_AL = 16384, T_BH = 32768, T_BL = 65536;
constexpr int BUFB = 98304;
constexpr int GSMEM = 2 * BUFB;   // 192 KB

template<int EPI>
__global__ void __launch_bounds__(256, 1)
mma_gemm(const __nv_bfloat16* __restrict__ Ah, const __nv_bfloat16* __restrict__ Al,
         const __nv_bfloat16* __restrict__ Bh, const __nv_bfloat16* __restrict__ Bl,
         float* __restrict__ C, const float* __restrict__ bias,
         int Kdim, int lda, int ldb, int ldc,
         long long sA, long long sB, long long sC, long long sCk, int ksl)
{
    extern __shared__ __align__(128) char smem[];
    const int tid = threadIdx.x, wid = tid >> 5, lane = tid & 31;
    uint32_t sbase = smem_u32(smem);
    const long long zz = blockIdx.z;
    const long long batch = zz >> ksl;
    const long long kidx = zz & ((1 << ksl) - 1);
    Ah += batch * sA + kidx * (long long)Kdim;
    Al += batch * sA + kidx * (long long)Kdim;
    Bh += batch * sB + kidx * (long long)Kdim;
    Bl += batch * sB + kidx * (long long)Kdim;
    C  += batch * sC + kidx * sCk;
    const int m0 = blockIdx.y * 128, n0 = blockIdx.x * 256;

    auto issue = [&](int c) {
        const int kc = c << 6;
        uint32_t sb = sbase + (c & 1) * BUFB;
#pragma unroll
        for (int i = 0; i < 4; i++) {            // A: 128 rows x 8 segs (hi+lo)
            const int idx = (i << 8) + tid;
            const int row = idx >> 3, seg = idx & 7;
            uint32_t so = sb + row * 128 + ((seg ^ (row & 7)) << 4);
            long long go = (long long)(m0 + row) * lda + kc + seg * 8;
            cp16(so + T_AH, Ah + go);
            cp16(so + T_AL, Al + go);
        }
#pragma unroll
        for (int i = 0; i < 8; i++) {            // B: 256 rows x 8 segs (hi+lo)
            const int idx = (i << 8) + tid;
            const int row = idx >> 3, seg = idx & 7;
            uint32_t so = sb + row * 128 + ((seg ^ (row & 7)) << 4);
            long long go = (long long)(n0 + row) * ldb + kc + seg * 8;
            cp16(so + T_BH, Bh + go);
            cp16(so + T_BL, Bl + go);
        }
        CP_COMMIT();
    };

    const int NC = Kdim >> 6;
    issue(0);

    const int wm = (wid >> 2) * 64, wn = (wid & 3) * 64;
    const int arow  = wm + (lane & 15);
    const int akseg = lane >> 4;
    const int r7a   = arow & 7;
    const int brin  = ((lane >> 4) << 3) + (lane & 7);   // 0..15 within tile
    const int bkseg = (lane >> 3) & 1;
    const int r7b   = lane & 7;

    float acc[4][8][4];
#pragma unroll
    for (int a = 0; a < 4; a++)
#pragma unroll
        for (int b = 0; b < 8; b++)
#pragma unroll
            for (int q = 0; q < 4; q++) acc[a][b][q] = 0.f;

    for (int c = 0; c < NC; c++) {
        if (c + 1 < NC) { issue(c + 1); CP_WAIT1(); } else { CP_WAIT0(); }
        __syncthreads();
        uint32_t sb = sbase + (c & 1) * BUFB;
#pragma unroll
        for (int ks = 0; ks < 4; ks++) {
            const int ks2 = ks * 2;
            uint32_t ah[4][4], alr[4][4];
#pragma unroll
            for (int mt = 0; mt < 4; mt++) {
                uint32_t ao = sb + T_AH + (arow + mt * 16) * 128
                            + (uint32_t)((((ks2 + akseg) ^ r7a)) << 4);
                ldsm4(ah[mt], ao);
                ldsm4(alr[mt], ao + (T_AL - T_AH));
            }
#pragma unroll
            for (int half = 0; half < 2; half++) {
                uint32_t bh[2][4], bl[2][4];
#pragma unroll
                for (int p = 0; p < 2; p++) {
                    const int row = wn + (half * 2 + p) * 16 + brin;
                    uint32_t bo = sb + T_BH + row * 128
                                + (uint32_t)((((ks2 + bkseg) ^ r7b)) << 4);
                    ldsm4(bh[p], bo);
                    ldsm4(bl[p], bo + (T_BL - T_BH));
                }
#pragma unroll
                for (int mt = 0; mt < 4; mt++)
#pragma unroll
                    for (int q = 0; q < 4; q++) {
                        const int nt = half * 4 + q;
                        const int p = q >> 1, hb = (q & 1) * 2;
                        mma16816(acc[mt][nt], ah[mt],  bh[p][hb], bh[p][hb + 1]);
                        mma16816(acc[mt][nt], ah[mt],  bl[p][hb], bl[p][hb + 1]);
                        mma16816(acc[mt][nt], alr[mt], bh[p][hb], bh[p][hb + 1]);
                    }
            }
        }
        __syncthreads();
    }

    const int rr = lane >> 2, cc = (lane & 3) * 2;

    if constexpr (EPI == 0 || EPI == 1) {
#pragma unroll
        for (int mt = 0; mt < 4; mt++) {
            const long long m = m0 + wm + mt * 16 + rr;
#pragma unroll
            for (int nt = 0; nt < 8; nt++) {
                const int n = n0 + wn + nt * 8 + cc;
                float bx = 0.f, by = 0.f;
                if (EPI == 1) {
                    float2 b2 = *(const float2*)(bias + n);
                    bx = b2.x; by = b2.y;
                }
                float2 v0 = make_float2(acc[mt][nt][0] + bx, acc[mt][nt][1] + by);
                float2 v1 = make_float2(acc[mt][nt][2] + bx, acc[mt][nt][3] + by);
                *(float2*)(C + m * ldc + n)       = v0;
                *(float2*)(C + (m + 8) * ldc + n) = v1;
            }
        }
    } else {
        // ---- EPI == 3: fused softmax over m + norm + dual-layout bf16 split ----
        // sf: 128 rows x 256 cols fp32, pitch 261 (odd -> conflict-light)
        float* sf = (float*)smem;
#pragma unroll
        for (int mt = 0; mt < 4; mt++) {
#pragma unroll
            for (int nt = 0; nt < 8; nt++) {
                int r = wm + mt * 16 + rr;
                int col = wn + nt * 8 + cc;
                float2 b2 = *(const float2*)(bias + n0 + col);
                sf[r * 261 + col]           = acc[mt][nt][0] + b2.x;
                sf[r * 261 + col + 1]       = acc[mt][nt][1] + b2.y;
                sf[(r + 8) * 261 + col]     = acc[mt][nt][2] + b2.x;
                sf[(r + 8) * 261 + col + 1] = acc[mt][nt][3] + b2.y;
            }
        }
        __syncthreads();
        // row softmax: 128 rows x 4 heads = 512 tasks, 2 per thread
#pragma unroll
        for (int it = 0; it < 2; it++) {
            int task = it * 256 + tid;
            int row = task & 127, hq = task >> 7;
            size_t bn = (size_t)m0 + row;
            int headg = (n0 >> 6) + hq;
            float inv_t = 1.0f / g_T[bn * 16 + headg];
            float* rp = sf + row * 261 + hq * 64;
            float mx = -1e30f;
#pragma unroll 8
            for (int i = 0; i < 64; i++) mx = fmaxf(mx, rp[i]);
            float sum = 0.f;
#pragma unroll 8
            for (int i = 0; i < 64; i++) {
                float e = expf((rp[i] - mx) * inv_t);
                rp[i] = e; sum += e;
            }
            float inv = 1.0f / sum;
#pragma unroll 8
            for (int i = 0; i < 64; i++) rp[i] *= inv;
        }
        __syncthreads();
        const int bidx = m0 >> 13;
        // per-hm norm: 256 columns, one thread each (sum 128 rows)
        {
            float s = 0.f;
#pragma unroll 8
            for (int i = 0; i < 128; i++) s += sf[i * 261 + tid];
            atomicAdd(&g_norm[bidx * 1024 + n0 + tid], s);
        }
        // coalesced row-major Sh/Sl writes (128x256 / 256thr / 2 = 64 iters)
#pragma unroll
        for (int i = 0; i < 64; i++) {
            int p = i * 256 + tid;
            int row = p >> 7, col = (p & 127) << 1;
            float w0 = sf[row * 261 + col], w1 = sf[row * 261 + col + 1];
            __nv_bfloat16 h0, l0, h1, l1;
            split2(w0, h0, l0); split2(w1, h1, l1);
            size_t o = ((size_t)m0 + row) * 1024 + n0 + col;
            *(__nv_bfloat162*)(g_Sh + o) = __nv_bfloat162(h0, h1);
            *(__nv_bfloat162*)(g_Sl + o) = __nv_bfloat162(l0, l1);
        }
        // coalesced transposed Sth/Stl writes
        {
            int nb = m0 & 8191;
#pragma unroll
            for (int i = 0; i < 64; i++) {
                int p = i * 256 + tid;
                int hm = p >> 6, n2 = (p & 63) << 1;
                float w0 = sf[n2 * 261 + hm], w1 = sf[(n2 + 1) * 261 + hm];
                __nv_bfloat16 h0, l0, h1, l1;
                split2(w0, h0, l0); split2(w1, h1, l1);
                size_t o = ((size_t)bidx * 1024 + n0 + hm) * 8192 + nb + n2;
                *(__nv_bfloat162*)(g_Sth + o) = __nv_bfloat162(h0, h1);
                *(__nv_bfloat162*)(g_Stl + o) = __nv_bfloat162(l0, l1);
            }
        }
    }
}

// ============ temperature GEMM: T = softplus(x @ w_temp + b_temp) + 0.5 ======
constexpr int TG_AH = 0, TG_AL = 16384;
constexpr int TG_BUF = 32768;
constexpr int TG_BH = 65536, TG_BL = 98304;
constexpr int TGSMEM = 131072;

__global__ void __launch_bounds__(256, 1)
k_tempmma(const __nv_bfloat16* __restrict__ xh, const __nv_bfloat16* __restrict__ xl,
          const float* __restrict__ b_temp)
{
    extern __shared__ __align__(128) char smem[];
    const int tid = threadIdx.x, wid = tid >> 5, lane = tid & 31;
    uint32_t sbase = smem_u32(smem);
    const int m0 = blockIdx.x * 128;

#pragma unroll
    for (int q = 0; q < 8; q++) {
        int i = q * 256 + tid;
        int c = i >> 7, r = (i >> 3) & 15, seg = i & 7;
        uint32_t so = sbase + TG_BH + c * 2048 + r * 128 + ((seg ^ (r & 7)) << 4);
        cp16(so, g_wth + r * 1024 + c * 64 + seg * 8);
        cp16(so + (TG_BL - TG_BH), g_wtl + r * 1024 + c * 64 + seg * 8);
    }

    auto issueA = [&](int c) {
        uint32_t sb = sbase + (c & 1) * TG_BUF;
        const int kc = c << 6;
#pragma unroll
        for (int q = 0; q < 4; q++) {
            int i = q * 256 + tid;
            int row = i >> 3, seg = i & 7;
            uint32_t so = sb + row * 128 + ((seg ^ (row & 7)) << 4);
            cp16(so,                   xh + (long long)(m0 + row) * 1024 + kc + seg * 8);
            cp16(so + (TG_AL - TG_AH), xl + (long long)(m0 + row) * 1024 + kc + seg * 8);
        }
        CP_COMMIT();
    };
    issueA(0);

    const int wm = wid * 16;
    const int arow  = wm + (lane & 15);
    const int akseg = lane >> 4;
    const int r7a   = arow & 7;
    const int brow  = ((lane >> 4) << 3) + (lane & 7);
    const int bkseg = (lane >> 3) & 1;
    const int r7b   = brow & 7;

    float acc[2][4];
#pragma unroll
    for (int nt = 0; nt < 2; nt++)
#pragma unroll
        for (int q = 0; q < 4; q++) acc[nt][q] = 0.f;

    for (int c = 0; c < 16; c++) {
        if (c + 1 < 16) { issueA(c + 1); CP_WAIT1(); } else { CP_WAIT0(); }
        __syncthreads();
        uint32_t sa = sbase + (c & 1) * TG_BUF;
        uint32_t sbb = sbase + TG_BH + c * 2048;
#pragma unroll
        for (int ks = 0; ks < 4; ks++) {
            const int ks2 = ks * 2;
            uint32_t ah[4], alr[4], bh[4], bl[4];
            uint32_t ao = sa + arow * 128 + (uint32_t)((((ks2 + akseg) ^ r7a)) << 4);
            ldsm4(ah, ao);
            ldsm4(alr, ao + (TG_AL - TG_AH));
            uint32_t bo = sbb + brow * 128 + (uint32_t)((((ks2 + bkseg) ^ r7b)) << 4);
            ldsm4(bh, bo);
            ldsm4(bl, bo + (TG_BL - TG_BH));
#pragma unroll
            for (int nt = 0; nt < 2; nt++) {
                const int hb = nt * 2;
                mma16816(acc[nt], ah,  bh[hb], bh[hb + 1]);
                mma16816(acc[nt], ah,  bl[hb], bl[hb + 1]);
                mma16816(acc[nt], alr, bh[hb], bh[hb + 1]);
            }
        }
        __syncthreads();
    }

    const int rr = lane >> 2, cc = (lane & 3) * 2;
    const long long r0 = m0 + wm + rr, r1 = r0 + 8;
#pragma unroll
    for (int nt = 0; nt < 2; nt++) {
        int head = nt * 8 + cc;
        float b0 = b_temp[head], b1 = b_temp[head + 1];
        float v[4] = {acc[nt][0] + b0, acc[nt][1] + b1,
                      acc[nt][2] + b0, acc[nt][3] + b1};
#pragma unroll
        for (int q = 0; q < 4; q++) {
            float s = v[q];
            v[q] = 0.5f + fmaxf(s, 0.f) + log1pf(expf(-fabsf(s)));
        }
        g_T[r0 * 16 + head]     = v[0];
        g_T[r0 * 16 + head + 1] = v[1];
        g_T[r1 * 16 + head]     = v[2];
        g_T[r1 * 16 + head + 1] = v[3];
    }
}

// ============ aux kernels ============
__global__ void k_zero()
{
    int i = blockIdx.x * 256 + threadIdx.x;
    if (i < cB * cHM) g_norm[i] = 0.f;
}

__global__ void __launch_bounds__(256)
k_wsplit(const float* __restrict__ w_temp)
{
    int idx = blockIdx.x * 256 + threadIdx.x;
    int h = idx >> 10, j = idx & 1023;
    __nv_bfloat16 hh, ll;
    split2(w_temp[j * 16 + h], hh, ll);
    g_wth[idx] = hh;
    g_wtl[idx] = ll;
}

__global__ void __launch_bounds__(256)
k_prep(const float* __restrict__ xq, const float* __restrict__ w_kv,
       const float* __restrict__ b_kv)
{
    int idx = blockIdx.x * 256 + threadIdx.x;
    int j = idx >> 10, hm = idx & 1023;
    int hbase = (hm >> 6) << 6;
    const float* xr = xq + (size_t)hm * 64;
    const float* wr = w_kv + (size_t)j * 2048 + hbase;
    float acc = 0.f;
#pragma unroll 8
    for (int d = 0; d < 64; d++) acc += xr[d] * wr[d];
    __nv_bfloat16 h, l; split2(acc, h, l);
    g_Ath[(size_t)hm * 1024 + j] = h;
    g_Atl[(size_t)hm * 1024 + j] = l;
    if (j == 0) {
        const float* br = b_kv + hbase;
        float cc = 0.f;
        for (int d = 0; d < 64; d++) cc += xr[d] * br[d];
        g_c[hm] = cc;
    }
}

// x -> (xh,xl) + (xth,xtl): fully coalesced (round-10 winning version)
__global__ void __launch_bounds__(256)
k_convx(const float* __restrict__ x)
{
    __shared__ float xs[64][67];
    const int jt = blockIdx.x, nt = blockIdx.y;
    const int t = threadIdx.x;
#pragma unroll
    for (int q = 0; q < 4; q++) {
        int lin = q * 256 + t;
        int row = lin >> 4, c4 = (lin & 15) << 2;
        float4 v = *(const float4*)(x + ((size_t)nt * 64 + row) * 1024 + jt * 64 + c4);
        xs[row][c4 + 0] = v.x; xs[row][c4 + 1] = v.y;
        xs[row][c4 + 2] = v.z; xs[row][c4 + 3] = v.w;
    }
    __syncthreads();
#pragma unroll
    for (int q = 0; q < 8; q++) {
        int lin = q * 256 + t;
        int row = lin >> 5, col = (lin & 31) << 1;
        float w0 = xs[row][col], w1 = xs[row][col + 1];
        __nv_bfloat16 h0, l0, h1, l1;
        split2(w0, h0, l0); split2(w1, h1, l1);
        size_t o = ((size_t)nt * 64 + row) * 1024 + jt * 64 + col;
        *(__nv_bfloat162*)(g_xh + o) = __nv_bfloat162(h0, h1);
        *(__nv_bfloat162*)(g_xl + o) = __nv_bfloat162(l0, l1);
    }
    const int b = (nt * 64) >> 13, nn0 = (nt * 64) & 8191;
#pragma unroll
    for (int q = 0; q < 8; q++) {
        int lin = q * 256 + t;
        int j = lin >> 5, n2 = (lin & 31) << 1;
        float w0 = xs[n2][j], w1 = xs[n2 + 1][j];
        __nv_bfloat16 h0, l0, h1, l1;
        split2(w0, h0, l0); split2(w1, h1, l1);
        size_t o = ((size_t)(b * 1024 + jt * 64 + j)) * 8192 + nn0 + n2;
        *(__nv_bfloat162*)(g_xth + o) = __nv_bfloat162(h0, h1);
        *(__nv_bfloat162*)(g_xtl + o) = __nv_bfloat162(l0, l1);
    }
}

// slice_token from 8 y-partials
__global__ void __launch_bounds__(256)
k_st(const float* __restrict__ w_kv, const float* __restrict__ b_kv)
{
    int z = blockIdx.x;
    int b = z >> 4, h = z & 15;
    constexpr size_t YPS = (size_t)cB * cHM * cH;
    const float* Yb = g_yp + ((size_t)b * 1024 + h * 64) * 1024;
    const float* Wv = w_kv + 1024 + h * 64;
    __shared__ float As[16][64];
    __shared__ float Bs[16][64];
    int t = threadIdx.x;
    int tyy = t >> 4, txx = t & 15;
    float acc[4][4] = {};
    for (int k0 = 0; k0 < 1024; k0 += 16) {
        {
            int m = t >> 2, k4 = (t & 3) << 2;
            size_t off = (size_t)m * 1024 + k0 + k4;
            float4 vs = make_float4(0.f, 0.f, 0.f, 0.f);
#pragma unroll
            for (int p = 0; p < 8; p++) {
                float4 v = *(const float4*)(Yb + p * YPS + off);
                vs.x += v.x; vs.y += v.y; vs.z += v.z; vs.w += v.w;
            }
            As[k4 + 0][m] = vs.x; As[k4 + 1][m] = vs.y;
            As[k4 + 2][m] = vs.z; As[k4 + 3][m] = vs.w;
        }
        {
            int k = t >> 4, n4 = (t & 15) << 2;
            *(float4*)&Bs[k][n4] = *(const float4*)(Wv + (size_t)(k0 + k) * 2048 + n4);
        }
        __syncthreads();
#pragma unroll
        for (int kk = 0; kk < 16; kk++) {
            float4 a  = *(const float4*)&As[kk][tyy * 4];
            float4 bb = *(const float4*)&Bs[kk][txx * 4];
            float av[4] = {a.x, a.y, a.z, a.w};
            float bv[4] = {bb.x, bb.y, bb.z, bb.w};
#pragma unroll
            for (int i = 0; i < 4; i++)
#pragma unroll
                for (int jj = 0; jj < 4; jj++) acc[i][jj] += av[i] * bv[jj];
        }
        __syncthreads();
    }
#pragma unroll
    for (int i = 0; i < 4; i++) {
        int m = tyy * 4 + i;
        float nrm = g_norm[b * 1024 + h * 64 + m];
        float inv = 1.0f / (nrm + 1e-5f);
#pragma unroll
        for (int jj = 0; jj < 4; jj++) {
            int d = txx * 4 + jj;
            float bvv = b_kv[1024 + h * 64 + d];
            g_st[((size_t)z * 64 + m) * 64 + d] = (acc[i][jj] + nrm * bvv) * inv;
        }
    }
}

__global__ void __launch_bounds__(64)
k_qkv(const float* __restrict__ qkv_proj)
{
    int z = blockIdx.x;
    int h = (z >> 6) & 15;
    int d = threadIdx.x;
    __shared__ float st[64];
    __shared__ float ex[64];
    st[d] = g_st[(size_t)z * 64 + d];
    __syncthreads();
    const float* P = qkv_proj + (size_t)h * 64 * 192;
    float q = 0.f, k = 0.f, v = 0.f;
#pragma unroll 8
    for (int j = 0; j < 64; j++) {
        float s = st[j];
        const float* pr = P + j * 192;
        q += s * pr[d]; k += s * pr[64 + d]; v += s * pr[128 + d];
    }
    float dot = q * k * 0.125f;
    ex[d] = dot;
    __syncthreads();
    float mx = -1e30f;
    for (int j = 0; j < 64; j++) mx = fmaxf(mx, ex[j]);
    __syncthreads();
    float e = expf(dot - mx);
    ex[d] = e;
    __syncthreads();
    float sum = 0.f;
    for (int j = 0; j < 64; j++) sum += ex[j];
    g_ost[(size_t)z * 64 + d] = (e / sum) * v;
}

__global__ void __launch_bounds__(256)
k_zmat(const float* __restrict__ w_out)
{
    int z = blockIdx.y, jc = blockIdx.x;
    int b = z >> 4, h = z & 15;
    __shared__ float As[64][64];
    __shared__ float Bs[64][64];
    int t = threadIdx.x;
#pragma unroll
    for (int r = 0; r < 4; r++) {
        int lin = t + r * 256;
        int row = lin >> 4;
        int c4  = (lin & 15) << 2;
        float4 v = *(const float4*)(g_ost + ((size_t)z * 64 + row) * 64 + c4);
        As[c4 + 0][row] = v.x; As[c4 + 1][row] = v.y;
        As[c4 + 2][row] = v.z; As[c4 + 3][row] = v.w;
        *(float4*)&Bs[row][c4] =
            *(const float4*)(w_out + (size_t)(h * 64 + row) * 1024 + jc * 64 + c4);
    }
    __syncthreads();
    int tyy = t >> 4, txx = t & 15;
    float acc[4][4] = {};
#pragma unroll
    for (int kk = 0; kk < 64; kk++) {
        float4 a  = *(const float4*)&As[kk][tyy * 4];
        float4 bb = *(const float4*)&Bs[kk][txx * 4];
        float av[4] = {a.x, a.y, a.z, a.w};
        float bv[4] = {bb.x, bb.y, bb.z, bb.w};
#pragma unroll
        for (int i = 0; i < 4; i++)
#pragma unroll
            for (int jj = 0; jj < 4; jj++) acc[i][jj] += av[i] * bv[jj];
    }
#pragma unroll
    for (int i = 0; i < 4; i++) {
        int hm = h * 64 + tyy * 4 + i;
#pragma unroll
        for (int jj = 0; jj < 4; jj++) {
            int j = jc * 64 + txx * 4 + jj;
            __nv_bfloat16 hh, ll; split2(acc[i][jj], hh, ll);
            size_t o = ((size_t)b * 1024 + j) * 1024 + hm;
            g_Zth[o] = hh; g_Ztl[o] = ll;
        }
    }
}

// ---------------------------------------------------------------------------
extern "C" void kernel_launch(void* const* d_in, const int* in_sizes, int n_in,
                              void* d_out, int out_size)
{
    (void)in_sizes; (void)n_in; (void)out_size;
    const float* x      = (const float*)d_in[0];
    const float* w_kv   = (const float*)d_in[2];
    const float* b_kv   = (const float*)d_in[3];
    const float* w_temp = (const float*)d_in[4];
    const float* b_temp = (const float*)d_in[5];
    const float* xq     = (const float*)d_in[6];
    const float* qkv_p  = (const float*)d_in[7];
    const float* w_out  = (const float*)d_in[8];
    const float* b_out  = (const float*)d_in[9];
    float* out = (float*)d_out;

    float *pc, *pyp;
    __nv_bfloat16 *pxh, *pxl, *pxth, *pxtl, *pSh, *pSl, *pSth, *pStl, *pAth, *pAtl, *pZth, *pZtl;
    cudaGetSymbolAddress((void**)&pc,  g_c);
    cudaGetSymbolAddress((void**)&pyp, g_yp);
    cudaGetSymbolAddress((void**)&pxh, g_xh);   cudaGetSymbolAddress((void**)&pxl, g_xl);
    cudaGetSymbolAddress((void**)&pxth, g_xth); cudaGetSymbolAddress((void**)&pxtl, g_xtl);
    cudaGetSymbolAddress((void**)&pSh, g_Sh);   cudaGetSymbolAddress((void**)&pSl, g_Sl);
    cudaGetSymbolAddress((void**)&pSth, g_Sth); cudaGetSymbolAddress((void**)&pStl, g_Stl);
    cudaGetSymbolAddress((void**)&pAth, g_Ath); cudaGetSymbolAddress((void**)&pAtl, g_Atl);
    cudaGetSymbolAddress((void**)&pZth, g_Zth); cudaGetSymbolAddress((void**)&pZtl, g_Ztl);

    cudaFuncSetAttribute(mma_gemm<0>, cudaFuncAttributeMaxDynamicSharedMemorySize, GSMEM);
    cudaFuncSetAttribute(mma_gemm<1>, cudaFuncAttributeMaxDynamicSharedMemorySize, GSMEM);
    cudaFuncSetAttribute(mma_gemm<3>, cudaFuncAttributeMaxDynamicSharedMemorySize, GSMEM);
    cudaFuncSetAttribute(k_tempmma,   cudaFuncAttributeMaxDynamicSharedMemorySize, TGSMEM);

    k_zero<<<16, 256>>>();
    k_wsplit<<<64, 256>>>(w_temp);
    k_prep<<<4096, 256>>>(xq, w_kv, b_kv);
    k_convx<<<dim3(16, 512), 256>>>(x);
    k_tempmma<<<256, 256, TGSMEM>>>(pxh, pxl, b_temp);
    // scores + fused softmax/norm/split (M=32768,N=1024,K=1024), tile 128x256
    mma_gemm<3><<<dim3(4, 256, 1), 256, GSMEM>>>(
        pxh, pxl, pAth, pAtl, nullptr, pc,
        1024, 1024, 1024, 0, 0, 0, 0, 0, 0);
    // y[b] = S[b]^T @ x[b] (M=1024,N=1024,K=8192), K-split x8, partial buffers
    mma_gemm<0><<<dim3(4, 8, cB * 8), 256, GSMEM>>>(
        pSth, pStl, pxth, pxtl, pyp, nullptr,
        1024, 8192, 8192, 1024,
        (long long)cHM * cN, (long long)cH * cN,
        (long long)cHM * cH, (long long)cB * cHM * cH, 3);
    k_st<<<cB * cNH, 256>>>(w_kv, b_kv);
    k_qkv<<<cB * cNH * 64, 64>>>(qkv_p);
    k_zmat<<<dim3(16, cB * cNH), 256>>>(w_out);
    // out[b] = S[b] @ Zt[b]^T + b_out (M=8192,N=1024,K=1024)
    mma_gemm<1><<<dim3(4, 64, cB), 256, GSMEM>>>(
        pSh, pSl, pZth, pZtl, out, b_out,
        1024, 1024, 1024, 1024,
        (long long)cN * cHM, (long long)cH * cHM,
        (long long)cN * cH, 0, 0);
}

// round 12
// speedup vs baseline: 1.6925x; 1.4150x over previous
#include <cuda_runtime.h>
#include <cuda_bf16.h>
#include <cuda_fp16.h>
#include <math.h>
#include <stdint.h>

constexpr int cB = 4, cN = 8192, cH = 1024, cNH = 16, cHM = 1024;

// ---------------- scratch (device globals) ----------------
__device__ __nv_bfloat16 g_xh [(size_t)cB * cN * cH];   // x hi (bf16, scores/temp)
__device__ __nv_bfloat16 g_xl [(size_t)cB * cN * cH];   // x lo
__device__ __half        g_xtf[(size_t)cB * cH * cN];   // x^T fp16 (y-GEMM B)
__device__ __half        g_Sf [(size_t)cB * cN * cHM];  // S fp16 (out-GEMM A)
__device__ __half        g_Sft[(size_t)cB * cHM * cN];  // S^T fp16 (y-GEMM A)
__device__ __nv_bfloat16 g_Ath[cHM * cH];
__device__ __nv_bfloat16 g_Atl[cHM * cH];
__device__ __half        g_Ztf[(size_t)cB * cH * cHM];  // Z^T fp16 (out-GEMM B)
__device__ __nv_bfloat16 g_wth[cNH * cH];
__device__ __nv_bfloat16 g_wtl[cNH * cH];
__device__ float g_c[cHM];
__device__ float g_T[cB * cN * cNH];
__device__ float g_norm[cB * cHM];
__device__ float g_yp[(size_t)8 * cB * cHM * cH];       // 8 K-split partials of y
__device__ float g_st[cB * cNH * 64 * 64];
__device__ float g_ost[cB * cNH * 64 * 64];

// ---------------- helpers ----------------
__device__ __forceinline__ uint32_t smem_u32(const void* p) {
    uint32_t a;
    asm("{ .reg .u64 t; cvta.to.shared.u64 t, %1; cvt.u32.u64 %0, t; }" : "=r"(a) : "l"(p));
    return a;
}
__device__ __forceinline__ void cp16(uint32_t s, const void* g) {
    asm volatile("cp.async.cg.shared.global [%0], [%1], 16;" :: "r"(s), "l"(g));
}
#define CP_COMMIT() asm volatile("cp.async.commit_group;" ::: "memory")
#define CP_WAIT1()  asm volatile("cp.async.wait_group 1;" ::: "memory")
#define CP_WAIT0()  asm volatile("cp.async.wait_group 0;" ::: "memory")

__device__ __forceinline__ void ldsm4(uint32_t* r, uint32_t a) {
    asm volatile("ldmatrix.sync.aligned.m8n8.x4.shared.b16 {%0,%1,%2,%3}, [%4];"
        : "=r"(r[0]), "=r"(r[1]), "=r"(r[2]), "=r"(r[3]) : "r"(a));
}
__device__ __forceinline__ void mma16816(float* d, const uint32_t* a,
                                         uint32_t b0, uint32_t b1) {
    asm volatile("mma.sync.aligned.m16n8k16.row.col.f32.bf16.bf16.f32 "
        "{%0,%1,%2,%3}, {%4,%5,%6,%7}, {%8,%9}, {%0,%1,%2,%3};"
        : "+f"(d[0]), "+f"(d[1]), "+f"(d[2]), "+f"(d[3])
        : "r"(a[0]), "r"(a[1]), "r"(a[2]), "r"(a[3]), "r"(b0), "r"(b1));
}
__device__ __forceinline__ void mma16816h(float* d, const uint32_t* a,
                                          uint32_t b0, uint32_t b1) {
    asm volatile("mma.sync.aligned.m16n8k16.row.col.f32.f16.f16.f32 "
        "{%0,%1,%2,%3}, {%4,%5,%6,%7}, {%8,%9}, {%0,%1,%2,%3};"
        : "+f"(d[0]), "+f"(d[1]), "+f"(d[2]), "+f"(d[3])
        : "r"(a[0]), "r"(a[1]), "r"(a[2]), "r"(a[3]), "r"(b0), "r"(b1));
}
__device__ __forceinline__ void split2(float v, __nv_bfloat16& h, __nv_bfloat16& l) {
    h = __float2bfloat16(v);
    l = __float2bfloat16(v - __bfloat162float(h));
}

// ===== bf16 3-term GEMM (scores only): CTA 128x256, warp 64x64, Kc=64 =======
constexpr int T_AH = 0, T_AL = 16384, T_BH = 32768, T_BL = 65536;
constexpr int BUFB = 98304;
constexpr int GSMEM = 2 * BUFB;   // 192 KB

__global__ void __launch_bounds__(256, 1)
mma_scores(const __nv_bfloat16* __restrict__ Ah, const __nv_bfloat16* __restrict__ Al,
           const __nv_bfloat16* __restrict__ Bh, const __nv_bfloat16* __restrict__ Bl,
           const float* __restrict__ bias)
{
    extern __shared__ __align__(128) char smem[];
    const int tid = threadIdx.x, wid = tid >> 5, lane = tid & 31;
    uint32_t sbase = smem_u32(smem);
    const int m0 = blockIdx.y * 128, n0 = blockIdx.x * 256;
    const int lda = 1024, ldb = 1024;

    auto issue = [&](int c) {
        const int kc = c << 6;
        uint32_t sb = sbase + (c & 1) * BUFB;
#pragma unroll
        for (int i = 0; i < 4; i++) {
            const int idx = (i << 8) + tid;
            const int row = idx >> 3, seg = idx & 7;
            uint32_t so = sb + row * 128 + ((seg ^ (row & 7)) << 4);
            long long go = (long long)(m0 + row) * lda + kc + seg * 8;
            cp16(so + T_AH, Ah + go);
            cp16(so + T_AL, Al + go);
        }
#pragma unroll
        for (int i = 0; i < 8; i++) {
            const int idx = (i << 8) + tid;
            const int row = idx >> 3, seg = idx & 7;
            uint32_t so = sb + row * 128 + ((seg ^ (row & 7)) << 4);
            long long go = (long long)(n0 + row) * ldb + kc + seg * 8;
            cp16(so + T_BH, Bh + go);
            cp16(so + T_BL, Bl + go);
        }
        CP_COMMIT();
    };

    issue(0);

    const int wm = (wid >> 2) * 64, wn = (wid & 3) * 64;
    const int arow  = wm + (lane & 15);
    const int akseg = lane >> 4;
    const int r7a   = arow & 7;
    const int brin  = ((lane >> 4) << 3) + (lane & 7);
    const int bkseg = (lane >> 3) & 1;
    const int r7b   = lane & 7;

    float acc[4][8][4];
#pragma unroll
    for (int a = 0; a < 4; a++)
#pragma unroll
        for (int b = 0; b < 8; b++)
#pragma unroll
            for (int q = 0; q < 4; q++) acc[a][b][q] = 0.f;

    for (int c = 0; c < 16; c++) {
        if (c + 1 < 16) { issue(c + 1); CP_WAIT1(); } else { CP_WAIT0(); }
        __syncthreads();
        uint32_t sb = sbase + (c & 1) * BUFB;
#pragma unroll
        for (int ks = 0; ks < 4; ks++) {
            const int ks2 = ks * 2;
            uint32_t ah[4][4], alr[4][4];
#pragma unroll
            for (int mt = 0; mt < 4; mt++) {
                uint32_t ao = sb + T_AH + (arow + mt * 16) * 128
                            + (uint32_t)((((ks2 + akseg) ^ r7a)) << 4);
                ldsm4(ah[mt], ao);
                ldsm4(alr[mt], ao + (T_AL - T_AH));
            }
#pragma unroll
            for (int half = 0; half < 2; half++) {
                uint32_t bh[2][4], bl[2][4];
#pragma unroll
                for (int p = 0; p < 2; p++) {
                    const int row = wn + (half * 2 + p) * 16 + brin;
                    uint32_t bo = sb + T_BH + row * 128
                                + (uint32_t)((((ks2 + bkseg) ^ r7b)) << 4);
                    ldsm4(bh[p], bo);
                    ldsm4(bl[p], bo + (T_BL - T_BH));
                }
#pragma unroll
                for (int mt = 0; mt < 4; mt++)
#pragma unroll
                    for (int q = 0; q < 4; q++) {
                        const int nt = half * 4 + q;
                        const int p = q >> 1, hb = (q & 1) * 2;
                        mma16816(acc[mt][nt], ah[mt],  bh[p][hb], bh[p][hb + 1]);
                        mma16816(acc[mt][nt], ah[mt],  bl[p][hb], bl[p][hb + 1]);
                        mma16816(acc[mt][nt], alr[mt], bh[p][hb], bh[p][hb + 1]);
                    }
            }
        }
        __syncthreads();
    }

    const int rr = lane >> 2, cc = (lane & 3) * 2;
    // ---- fused softmax over m + norm + fp16 dual-layout stores ----
    float* sf = (float*)smem;                 // 128 x 256, pitch 261
#pragma unroll
    for (int mt = 0; mt < 4; mt++) {
#pragma unroll
        for (int nt = 0; nt < 8; nt++) {
            int r = wm + mt * 16 + rr;
            int col = wn + nt * 8 + cc;
            float2 b2 = *(const float2*)(bias + n0 + col);
            sf[r * 261 + col]           = acc[mt][nt][0] + b2.x;
            sf[r * 261 + col + 1]       = acc[mt][nt][1] + b2.y;
            sf[(r + 8) * 261 + col]     = acc[mt][nt][2] + b2.x;
            sf[(r + 8) * 261 + col + 1] = acc[mt][nt][3] + b2.y;
        }
    }
    __syncthreads();
#pragma unroll
    for (int it = 0; it < 2; it++) {
        int task = it * 256 + tid;
        int row = task & 127, hq = task >> 7;
        size_t bn = (size_t)m0 + row;
        int headg = (n0 >> 6) + hq;
        float inv_t = 1.0f / g_T[bn * 16 + headg];
        float* rp = sf + row * 261 + hq * 64;
        float mx = -1e30f;
#pragma unroll 8
        for (int i = 0; i < 64; i++) mx = fmaxf(mx, rp[i]);
        float sum = 0.f;
#pragma unroll 8
        for (int i = 0; i < 64; i++) {
            float e = expf((rp[i] - mx) * inv_t);
            rp[i] = e; sum += e;
        }
        float inv = 1.0f / sum;
#pragma unroll 8
        for (int i = 0; i < 64; i++) rp[i] *= inv;
    }
    __syncthreads();
    const int bidx = m0 >> 13;
    {
        float s = 0.f;
#pragma unroll 8
        for (int i = 0; i < 128; i++) s += sf[i * 261 + tid];
        atomicAdd(&g_norm[bidx * 1024 + n0 + tid], s);
    }
#pragma unroll
    for (int i = 0; i < 64; i++) {
        int p = i * 256 + tid;
        int row = p >> 7, col = (p & 127) << 1;
        float w0 = sf[row * 261 + col], w1 = sf[row * 261 + col + 1];
        size_t o = ((size_t)m0 + row) * 1024 + n0 + col;
        *(__half2*)(g_Sf + o) = __floats2half2_rn(w0, w1);
    }
    {
        int nb = m0 & 8191;
#pragma unroll
        for (int i = 0; i < 64; i++) {
            int p = i * 256 + tid;
            int hm = p >> 6, n2 = (p & 63) << 1;
            float w0 = sf[n2 * 261 + hm], w1 = sf[(n2 + 1) * 261 + hm];
            size_t o = ((size_t)bidx * 1024 + n0 + hm) * 8192 + nb + n2;
            *(__half2*)(g_Sft + o) = __floats2half2_rn(w0, w1);
        }
    }
}

// ===== fp16 single-pass GEMM (y / out): CTA 128x256, warp 64x64, Kc=64 ======
constexpr int S1_A = 0, S1_B = 16384;
constexpr int BUF1 = 49152;
constexpr int GSMEM1 = 2 * BUF1;   // 96 KB

template<int EPI>   // 0 = plain store (K-split partials), 1 = bias + store
__global__ void __launch_bounds__(256, 1)
mma1_gemm(const __half* __restrict__ A, const __half* __restrict__ B,
          float* __restrict__ C, const float* __restrict__ bias,
          int Kdim, int lda, int ldb, int ldc,
          long long sA, long long sB, long long sC, long long sCk, int ksl)
{
    extern __shared__ __align__(128) char smem[];
    const int tid = threadIdx.x, wid = tid >> 5, lane = tid & 31;
    uint32_t sbase = smem_u32(smem);
    const long long zz = blockIdx.z;
    const long long batch = zz >> ksl;
    const long long kidx = zz & ((1 << ksl) - 1);
    A += batch * sA + kidx * (long long)Kdim;
    B += batch * sB + kidx * (long long)Kdim;
    C += batch * sC + kidx * sCk;
    const int m0 = blockIdx.y * 128, n0 = blockIdx.x * 256;

    auto issue = [&](int c) {
        const int kc = c << 6;
        uint32_t sb = sbase + (c & 1) * BUF1;
#pragma unroll
        for (int i = 0; i < 4; i++) {
            const int idx = (i << 8) + tid;
            const int row = idx >> 3, seg = idx & 7;
            uint32_t so = sb + S1_A + row * 128 + ((seg ^ (row & 7)) << 4);
            cp16(so, A + (long long)(m0 + row) * lda + kc + seg * 8);
        }
#pragma unroll
        for (int i = 0; i < 8; i++) {
            const int idx = (i << 8) + tid;
            const int row = idx >> 3, seg = idx & 7;
            uint32_t so = sb + S1_B + row * 128 + ((seg ^ (row & 7)) << 4);
            cp16(so, B + (long long)(n0 + row) * ldb + kc + seg * 8);
        }
        CP_COMMIT();
    };

    const int NC = Kdim >> 6;
    issue(0);

    const int wm = (wid >> 2) * 64, wn = (wid & 3) * 64;
    const int arow  = wm + (lane & 15);
    const int akseg = lane >> 4;
    const int r7a   = arow & 7;
    const int brin  = ((lane >> 4) << 3) + (lane & 7);
    const int bkseg = (lane >> 3) & 1;
    const int r7b   = lane & 7;

    float acc[4][8][4];
#pragma unroll
    for (int a = 0; a < 4; a++)
#pragma unroll
        for (int b = 0; b < 8; b++)
#pragma unroll
            for (int q = 0; q < 4; q++) acc[a][b][q] = 0.f;

    for (int c = 0; c < NC; c++) {
        if (c + 1 < NC) { issue(c + 1); CP_WAIT1(); } else { CP_WAIT0(); }
        __syncthreads();
        uint32_t sb = sbase + (c & 1) * BUF1;
#pragma unroll
        for (int ks = 0; ks < 4; ks++) {
            const int ks2 = ks * 2;
            uint32_t ah[4][4];
#pragma unroll
            for (int mt = 0; mt < 4; mt++) {
                uint32_t ao = sb + S1_A + (arow + mt * 16) * 128
                            + (uint32_t)((((ks2 + akseg) ^ r7a)) << 4);
                ldsm4(ah[mt], ao);
            }
#pragma unroll
            for (int half = 0; half < 2; half++) {
                uint32_t bh[2][4];
#pragma unroll
                for (int p = 0; p < 2; p++) {
                    const int row = wn + (half * 2 + p) * 16 + brin;
                    uint32_t bo = sb + S1_B + row * 128
                                + (uint32_t)((((ks2 + bkseg) ^ r7b)) << 4);
                    ldsm4(bh[p], bo);
                }
#pragma unroll
                for (int mt = 0; mt < 4; mt++)
#pragma unroll
                    for (int q = 0; q < 4; q++) {
                        const int nt = half * 4 + q;
                        const int p = q >> 1, hb = (q & 1) * 2;
                        mma16816h(acc[mt][nt], ah[mt], bh[p][hb], bh[p][hb + 1]);
                    }
            }
        }
        __syncthreads();
    }

    const int rr = lane >> 2, cc = (lane & 3) * 2;
#pragma unroll
    for (int mt = 0; mt < 4; mt++) {
        const long long m = m0 + wm + mt * 16 + rr;
#pragma unroll
        for (int nt = 0; nt < 8; nt++) {
            const int n = n0 + wn + nt * 8 + cc;
            float bx = 0.f, by = 0.f;
            if (EPI == 1) {
                float2 b2 = *(const float2*)(bias + n);
                bx = b2.x; by = b2.y;
            }
            float2 v0 = make_float2(acc[mt][nt][0] + bx, acc[mt][nt][1] + by);
            float2 v1 = make_float2(acc[mt][nt][2] + bx, acc[mt][nt][3] + by);
            *(float2*)(C + m * ldc + n)       = v0;
            *(float2*)(C + (m + 8) * ldc + n) = v1;
        }
    }
}

// ============ temperature GEMM (bf16 split, unchanged) ============
constexpr int TG_AH = 0, TG_AL = 16384;
constexpr int TG_BUF = 32768;
constexpr int TG_BH = 65536, TG_BL = 98304;
constexpr int TGSMEM = 131072;

__global__ void __launch_bounds__(256, 1)
k_tempmma(const __nv_bfloat16* __restrict__ xh, const __nv_bfloat16* __restrict__ xl,
          const float* __restrict__ b_temp)
{
    extern __shared__ __align__(128) char smem[];
    const int tid = threadIdx.x, wid = tid >> 5, lane = tid & 31;
    uint32_t sbase = smem_u32(smem);
    const int m0 = blockIdx.x * 128;

#pragma unroll
    for (int q = 0; q < 8; q++) {
        int i = q * 256 + tid;
        int c = i >> 7, r = (i >> 3) & 15, seg = i & 7;
        uint32_t so = sbase + TG_BH + c * 2048 + r * 128 + ((seg ^ (r & 7)) << 4);
        cp16(so, g_wth + r * 1024 + c * 64 + seg * 8);
        cp16(so + (TG_BL - TG_BH), g_wtl + r * 1024 + c * 64 + seg * 8);
    }

    auto issueA = [&](int c) {
        uint32_t sb = sbase + (c & 1) * TG_BUF;
        const int kc = c << 6;
#pragma unroll
        for (int q = 0; q < 4; q++) {
            int i = q * 256 + tid;
            int row = i >> 3, seg = i & 7;
            uint32_t so = sb + row * 128 + ((seg ^ (row & 7)) << 4);
            cp16(so,                   xh + (long long)(m0 + row) * 1024 + kc + seg * 8);
            cp16(so + (TG_AL - TG_AH), xl + (long long)(m0 + row) * 1024 + kc + seg * 8);
        }
        CP_COMMIT();
    };
    issueA(0);

    const int wm = wid * 16;
    const int arow  = wm + (lane & 15);
    const int akseg = lane >> 4;
    const int r7a   = arow & 7;
    const int brow  = ((lane >> 4) << 3) + (lane & 7);
    const int bkseg = (lane >> 3) & 1;
    const int r7b   = brow & 7;

    float acc[2][4];
#pragma unroll
    for (int nt = 0; nt < 2; nt++)
#pragma unroll
        for (int q = 0; q < 4; q++) acc[nt][q] = 0.f;

    for (int c = 0; c < 16; c++) {
        if (c + 1 < 16) { issueA(c + 1); CP_WAIT1(); } else { CP_WAIT0(); }
        __syncthreads();
        uint32_t sa = sbase + (c & 1) * TG_BUF;
        uint32_t sbb = sbase + TG_BH + c * 2048;
#pragma unroll
        for (int ks = 0; ks < 4; ks++) {
            const int ks2 = ks * 2;
            uint32_t ah[4], alr[4], bh[4], bl[4];
            uint32_t ao = sa + arow * 128 + (uint32_t)((((ks2 + akseg) ^ r7a)) << 4);
            ldsm4(ah, ao);
            ldsm4(alr, ao + (TG_AL - TG_AH));
            uint32_t bo = sbb + brow * 128 + (uint32_t)((((ks2 + bkseg) ^ r7b)) << 4);
            ldsm4(bh, bo);
            ldsm4(bl, bo + (TG_BL - TG_BH));
#pragma unroll
            for (int nt = 0; nt < 2; nt++) {
                const int hb = nt * 2;
                mma16816(acc[nt], ah,  bh[hb], bh[hb + 1]);
                mma16816(acc[nt], ah,  bl[hb], bl[hb + 1]);
                mma16816(acc[nt], alr, bh[hb], bh[hb + 1]);
            }
        }
        __syncthreads();
    }

    const int rr = lane >> 2, cc = (lane & 3) * 2;
    const long long r0 = m0 + wm + rr, r1 = r0 + 8;
#pragma unroll
    for (int nt = 0; nt < 2; nt++) {
        int head = nt * 8 + cc;
        float b0 = b_temp[head], b1 = b_temp[head + 1];
        float v[4] = {acc[nt][0] + b0, acc[nt][1] + b1,
                      acc[nt][2] + b0, acc[nt][3] + b1};
#pragma unroll
        for (int q = 0; q < 4; q++) {
            float s = v[q];
            v[q] = 0.5f + fmaxf(s, 0.f) + log1pf(expf(-fabsf(s)));
        }
        g_T[r0 * 16 + head]     = v[0];
        g_T[r0 * 16 + head + 1] = v[1];
        g_T[r1 * 16 + head]     = v[2];
        g_T[r1 * 16 + head + 1] = v[3];
    }
}

// ============ aux kernels ============
__global__ void k_zero()
{
    int i = blockIdx.x * 256 + threadIdx.x;
    if (i < cB * cHM) g_norm[i] = 0.f;
}

__global__ void __launch_bounds__(256)
k_wsplit(const float* __restrict__ w_temp)
{
    int idx = blockIdx.x * 256 + threadIdx.x;
    int h = idx >> 10, j = idx & 1023;
    __nv_bfloat16 hh, ll;
    split2(w_temp[j * 16 + h], hh, ll);
    g_wth[idx] = hh;
    g_wtl[idx] = ll;
}

__global__ void __launch_bounds__(256)
k_prep(const float* __restrict__ xq, const float* __restrict__ w_kv,
       const float* __restrict__ b_kv)
{
    int idx = blockIdx.x * 256 + threadIdx.x;
    int j = idx >> 10, hm = idx & 1023;
    int hbase = (hm >> 6) << 6;
    const float* xr = xq + (size_t)hm * 64;
    const float* wr = w_kv + (size_t)j * 2048 + hbase;
    float acc = 0.f;
#pragma unroll 8
    for (int d = 0; d < 64; d++) acc += xr[d] * wr[d];
    __nv_bfloat16 h, l; split2(acc, h, l);
    g_Ath[(size_t)hm * 1024 + j] = h;
    g_Atl[(size_t)hm * 1024 + j] = l;
    if (j == 0) {
        const float* br = b_kv + hbase;
        float cc = 0.f;
        for (int d = 0; d < 64; d++) cc += xr[d] * br[d];
        g_c[hm] = cc;
    }
}

// x -> (xh,xl bf16 straight) + (xtf fp16 transposed); coalesced
__global__ void __launch_bounds__(256)
k_convx(const float* __restrict__ x)
{
    __shared__ float xs[64][67];
    const int jt = blockIdx.x, nt = blockIdx.y;
    const int t = threadIdx.x;
#pragma unroll
    for (int q = 0; q < 4; q++) {
        int lin = q * 256 + t;
        int row = lin >> 4, c4 = (lin & 15) << 2;
        float4 v = *(const float4*)(x + ((size_t)nt * 64 + row) * 1024 + jt * 64 + c4);
        xs[row][c4 + 0] = v.x; xs[row][c4 + 1] = v.y;
        xs[row][c4 + 2] = v.z; xs[row][c4 + 3] = v.w;
    }
    __syncthreads();
#pragma unroll
    for (int q = 0; q < 8; q++) {
        int lin = q * 256 + t;
        int row = lin >> 5, col = (lin & 31) << 1;
        float w0 = xs[row][col], w1 = xs[row][col + 1];
        __nv_bfloat16 h0, l0, h1, l1;
        split2(w0, h0, l0); split2(w1, h1, l1);
        size_t o = ((size_t)nt * 64 + row) * 1024 + jt * 64 + col;
        *(__nv_bfloat162*)(g_xh + o) = __nv_bfloat162(h0, h1);
        *(__nv_bfloat162*)(g_xl + o) = __nv_bfloat162(l0, l1);
    }
    const int b = (nt * 64) >> 13, nn0 = (nt * 64) & 8191;
#pragma unroll
    for (int q = 0; q < 8; q++) {
        int lin = q * 256 + t;
        int j = lin >> 5, n2 = (lin & 31) << 1;
        size_t o = ((size_t)(b * 1024 + jt * 64 + j)) * 8192 + nn0 + n2;
        *(__half2*)(g_xtf + o) = __floats2half2_rn(xs[n2][j], xs[n2 + 1][j]);
    }
}

// slice_token from 8 y-partials
__global__ void __launch_bounds__(256)
k_st(const float* __restrict__ w_kv, const float* __restrict__ b_kv)
{
    int z = blockIdx.x;
    int b = z >> 4, h = z & 15;
    constexpr size_t YPS = (size_t)cB * cHM * cH;
    const float* Yb = g_yp + ((size_t)b * 1024 + h * 64) * 1024;
    const float* Wv = w_kv + 1024 + h * 64;
    __shared__ float As[16][64];
    __shared__ float Bs[16][64];
    int t = threadIdx.x;
    int tyy = t >> 4, txx = t & 15;
    float acc[4][4] = {};
    for (int k0 = 0; k0 < 1024; k0 += 16) {
        {
            int m = t >> 2, k4 = (t & 3) << 2;
            size_t off = (size_t)m * 1024 + k0 + k4;
            float4 vs = make_float4(0.f, 0.f, 0.f, 0.f);
#pragma unroll
            for (int p = 0; p < 8; p++) {
                float4 v = *(const float4*)(Yb + p * YPS + off);
                vs.x += v.x; vs.y += v.y; vs.z += v.z; vs.w += v.w;
            }
            As[k4 + 0][m] = vs.x; As[k4 + 1][m] = vs.y;
            As[k4 + 2][m] = vs.z; As[k4 + 3][m] = vs.w;
        }
        {
            int k = t >> 4, n4 = (t & 15) << 2;
            *(float4*)&Bs[k][n4] = *(const float4*)(Wv + (size_t)(k0 + k) * 2048 + n4);
        }
        __syncthreads();
#pragma unroll
        for (int kk = 0; kk < 16; kk++) {
            float4 a  = *(const float4*)&As[kk][tyy * 4];
            float4 bb = *(const float4*)&Bs[kk][txx * 4];
            float av[4] = {a.x, a.y, a.z, a.w};
            float bv[4] = {bb.x, bb.y, bb.z, bb.w};
#pragma unroll
            for (int i = 0; i < 4; i++)
#pragma unroll
                for (int jj = 0; jj < 4; jj++) acc[i][jj] += av[i] * bv[jj];
        }
        __syncthreads();
    }
#pragma unroll
    for (int i = 0; i < 4; i++) {
        int m = tyy * 4 + i;
        float nrm = g_norm[b * 1024 + h * 64 + m];
        float inv = 1.0f / (nrm + 1e-5f);
#pragma unroll
        for (int jj = 0; jj < 4; jj++) {
            int d = txx * 4 + jj;
            float bvv = b_kv[1024 + h * 64 + d];
            g_st[((size_t)z * 64 + m) * 64 + d] = (acc[i][jj] + nrm * bvv) * inv;
        }
    }
}

__global__ void __launch_bounds__(64)
k_qkv(const float* __restrict__ qkv_proj)
{
    int z = blockIdx.x;
    int h = (z >> 6) & 15;
    int d = threadIdx.x;
    __shared__ float st[64];
    __shared__ float ex[64];
    st[d] = g_st[(size_t)z * 64 + d];
    __syncthreads();
    const float* P = qkv_proj + (size_t)h * 64 * 192;
    float q = 0.f, k = 0.f, v = 0.f;
#pragma unroll 8
    for (int j = 0; j < 64; j++) {
        float s = st[j];
        const float* pr = P + j * 192;
        q += s * pr[d]; k += s * pr[64 + d]; v += s * pr[128 + d];
    }
    float dot = q * k * 0.125f;
    ex[d] = dot;
    __syncthreads();
    float mx = -1e30f;
    for (int j = 0; j < 64; j++) mx = fmaxf(mx, ex[j]);
    __syncthreads();
    float e = expf(dot - mx);
    ex[d] = e;
    __syncthreads();
    float sum = 0.f;
    for (int j = 0; j < 64; j++) sum += ex[j];
    g_ost[(size_t)z * 64 + d] = (e / sum) * v;
}

__global__ void __launch_bounds__(256)
k_zmat(const float* __restrict__ w_out)
{
    int z = blockIdx.y, jc = blockIdx.x;
    int b = z >> 4, h = z & 15;
    __shared__ float As[64][64];
    __shared__ float Bs[64][64];
    int t = threadIdx.x;
#pragma unroll
    for (int r = 0; r < 4; r++) {
        int lin = t + r * 256;
        int row = lin >> 4;
        int c4  = (lin & 15) << 2;
        float4 v = *(const float4*)(g_ost + ((size_t)z * 64 + row) * 64 + c4);
        As[c4 + 0][row] = v.x; As[c4 + 1][row] = v.y;
        As[c4 + 2][row] = v.z; As[c4 + 3][row] = v.w;
        *(float4*)&Bs[row][c4] =
            *(const float4*)(w_out + (size_t)(h * 64 + row) * 1024 + jc * 64 + c4);
    }
    __syncthreads();
    int tyy = t >> 4, txx = t & 15;
    float acc[4][4] = {};
#pragma unroll
    for (int kk = 0; kk < 64; kk++) {
        float4 a  = *(const float4*)&As[kk][tyy * 4];
        float4 bb = *(const float4*)&Bs[kk][txx * 4];
        float av[4] = {a.x, a.y, a.z, a.w};
        float bv[4] = {bb.x, bb.y, bb.z, bb.w};
#pragma unroll
        for (int i = 0; i < 4; i++)
#pragma unroll
            for (int jj = 0; jj < 4; jj++) acc[i][jj] += av[i] * bv[jj];
    }
#pragma unroll
    for (int i = 0; i < 4; i++) {
        int hm = h * 64 + tyy * 4 + i;
#pragma unroll
        for (int jj = 0; jj < 4; jj++) {
            int j = jc * 64 + txx * 4 + jj;
            g_Ztf[((size_t)b * 1024 + j) * 1024 + hm] = __float2half(acc[i][jj]);
        }
    }
}

// ---------------------------------------------------------------------------
extern "C" void kernel_launch(void* const* d_in, const int* in_sizes, int n_in,
                              void* d_out, int out_size)
{
    (void)in_sizes; (void)n_in; (void)out_size;
    const float* x      = (const float*)d_in[0];
    const float* w_kv   = (const float*)d_in[2];
    const float* b_kv   = (const float*)d_in[3];
    const float* w_temp = (const float*)d_in[4];
    const float* b_temp = (const float*)d_in[5];
    const float* xq     = (const float*)d_in[6];
    const float* qkv_p  = (const float*)d_in[7];
    const float* w_out  = (const float*)d_in[8];
    const float* b_out  = (const float*)d_in[9];
    float* out = (float*)d_out;

    float *pc, *pyp;
    __nv_bfloat16 *pxh, *pxl, *pAth, *pAtl;
    __half *pxtf, *pSf, *pSft, *pZtf;
    cudaGetSymbolAddress((void**)&pc,  g_c);
    cudaGetSymbolAddress((void**)&pyp, g_yp);
    cudaGetSymbolAddress((void**)&pxh, g_xh);   cudaGetSymbolAddress((void**)&pxl, g_xl);
    cudaGetSymbolAddress((void**)&pxtf, g_xtf);
    cudaGetSymbolAddress((void**)&pSf, g_Sf);   cudaGetSymbolAddress((void**)&pSft, g_Sft);
    cudaGetSymbolAddress((void**)&pAth, g_Ath); cudaGetSymbolAddress((void**)&pAtl, g_Atl);
    cudaGetSymbolAddress((void**)&pZtf, g_Ztf);

    cudaFuncSetAttribute(mma_scores,   cudaFuncAttributeMaxDynamicSharedMemorySize, GSMEM);
    cudaFuncSetAttribute(mma1_gemm<0>, cudaFuncAttributeMaxDynamicSharedMemorySize, GSMEM1);
    cudaFuncSetAttribute(mma1_gemm<1>, cudaFuncAttributeMaxDynamicSharedMemorySize, GSMEM1);
    cudaFuncSetAttribute(k_tempmma,    cudaFuncAttributeMaxDynamicSharedMemorySize, TGSMEM);

    k_zero<<<16, 256>>>();
    k_wsplit<<<64, 256>>>(w_temp);
    k_prep<<<4096, 256>>>(xq, w_kv, b_kv);
    k_convx<<<dim3(16, 512), 256>>>(x);
    k_tempmma<<<256, 256, TGSMEM>>>(pxh, pxl, b_temp);
    // scores (bf16 3-term) + fused softmax/norm/fp16 stores
    mma_scores<<<dim3(4, 256, 1), 256, GSMEM>>>(pxh, pxl, pAth, pAtl, pc);
    // y[b] = S[b]^T @ x[b] (fp16 single-pass), K-split x8
    mma1_gemm<0><<<dim3(4, 8, cB * 8), 256, GSMEM1>>>(
        pSft, pxtf, pyp, nullptr,
        1024, 8192, 8192, 1024,
        (long long)cHM * cN, (long long)cH * cN,
        (long long)cHM * cH, (long long)cB * cHM * cH, 3);
    k_st<<<cB * cNH, 256>>>(w_kv, b_kv);
    k_qkv<<<cB * cNH * 64, 64>>>(qkv_p);
    k_zmat<<<dim3(16, cB * cNH), 256>>>(w_out);
    // out[b] = S[b] @ Zt[b]^T + b_out (fp16 single-pass)
    mma1_gemm<1><<<dim3(4, 64, cB), 256, GSMEM1>>>(
        pSf, pZtf, out, b_out,
        1024, 1024, 1024, 1024,
        (long long)cN * cHM, (long long)cH * cHM,
        (long long)cN * cH, 0, 0);
}

// round 13
// speedup vs baseline: 1.7299x; 1.0221x over previous
#include <cuda_runtime.h>
#include <cuda_bf16.h>
#include <cuda_fp16.h>
#include <math.h>
#include <stdint.h>

constexpr int cB = 4, cN = 8192, cH = 1024, cNH = 16, cHM = 1024;

// ---------------- scratch (device globals) ----------------
__device__ __nv_bfloat16 g_xh [(size_t)cB * cN * cH];
__device__ __nv_bfloat16 g_xl [(size_t)cB * cN * cH];
__device__ __half        g_xtf[(size_t)cB * cH * cN];
__device__ __half        g_Sf [(size_t)cB * cN * cHM];
__device__ __half        g_Sft[(size_t)cB * cHM * cN];
__device__ __nv_bfloat16 g_Ath[cHM * cH];
__device__ __nv_bfloat16 g_Atl[cHM * cH];
__device__ __half        g_Ztf[(size_t)cB * cH * cHM];
__device__ __nv_bfloat16 g_wth[cNH * cH];
__device__ __nv_bfloat16 g_wtl[cNH * cH];
__device__ float g_c[cHM];
__device__ float g_T[cB * cN * cNH];
__device__ float g_norm[cB * cHM];
__device__ float g_yp[(size_t)8 * cB * cHM * cH];
__device__ float g_st[cB * cNH * 64 * 64];
__device__ float g_ost[cB * cNH * 64 * 64];

// ---------------- helpers ----------------
__device__ __forceinline__ uint32_t smem_u32(const void* p) {
    uint32_t a;
    asm("{ .reg .u64 t; cvta.to.shared.u64 t, %1; cvt.u32.u64 %0, t; }" : "=r"(a) : "l"(p));
    return a;
}
__device__ __forceinline__ void cp16(uint32_t s, const void* g) {
    asm volatile("cp.async.cg.shared.global [%0], [%1], 16;" :: "r"(s), "l"(g));
}
#define CP_COMMIT() asm volatile("cp.async.commit_group;" ::: "memory")
#define CP_WAIT1()  asm volatile("cp.async.wait_group 1;" ::: "memory")
#define CP_WAIT0()  asm volatile("cp.async.wait_group 0;" ::: "memory")

__device__ __forceinline__ void ldsm4(uint32_t* r, uint32_t a) {
    asm volatile("ldmatrix.sync.aligned.m8n8.x4.shared.b16 {%0,%1,%2,%3}, [%4];"
        : "=r"(r[0]), "=r"(r[1]), "=r"(r[2]), "=r"(r[3]) : "r"(a));
}
__device__ __forceinline__ void mma16816(float* d, const uint32_t* a,
                                         uint32_t b0, uint32_t b1) {
    asm volatile("mma.sync.aligned.m16n8k16.row.col.f32.bf16.bf16.f32 "
        "{%0,%1,%2,%3}, {%4,%5,%6,%7}, {%8,%9}, {%0,%1,%2,%3};"
        : "+f"(d[0]), "+f"(d[1]), "+f"(d[2]), "+f"(d[3])
        : "r"(a[0]), "r"(a[1]), "r"(a[2]), "r"(a[3]), "r"(b0), "r"(b1));
}
__device__ __forceinline__ void mma16816h(float* d, const uint32_t* a,
                                          uint32_t b0, uint32_t b1) {
    asm volatile("mma.sync.aligned.m16n8k16.row.col.f32.f16.f16.f32 "
        "{%0,%1,%2,%3}, {%4,%5,%6,%7}, {%8,%9}, {%0,%1,%2,%3};"
        : "+f"(d[0]), "+f"(d[1]), "+f"(d[2]), "+f"(d[3])
        : "r"(a[0]), "r"(a[1]), "r"(a[2]), "r"(a[3]), "r"(b0), "r"(b1));
}
__device__ __forceinline__ void split2(float v, __nv_bfloat16& h, __nv_bfloat16& l) {
    h = __float2bfloat16(v);
    l = __float2bfloat16(v - __bfloat162float(h));
}

// ===== bf16 3-term GEMM (scores only): CTA 128x256, warp 64x64, Kc=64 =======
constexpr int T_AH = 0, T_AL = 16384, T_BH = 32768, T_BL = 65536;
constexpr int BUFB = 98304;
constexpr int GSMEM = 2 * BUFB;   // 192 KB

__global__ void __launch_bounds__(256, 1)
mma_scores(const __nv_bfloat16* __restrict__ Ah, const __nv_bfloat16* __restrict__ Al,
           const __nv_bfloat16* __restrict__ Bh, const __nv_bfloat16* __restrict__ Bl,
           const float* __restrict__ bias)
{
    extern __shared__ __align__(128) char smem[];
    const int tid = threadIdx.x, wid = tid >> 5, lane = tid & 31;
    uint32_t sbase = smem_u32(smem);
    const int m0 = blockIdx.y * 128, n0 = blockIdx.x * 256;
    const int lda = 1024, ldb = 1024;

    auto issue = [&](int c) {
        const int kc = c << 6;
        uint32_t sb = sbase + (c & 1) * BUFB;
#pragma unroll
        for (int i = 0; i < 4; i++) {
            const int idx = (i << 8) + tid;
            const int row = idx >> 3, seg = idx & 7;
            uint32_t so = sb + row * 128 + ((seg ^ (row & 7)) << 4);
            long long go = (long long)(m0 + row) * lda + kc + seg * 8;
            cp16(so + T_AH, Ah + go);
            cp16(so + T_AL, Al + go);
        }
#pragma unroll
        for (int i = 0; i < 8; i++) {
            const int idx = (i << 8) + tid;
            const int row = idx >> 3, seg = idx & 7;
            uint32_t so = sb + row * 128 + ((seg ^ (row & 7)) << 4);
            long long go = (long long)(n0 + row) * ldb + kc + seg * 8;
            cp16(so + T_BH, Bh + go);
            cp16(so + T_BL, Bl + go);
        }
        CP_COMMIT();
    };

    issue(0);

    const int wm = (wid >> 2) * 64, wn = (wid & 3) * 64;
    const int arow  = wm + (lane & 15);
    const int akseg = lane >> 4;
    const int r7a   = arow & 7;
    const int brin  = ((lane >> 4) << 3) + (lane & 7);
    const int bkseg = (lane >> 3) & 1;
    const int r7b   = lane & 7;

    float acc[4][8][4];
#pragma unroll
    for (int a = 0; a < 4; a++)
#pragma unroll
        for (int b = 0; b < 8; b++)
#pragma unroll
            for (int q = 0; q < 4; q++) acc[a][b][q] = 0.f;

    for (int c = 0; c < 16; c++) {
        if (c + 1 < 16) { issue(c + 1); CP_WAIT1(); } else { CP_WAIT0(); }
        __syncthreads();
        uint32_t sb = sbase + (c & 1) * BUFB;
#pragma unroll
        for (int ks = 0; ks < 4; ks++) {
            const int ks2 = ks * 2;
            uint32_t ah[4][4], alr[4][4];
#pragma unroll
            for (int mt = 0; mt < 4; mt++) {
                uint32_t ao = sb + T_AH + (arow + mt * 16) * 128
                            + (uint32_t)((((ks2 + akseg) ^ r7a)) << 4);
                ldsm4(ah[mt], ao);
                ldsm4(alr[mt], ao + (T_AL - T_AH));
            }
#pragma unroll
            for (int half = 0; half < 2; half++) {
                uint32_t bh[2][4], bl[2][4];
#pragma unroll
                for (int p = 0; p < 2; p++) {
                    const int row = wn + (half * 2 + p) * 16 + brin;
                    uint32_t bo = sb + T_BH + row * 128
                                + (uint32_t)((((ks2 + bkseg) ^ r7b)) << 4);
                    ldsm4(bh[p], bo);
                    ldsm4(bl[p], bo + (T_BL - T_BH));
                }
#pragma unroll
                for (int mt = 0; mt < 4; mt++)
#pragma unroll
                    for (int q = 0; q < 4; q++) {
                        const int nt = half * 4 + q;
                        const int p = q >> 1, hb = (q & 1) * 2;
                        mma16816(acc[mt][nt], ah[mt],  bh[p][hb], bh[p][hb + 1]);
                        mma16816(acc[mt][nt], ah[mt],  bl[p][hb], bl[p][hb + 1]);
                        mma16816(acc[mt][nt], alr[mt], bh[p][hb], bh[p][hb + 1]);
                    }
            }
        }
        __syncthreads();
    }

    const int rr = lane >> 2, cc = (lane & 3) * 2;
    // ---- fused softmax over m + norm + fp16 dual-layout stores ----
    float* sf = (float*)smem;                 // 128 x 256, pitch 261
#pragma unroll
    for (int mt = 0; mt < 4; mt++) {
#pragma unroll
        for (int nt = 0; nt < 8; nt++) {
            int r = wm + mt * 16 + rr;
            int col = wn + nt * 8 + cc;
            float2 b2 = *(const float2*)(bias + n0 + col);
            sf[r * 261 + col]           = acc[mt][nt][0] + b2.x;
            sf[r * 261 + col + 1]       = acc[mt][nt][1] + b2.y;
            sf[(r + 8) * 261 + col]     = acc[mt][nt][2] + b2.x;
            sf[(r + 8) * 261 + col + 1] = acc[mt][nt][3] + b2.y;
        }
    }
    __syncthreads();
#pragma unroll
    for (int it = 0; it < 2; it++) {
        int task = it * 256 + tid;
        int row = task & 127, hq = task >> 7;
        size_t bn = (size_t)m0 + row;
        int headg = (n0 >> 6) + hq;
        float inv_t = 1.0f / g_T[bn * 16 + headg];
        float* rp = sf + row * 261 + hq * 64;
        float mx = -1e30f;
#pragma unroll 8
        for (int i = 0; i < 64; i++) mx = fmaxf(mx, rp[i]);
        float sum = 0.f;
#pragma unroll 8
        for (int i = 0; i < 64; i++) {
            float e = expf((rp[i] - mx) * inv_t);
            rp[i] = e; sum += e;
        }
        float inv = 1.0f / sum;
#pragma unroll 8
        for (int i = 0; i < 64; i++) rp[i] *= inv;
    }
    __syncthreads();
    const int bidx = m0 >> 13;
    {
        float s = 0.f;
#pragma unroll 8
        for (int i = 0; i < 128; i++) s += sf[i * 261 + tid];
        atomicAdd(&g_norm[bidx * 1024 + n0 + tid], s);
    }
#pragma unroll
    for (int i = 0; i < 64; i++) {
        int p = i * 256 + tid;
        int row = p >> 7, col = (p & 127) << 1;
        float w0 = sf[row * 261 + col], w1 = sf[row * 261 + col + 1];
        size_t o = ((size_t)m0 + row) * 1024 + n0 + col;
        *(__half2*)(g_Sf + o) = __floats2half2_rn(w0, w1);
    }
    {
        int nb = m0 & 8191;
#pragma unroll
        for (int i = 0; i < 64; i++) {
            int p = i * 256 + tid;
            int hm = p >> 6, n2 = (p & 63) << 1;
            float w0 = sf[n2 * 261 + hm], w1 = sf[(n2 + 1) * 261 + hm];
            size_t o = ((size_t)bidx * 1024 + n0 + hm) * 8192 + nb + n2;
            *(__half2*)(g_Sft + o) = __floats2half2_rn(w0, w1);
        }
    }
}

// ===== fp16 single-pass GEMM (y / out): CTA 128x256, warp 64x64, Kc=64 ======
constexpr int S1_A = 0, S1_B = 16384;
constexpr int BUF1 = 49152;
constexpr int GSMEM1 = 2 * BUF1;   // 96 KB

template<int EPI>   // 0 = plain store (K-split partials), 1 = bias + store
__global__ void __launch_bounds__(256, 1)
mma1_gemm(const __half* __restrict__ A, const __half* __restrict__ B,
          float* __restrict__ C, const float* __restrict__ bias,
          int Kdim, int lda, int ldb, int ldc,
          long long sA, long long sB, long long sC, long long sCk, int ksl)
{
    extern __shared__ __align__(128) char smem[];
    const int tid = threadIdx.x, wid = tid >> 5, lane = tid & 31;
    uint32_t sbase = smem_u32(smem);
    const long long zz = blockIdx.z;
    const long long batch = zz >> ksl;
    const long long kidx = zz & ((1 << ksl) - 1);
    A += batch * sA + kidx * (long long)Kdim;
    B += batch * sB + kidx * (long long)Kdim;
    C += batch * sC + kidx * sCk;
    const int m0 = blockIdx.y * 128, n0 = blockIdx.x * 256;

    auto issue = [&](int c) {
        const int kc = c << 6;
        uint32_t sb = sbase + (c & 1) * BUF1;
#pragma unroll
        for (int i = 0; i < 4; i++) {
            const int idx = (i << 8) + tid;
            const int row = idx >> 3, seg = idx & 7;
            uint32_t so = sb + S1_A + row * 128 + ((seg ^ (row & 7)) << 4);
            cp16(so, A + (long long)(m0 + row) * lda + kc + seg * 8);
        }
#pragma unroll
        for (int i = 0; i < 8; i++) {
            const int idx = (i << 8) + tid;
            const int row = idx >> 3, seg = idx & 7;
            uint32_t so = sb + S1_B + row * 128 + ((seg ^ (row & 7)) << 4);
            cp16(so, B + (long long)(n0 + row) * ldb + kc + seg * 8);
        }
        CP_COMMIT();
    };

    const int NC = Kdim >> 6;
    issue(0);

    const int wm = (wid >> 2) * 64, wn = (wid & 3) * 64;
    const int arow  = wm + (lane & 15);
    const int akseg = lane >> 4;
    const int r7a   = arow & 7;
    const int brin  = ((lane >> 4) << 3) + (lane & 7);
    const int bkseg = (lane >> 3) & 1;
    const int r7b   = lane & 7;

    float acc[4][8][4];
#pragma unroll
    for (int a = 0; a < 4; a++)
#pragma unroll
        for (int b = 0; b < 8; b++)
#pragma unroll
            for (int q = 0; q < 4; q++) acc[a][b][q] = 0.f;

    for (int c = 0; c < NC; c++) {
        if (c + 1 < NC) { issue(c + 1); CP_WAIT1(); } else { CP_WAIT0(); }
        __syncthreads();
        uint32_t sb = sbase + (c & 1) * BUF1;
#pragma unroll
        for (int ks = 0; ks < 4; ks++) {
            const int ks2 = ks * 2;
            uint32_t ah[4][4];
#pragma unroll
            for (int mt = 0; mt < 4; mt++) {
                uint32_t ao = sb + S1_A + (arow + mt * 16) * 128
                            + (uint32_t)((((ks2 + akseg) ^ r7a)) << 4);
                ldsm4(ah[mt], ao);
            }
#pragma unroll
            for (int half = 0; half < 2; half++) {
                uint32_t bh[2][4];
#pragma unroll
                for (int p = 0; p < 2; p++) {
                    const int row = wn + (half * 2 + p) * 16 + brin;
                    uint32_t bo = sb + S1_B + row * 128
                                + (uint32_t)((((ks2 + bkseg) ^ r7b)) << 4);
                    ldsm4(bh[p], bo);
                }
#pragma unroll
                for (int mt = 0; mt < 4; mt++)
#pragma unroll
                    for (int q = 0; q < 4; q++) {
                        const int nt = half * 4 + q;
                        const int p = q >> 1, hb = (q & 1) * 2;
                        mma16816h(acc[mt][nt], ah[mt], bh[p][hb], bh[p][hb + 1]);
                    }
            }
        }
        __syncthreads();
    }

    const int rr = lane >> 2, cc = (lane & 3) * 2;
#pragma unroll
    for (int mt = 0; mt < 4; mt++) {
        const long long m = m0 + wm + mt * 16 + rr;
#pragma unroll
        for (int nt = 0; nt < 8; nt++) {
            const int n = n0 + wn + nt * 8 + cc;
            float bx = 0.f, by = 0.f;
            if (EPI == 1) {
                float2 b2 = *(const float2*)(bias + n);
                bx = b2.x; by = b2.y;
            }
            float2 v0 = make_float2(acc[mt][nt][0] + bx, acc[mt][nt][1] + by);
            float2 v1 = make_float2(acc[mt][nt][2] + bx, acc[mt][nt][3] + by);
            *(float2*)(C + m * ldc + n)       = v0;
            *(float2*)(C + (m + 8) * ldc + n) = v1;
        }
    }
}

// ============ temperature GEMM (bf16 split) ============
constexpr int TG_AH = 0, TG_AL = 16384;
constexpr int TG_BUF = 32768;
constexpr int TG_BH = 65536, TG_BL = 98304;
constexpr int TGSMEM = 131072;

__global__ void __launch_bounds__(256, 1)
k_tempmma(const __nv_bfloat16* __restrict__ xh, const __nv_bfloat16* __restrict__ xl,
          const float* __restrict__ b_temp)
{
    extern __shared__ __align__(128) char smem[];
    const int tid = threadIdx.x, wid = tid >> 5, lane = tid & 31;
    uint32_t sbase = smem_u32(smem);
    const int m0 = blockIdx.x * 128;

#pragma unroll
    for (int q = 0; q < 8; q++) {
        int i = q * 256 + tid;
        int c = i >> 7, r = (i >> 3) & 15, seg = i & 7;
        uint32_t so = sbase + TG_BH + c * 2048 + r * 128 + ((seg ^ (r & 7)) << 4);
        cp16(so, g_wth + r * 1024 + c * 64 + seg * 8);
        cp16(so + (TG_BL - TG_BH), g_wtl + r * 1024 + c * 64 + seg * 8);
    }

    auto issueA = [&](int c) {
        uint32_t sb = sbase + (c & 1) * TG_BUF;
        const int kc = c << 6;
#pragma unroll
        for (int q = 0; q < 4; q++) {
            int i = q * 256 + tid;
            int row = i >> 3, seg = i & 7;
            uint32_t so = sb + row * 128 + ((seg ^ (row & 7)) << 4);
            cp16(so,                   xh + (long long)(m0 + row) * 1024 + kc + seg * 8);
            cp16(so + (TG_AL - TG_AH), xl + (long long)(m0 + row) * 1024 + kc + seg * 8);
        }
        CP_COMMIT();
    };
    issueA(0);

    const int wm = wid * 16;
    const int arow  = wm + (lane & 15);
    const int akseg = lane >> 4;
    const int r7a   = arow & 7;
    const int brow  = ((lane >> 4) << 3) + (lane & 7);
    const int bkseg = (lane >> 3) & 1;
    const int r7b   = brow & 7;

    float acc[2][4];
#pragma unroll
    for (int nt = 0; nt < 2; nt++)
#pragma unroll
        for (int q = 0; q < 4; q++) acc[nt][q] = 0.f;

    for (int c = 0; c < 16; c++) {
        if (c + 1 < 16) { issueA(c + 1); CP_WAIT1(); } else { CP_WAIT0(); }
        __syncthreads();
        uint32_t sa = sbase + (c & 1) * TG_BUF;
        uint32_t sbb = sbase + TG_BH + c * 2048;
#pragma unroll
        for (int ks = 0; ks < 4; ks++) {
            const int ks2 = ks * 2;
            uint32_t ah[4], alr[4], bh[4], bl[4];
            uint32_t ao = sa + arow * 128 + (uint32_t)((((ks2 + akseg) ^ r7a)) << 4);
            ldsm4(ah, ao);
            ldsm4(alr, ao + (TG_AL - TG_AH));
            uint32_t bo = sbb + brow * 128 + (uint32_t)((((ks2 + bkseg) ^ r7b)) << 4);
            ldsm4(bh, bo);
            ldsm4(bl, bo + (TG_BL - TG_BH));
#pragma unroll
            for (int nt = 0; nt < 2; nt++) {
                const int hb = nt * 2;
                mma16816(acc[nt], ah,  bh[hb], bh[hb + 1]);
                mma16816(acc[nt], ah,  bl[hb], bl[hb + 1]);
                mma16816(acc[nt], alr, bh[hb], bh[hb + 1]);
            }
        }
        __syncthreads();
    }

    const int rr = lane >> 2, cc = (lane & 3) * 2;
    const long long r0 = m0 + wm + rr, r1 = r0 + 8;
#pragma unroll
    for (int nt = 0; nt < 2; nt++) {
        int head = nt * 8 + cc;
        float b0 = b_temp[head], b1 = b_temp[head + 1];
        float v[4] = {acc[nt][0] + b0, acc[nt][1] + b1,
                      acc[nt][2] + b0, acc[nt][3] + b1};
#pragma unroll
        for (int q = 0; q < 4; q++) {
            float s = v[q];
            v[q] = 0.5f + fmaxf(s, 0.f) + log1pf(expf(-fabsf(s)));
        }
        g_T[r0 * 16 + head]     = v[0];
        g_T[r0 * 16 + head + 1] = v[1];
        g_T[r1 * 16 + head]     = v[2];
        g_T[r1 * 16 + head + 1] = v[3];
    }
}

// ============ fused prologue: convx | prep | wsplit | zero ============
// blocks [0,8192): convx, [8192,12288): prep, [12288,12352): wsplit,
// [12352,12368): zero norm
__global__ void __launch_bounds__(256)
k_aux(const float* __restrict__ x, const float* __restrict__ xq,
      const float* __restrict__ w_kv, const float* __restrict__ b_kv,
      const float* __restrict__ w_temp)
{
    __shared__ float xs[64][67];
    const int bid = blockIdx.x;
    const int t = threadIdx.x;

    if (bid < 8192) {
        // ---- convx: x -> (xh,xl bf16) + (xtf fp16 transposed) ----
        const int jt = bid & 15, nt = bid >> 4;
#pragma unroll
        for (int q = 0; q < 4; q++) {
            int lin = q * 256 + t;
            int row = lin >> 4, c4 = (lin & 15) << 2;
            float4 v = *(const float4*)(x + ((size_t)nt * 64 + row) * 1024 + jt * 64 + c4);
            xs[row][c4 + 0] = v.x; xs[row][c4 + 1] = v.y;
            xs[row][c4 + 2] = v.z; xs[row][c4 + 3] = v.w;
        }
        __syncthreads();
#pragma unroll
        for (int q = 0; q < 8; q++) {
            int lin = q * 256 + t;
            int row = lin >> 5, col = (lin & 31) << 1;
            float w0 = xs[row][col], w1 = xs[row][col + 1];
            __nv_bfloat16 h0, l0, h1, l1;
            split2(w0, h0, l0); split2(w1, h1, l1);
            size_t o = ((size_t)nt * 64 + row) * 1024 + jt * 64 + col;
            *(__nv_bfloat162*)(g_xh + o) = __nv_bfloat162(h0, h1);
            *(__nv_bfloat162*)(g_xl + o) = __nv_bfloat162(l0, l1);
        }
        const int b = (nt * 64) >> 13, nn0 = (nt * 64) & 8191;
#pragma unroll
        for (int q = 0; q < 8; q++) {
            int lin = q * 256 + t;
            int j = lin >> 5, n2 = (lin & 31) << 1;
            size_t o = ((size_t)(b * 1024 + jt * 64 + j)) * 8192 + nn0 + n2;
            *(__half2*)(g_xtf + o) = __floats2half2_rn(xs[n2][j], xs[n2 + 1][j]);
        }
    } else if (bid < 12288) {
        // ---- prep: At = xq @ Wk^T (bf16 split) + c ----
        int idx = (bid - 8192) * 256 + t;
        int j = idx >> 10, hm = idx & 1023;
        int hbase = (hm >> 6) << 6;
        const float* xr = xq + (size_t)hm * 64;
        const float* wr = w_kv + (size_t)j * 2048 + hbase;
        float acc = 0.f;
#pragma unroll 8
        for (int d = 0; d < 64; d++) acc += xr[d] * wr[d];
        __nv_bfloat16 h, l; split2(acc, h, l);
        g_Ath[(size_t)hm * 1024 + j] = h;
        g_Atl[(size_t)hm * 1024 + j] = l;
        if (j == 0) {
            const float* br = b_kv + hbase;
            float cc = 0.f;
            for (int d = 0; d < 64; d++) cc += xr[d] * br[d];
            g_c[hm] = cc;
        }
    } else if (bid < 12352) {
        // ---- wsplit ----
        int idx = (bid - 12288) * 256 + t;
        int h = idx >> 10, j = idx & 1023;
        __nv_bfloat16 hh, ll;
        split2(w_temp[j * 16 + h], hh, ll);
        g_wth[idx] = hh;
        g_wtl[idx] = ll;
    } else {
        // ---- zero norms ----
        int i = (bid - 12352) * 256 + t;
        if (i < cB * cHM) g_norm[i] = 0.f;
    }
}

// ============ reduce 8 y-partials into partial 0 ============
__global__ void __launch_bounds__(256)
k_yred()
{
    constexpr size_t YPS4 = (size_t)cB * cHM * cH / 4;
    size_t i = (size_t)blockIdx.x * 256 + threadIdx.x;   // 1M float4
    float4* base = (float4*)g_yp;
    float4 s = base[i];
#pragma unroll
    for (int p = 1; p < 8; p++) {
        float4 v = base[p * YPS4 + i];
        s.x += v.x; s.y += v.y; s.z += v.z; s.w += v.w;
    }
    base[i] = s;
}

// slice_token from reduced y (partial 0)
__global__ void __launch_bounds__(256)
k_st(const float* __restrict__ w_kv, const float* __restrict__ b_kv)
{
    int z = blockIdx.x;
    int b = z >> 4, h = z & 15;
    const float* Yb = g_yp + ((size_t)b * 1024 + h * 64) * 1024;
    const float* Wv = w_kv + 1024 + h * 64;
    __shared__ float As[16][64];
    __shared__ float Bs[16][64];
    int t = threadIdx.x;
    int tyy = t >> 4, txx = t & 15;
    float acc[4][4] = {};
    for (int k0 = 0; k0 < 1024; k0 += 16) {
        {
            int m = t >> 2, k4 = (t & 3) << 2;
            float4 v = *(const float4*)(Yb + (size_t)m * 1024 + k0 + k4);
            As[k4 + 0][m] = v.x; As[k4 + 1][m] = v.y;
            As[k4 + 2][m] = v.z; As[k4 + 3][m] = v.w;
        }
        {
            int k = t >> 4, n4 = (t & 15) << 2;
            *(float4*)&Bs[k][n4] = *(const float4*)(Wv + (size_t)(k0 + k) * 2048 + n4);
        }
        __syncthreads();
#pragma unroll
        for (int kk = 0; kk < 16; kk++) {
            float4 a  = *(const float4*)&As[kk][tyy * 4];
            float4 bb = *(const float4*)&Bs[kk][txx * 4];
            float av[4] = {a.x, a.y, a.z, a.w};
            float bv[4] = {bb.x, bb.y, bb.z, bb.w};
#pragma unroll
            for (int i = 0; i < 4; i++)
#pragma unroll
                for (int jj = 0; jj < 4; jj++) acc[i][jj] += av[i] * bv[jj];
        }
        __syncthreads();
    }
#pragma unroll
    for (int i = 0; i < 4; i++) {
        int m = tyy * 4 + i;
        float nrm = g_norm[b * 1024 + h * 64 + m];
        float inv = 1.0f / (nrm + 1e-5f);
#pragma unroll
        for (int jj = 0; jj < 4; jj++) {
            int d = txx * 4 + jj;
            float bvv = b_kv[1024 + h * 64 + d];
            g_st[((size_t)z * 64 + m) * 64 + d] = (acc[i][jj] + nrm * bvv) * inv;
        }
    }
}

__global__ void __launch_bounds__(64)
k_qkv(const float* __restrict__ qkv_proj)
{
    int z = blockIdx.x;
    int h = (z >> 6) & 15;
    int d = threadIdx.x;
    __shared__ float st[64];
    __shared__ float ex[64];
    st[d] = g_st[(size_t)z * 64 + d];
    __syncthreads();
    const float* P = qkv_proj + (size_t)h * 64 * 192;
    float q = 0.f, k = 0.f, v = 0.f;
#pragma unroll 8
    for (int j = 0; j < 64; j++) {
        float s = st[j];
        const float* pr = P + j * 192;
        q += s * pr[d]; k += s * pr[64 + d]; v += s * pr[128 + d];
    }
    float dot = q * k * 0.125f;
    ex[d] = dot;
    __syncthreads();
    float mx = -1e30f;
    for (int j = 0; j < 64; j++) mx = fmaxf(mx, ex[j]);
    __syncthreads();
    float e = expf(dot - mx);
    ex[d] = e;
    __syncthreads();
    float sum = 0.f;
    for (int j = 0; j < 64; j++) sum += ex[j];
    g_ost[(size_t)z * 64 + d] = (e / sum) * v;
}

__global__ void __launch_bounds__(256)
k_zmat(const float* __restrict__ w_out)
{
    int z = blockIdx.y, jc = blockIdx.x;
    int b = z >> 4, h = z & 15;
    __shared__ float As[64][64];
    __shared__ float Bs[64][64];
    int t = threadIdx.x;
#pragma unroll
    for (int r = 0; r < 4; r++) {
        int lin = t + r * 256;
        int row = lin >> 4;
        int c4  = (lin & 15) << 2;
        float4 v = *(const float4*)(g_ost + ((size_t)z * 64 + row) * 64 + c4);
        As[c4 + 0][row] = v.x; As[c4 + 1][row] = v.y;
        As[c4 + 2][row] = v.z; As[c4 + 3][row] = v.w;
        *(float4*)&Bs[row][c4] =
            *(const float4*)(w_out + (size_t)(h * 64 + row) * 1024 + jc * 64 + c4);
    }
    __syncthreads();
    int tyy = t >> 4, txx = t & 15;
    float acc[4][4] = {};
#pragma unroll
    for (int kk = 0; kk < 64; kk++) {
        float4 a  = *(const float4*)&As[kk][tyy * 4];
        float4 bb = *(const float4*)&Bs[kk][txx * 4];
        float av[4] = {a.x, a.y, a.z, a.w};
        float bv[4] = {bb.x, bb.y, bb.z, bb.w};
#pragma unroll
        for (int i = 0; i < 4; i++)
#pragma unroll
            for (int jj = 0; jj < 4; jj++) acc[i][jj] += av[i] * bv[jj];
    }
#pragma unroll
    for (int i = 0; i < 4; i++) {
        int hm = h * 64 + tyy * 4 + i;
#pragma unroll
        for (int jj = 0; jj < 4; jj++) {
            int j = jc * 64 + txx * 4 + jj;
            g_Ztf[((size_t)b * 1024 + j) * 1024 + hm] = __float2half(acc[i][jj]);
        }
    }
}

// ---------------------------------------------------------------------------
extern "C" void kernel_launch(void* const* d_in, const int* in_sizes, int n_in,
                              void* d_out, int out_size)
{
    (void)in_sizes; (void)n_in; (void)out_size;
    const float* x      = (const float*)d_in[0];
    const float* w_kv   = (const float*)d_in[2];
    const float* b_kv   = (const float*)d_in[3];
    const float* w_temp = (const float*)d_in[4];
    const float* b_temp = (const float*)d_in[5];
    const float* xq     = (const float*)d_in[6];
    const float* qkv_p  = (const float*)d_in[7];
    const float* w_out  = (const float*)d_in[8];
    const float* b_out  = (const float*)d_in[9];
    float* out = (float*)d_out;

    float *pc, *pyp;
    __nv_bfloat16 *pxh, *pxl, *pAth, *pAtl;
    __half *pxtf, *pSf, *pSft, *pZtf;
    cudaGetSymbolAddress((void**)&pc,  g_c);
    cudaGetSymbolAddress((void**)&pyp, g_yp);
    cudaGetSymbolAddress((void**)&pxh, g_xh);   cudaGetSymbolAddress((void**)&pxl, g_xl);
    cudaGetSymbolAddress((void**)&pxtf, g_xtf);
    cudaGetSymbolAddress((void**)&pSf, g_Sf);   cudaGetSymbolAddress((void**)&pSft, g_Sft);
    cudaGetSymbolAddress((void**)&pAth, g_Ath); cudaGetSymbolAddress((void**)&pAtl, g_Atl);
    cudaGetSymbolAddress((void**)&pZtf, g_Ztf);

    cudaFuncSetAttribute(mma_scores,   cudaFuncAttributeMaxDynamicSharedMemorySize, GSMEM);
    cudaFuncSetAttribute(mma1_gemm<0>, cudaFuncAttributeMaxDynamicSharedMemorySize, GSMEM1);
    cudaFuncSetAttribute(mma1_gemm<1>, cudaFuncAttributeMaxDynamicSharedMemorySize, GSMEM1);
    cudaFuncSetAttribute(k_tempmma,    cudaFuncAttributeMaxDynamicSharedMemorySize, TGSMEM);

    // fused prologue: convx + prep + wsplit + zero
    k_aux<<<12368, 256>>>(x, xq, w_kv, b_kv, w_temp);
    k_tempmma<<<256, 256, TGSMEM>>>(pxh, pxl, b_temp);
    // scores (bf16 3-term) + fused softmax/norm/fp16 stores
    mma_scores<<<dim3(4, 256, 1), 256, GSMEM>>>(pxh, pxl, pAth, pAtl, pc);
    // y[b] = S[b]^T @ x[b] (fp16 single-pass), K-split x8
    mma1_gemm<0><<<dim3(4, 8, cB * 8), 256, GSMEM1>>>(
        pSft, pxtf, pyp, nullptr,
        1024, 8192, 8192, 1024,
        (long long)cHM * cN, (long long)cH * cN,
        (long long)cHM * cH, (long long)cB * cHM * cH, 3);
    k_yred<<<4096, 256>>>();
    k_st<<<cB * cNH, 256>>>(w_kv, b_kv);
    k_qkv<<<cB * cNH * 64, 64>>>(qkv_p);
    k_zmat<<<dim3(16, cB * cNH), 256>>>(w_out);
    // out[b] = S[b] @ Zt[b]^T + b_out (fp16 single-pass)
    mma1_gemm<1><<<dim3(4, 64, cB), 256, GSMEM1>>>(
        pSf, pZtf, out, b_out,
        1024, 1024, 1024, 1024,
        (long long)cN * cHM, (long long)cH * cHM,
        (long long)cN * cH, 0, 0);
}

// round 14
// speedup vs baseline: 1.7339x; 1.0023x over previous
#include <cuda_runtime.h>
#include <cuda_bf16.h>
#include <cuda_fp16.h>
#include <math.h>
#include <stdint.h>

constexpr int cB = 4, cN = 8192, cH = 1024, cNH = 16, cHM = 1024;

// ---------------- scratch (device globals) ----------------
__device__ __nv_bfloat16 g_xh [(size_t)cB * cN * cH];
__device__ __nv_bfloat16 g_xl [(size_t)cB * cN * cH];
__device__ __half        g_xtf[(size_t)cB * cH * cN];
__device__ __half        g_Sf [(size_t)cB * cN * cHM];
__device__ __half        g_Sft[(size_t)cB * cHM * cN];
__device__ __nv_bfloat16 g_Ath[cHM * cH];
__device__ __nv_bfloat16 g_Atl[cHM * cH];
__device__ __half        g_Ztf[(size_t)cB * cH * cHM];
__device__ __nv_bfloat16 g_wth[cNH * cH];
__device__ __nv_bfloat16 g_wtl[cNH * cH];
__device__ float g_c[cHM];
__device__ float g_T[cB * cN * cNH];
__device__ float g_norm[cB * cHM];
__device__ float g_yp[(size_t)8 * cB * cHM * cH];
__device__ float g_st[cB * cNH * 64 * 64];
__device__ float g_ost[cB * cNH * 64 * 64];

// ---------------- helpers ----------------
__device__ __forceinline__ uint32_t smem_u32(const void* p) {
    uint32_t a;
    asm("{ .reg .u64 t; cvta.to.shared.u64 t, %1; cvt.u32.u64 %0, t; }" : "=r"(a) : "l"(p));
    return a;
}
__device__ __forceinline__ void cp16(uint32_t s, const void* g) {
    asm volatile("cp.async.cg.shared.global [%0], [%1], 16;" :: "r"(s), "l"(g));
}
#define CP_COMMIT() asm volatile("cp.async.commit_group;" ::: "memory")
#define CP_WAIT1()  asm volatile("cp.async.wait_group 1;" ::: "memory")
#define CP_WAIT0()  asm volatile("cp.async.wait_group 0;" ::: "memory")

__device__ __forceinline__ void ldsm4(uint32_t* r, uint32_t a) {
    asm volatile("ldmatrix.sync.aligned.m8n8.x4.shared.b16 {%0,%1,%2,%3}, [%4];"
        : "=r"(r[0]), "=r"(r[1]), "=r"(r[2]), "=r"(r[3]) : "r"(a));
}
__device__ __forceinline__ void mma16816(float* d, const uint32_t* a,
                                         uint32_t b0, uint32_t b1) {
    asm volatile("mma.sync.aligned.m16n8k16.row.col.f32.bf16.bf16.f32 "
        "{%0,%1,%2,%3}, {%4,%5,%6,%7}, {%8,%9}, {%0,%1,%2,%3};"
        : "+f"(d[0]), "+f"(d[1]), "+f"(d[2]), "+f"(d[3])
        : "r"(a[0]), "r"(a[1]), "r"(a[2]), "r"(a[3]), "r"(b0), "r"(b1));
}
__device__ __forceinline__ void mma16816h(float* d, const uint32_t* a,
                                          uint32_t b0, uint32_t b1) {
    asm volatile("mma.sync.aligned.m16n8k16.row.col.f32.f16.f16.f32 "
        "{%0,%1,%2,%3}, {%4,%5,%6,%7}, {%8,%9}, {%0,%1,%2,%3};"
        : "+f"(d[0]), "+f"(d[1]), "+f"(d[2]), "+f"(d[3])
        : "r"(a[0]), "r"(a[1]), "r"(a[2]), "r"(a[3]), "r"(b0), "r"(b1));
}
__device__ __forceinline__ void split2(float v, __nv_bfloat16& h, __nv_bfloat16& l) {
    h = __float2bfloat16(v);
    l = __float2bfloat16(v - __bfloat162float(h));
}

// ===== bf16 3-term GEMM (scores): CTA 128x256, 16 warps, warp 64x32, Kc=64 ==
constexpr int T_AH = 0, T_AL = 16384, T_BH = 32768, T_BL = 65536;
constexpr int BUFB = 98304;
constexpr int GSMEM = 2 * BUFB;   // 192 KB

__global__ void __launch_bounds__(512, 1)
mma_scores(const __nv_bfloat16* __restrict__ Ah, const __nv_bfloat16* __restrict__ Al,
           const __nv_bfloat16* __restrict__ Bh, const __nv_bfloat16* __restrict__ Bl,
           const float* __restrict__ bias)
{
    extern __shared__ __align__(128) char smem[];
    const int tid = threadIdx.x, wid = tid >> 5, lane = tid & 31;
    uint32_t sbase = smem_u32(smem);
    const int m0 = blockIdx.y * 128, n0 = blockIdx.x * 256;
    const int lda = 1024, ldb = 1024;

    auto issue = [&](int c) {
        const int kc = c << 6;
        uint32_t sb = sbase + (c & 1) * BUFB;
#pragma unroll
        for (int i = 0; i < 2; i++) {            // A hi/lo: 1024 cp16 pairs
            const int idx = (i << 9) + tid;
            const int row = idx >> 3, seg = idx & 7;
            uint32_t so = sb + row * 128 + ((seg ^ (row & 7)) << 4);
            long long go = (long long)(m0 + row) * lda + kc + seg * 8;
            cp16(so + T_AH, Ah + go);
            cp16(so + T_AL, Al + go);
        }
#pragma unroll
        for (int i = 0; i < 4; i++) {            // B hi/lo: 2048 cp16 pairs
            const int idx = (i << 9) + tid;
            const int row = idx >> 3, seg = idx & 7;
            uint32_t so = sb + row * 128 + ((seg ^ (row & 7)) << 4);
            long long go = (long long)(n0 + row) * ldb + kc + seg * 8;
            cp16(so + T_BH, Bh + go);
            cp16(so + T_BL, Bl + go);
        }
        CP_COMMIT();
    };

    issue(0);

    const int wm = (wid & 1) * 64, wn = (wid >> 1) * 32;
    const int arow  = wm + (lane & 15);
    const int akseg = lane >> 4;
    const int r7a   = arow & 7;
    const int brin  = ((lane >> 4) << 3) + (lane & 7);
    const int bkseg = (lane >> 3) & 1;
    const int r7b   = lane & 7;

    float acc[4][4][4];
#pragma unroll
    for (int a = 0; a < 4; a++)
#pragma unroll
        for (int b = 0; b < 4; b++)
#pragma unroll
            for (int q = 0; q < 4; q++) acc[a][b][q] = 0.f;

    for (int c = 0; c < 16; c++) {
        if (c + 1 < 16) { issue(c + 1); CP_WAIT1(); } else { CP_WAIT0(); }
        __syncthreads();
        uint32_t sb = sbase + (c & 1) * BUFB;
#pragma unroll
        for (int ks = 0; ks < 4; ks++) {
            const int ks2 = ks * 2;
            uint32_t ah[4][4], alr[4][4], bh[2][4], bl[2][4];
#pragma unroll
            for (int mt = 0; mt < 4; mt++) {
                uint32_t ao = sb + T_AH + (arow + mt * 16) * 128
                            + (uint32_t)((((ks2 + akseg) ^ r7a)) << 4);
                ldsm4(ah[mt], ao);
                ldsm4(alr[mt], ao + (T_AL - T_AH));
            }
#pragma unroll
            for (int p = 0; p < 2; p++) {
                const int row = wn + p * 16 + brin;
                uint32_t bo = sb + T_BH + row * 128
                            + (uint32_t)((((ks2 + bkseg) ^ r7b)) << 4);
                ldsm4(bh[p], bo);
                ldsm4(bl[p], bo + (T_BL - T_BH));
            }
#pragma unroll
            for (int mt = 0; mt < 4; mt++)
#pragma unroll
                for (int nt = 0; nt < 4; nt++) {
                    const int p = nt >> 1, hb = (nt & 1) * 2;
                    mma16816(acc[mt][nt], ah[mt],  bh[p][hb], bh[p][hb + 1]);
                    mma16816(acc[mt][nt], ah[mt],  bl[p][hb], bl[p][hb + 1]);
                    mma16816(acc[mt][nt], alr[mt], bh[p][hb], bh[p][hb + 1]);
                }
        }
        __syncthreads();
    }

    const int rr = lane >> 2, cc = (lane & 3) * 2;
    // ---- fused softmax over m + norm + fp16 dual-layout stores ----
    float* sf = (float*)smem;                 // 128 x 256, pitch 261
#pragma unroll
    for (int mt = 0; mt < 4; mt++) {
#pragma unroll
        for (int nt = 0; nt < 4; nt++) {
            int r = wm + mt * 16 + rr;
            int col = wn + nt * 8 + cc;
            float2 b2 = *(const float2*)(bias + n0 + col);
            sf[r * 261 + col]           = acc[mt][nt][0] + b2.x;
            sf[r * 261 + col + 1]       = acc[mt][nt][1] + b2.y;
            sf[(r + 8) * 261 + col]     = acc[mt][nt][2] + b2.x;
            sf[(r + 8) * 261 + col + 1] = acc[mt][nt][3] + b2.y;
        }
    }
    __syncthreads();
    {   // row softmax: 128 rows x 4 head-quarters = 512 tasks, 1 per thread
        int row = tid & 127, hq = tid >> 7;
        size_t bn = (size_t)m0 + row;
        int headg = (n0 >> 6) + hq;
        float inv_t = 1.0f / g_T[bn * 16 + headg];
        float* rp = sf + row * 261 + hq * 64;
        float mx = -1e30f;
#pragma unroll 8
        for (int i = 0; i < 64; i++) mx = fmaxf(mx, rp[i]);
        float sum = 0.f;
#pragma unroll 8
        for (int i = 0; i < 64; i++) {
            float e = expf((rp[i] - mx) * inv_t);
            rp[i] = e; sum += e;
        }
        float inv = 1.0f / sum;
#pragma unroll 8
        for (int i = 0; i < 64; i++) rp[i] *= inv;
    }
    __syncthreads();
    const int bidx = m0 >> 13;
    if (tid < 256) {
        float s = 0.f;
#pragma unroll 8
        for (int i = 0; i < 128; i++) s += sf[i * 261 + tid];
        atomicAdd(&g_norm[bidx * 1024 + n0 + tid], s);
    }
#pragma unroll
    for (int i = 0; i < 32; i++) {
        int p = i * 512 + tid;
        int row = p >> 7, col = (p & 127) << 1;
        float w0 = sf[row * 261 + col], w1 = sf[row * 261 + col + 1];
        size_t o = ((size_t)m0 + row) * 1024 + n0 + col;
        *(__half2*)(g_Sf + o) = __floats2half2_rn(w0, w1);
    }
    {
        int nb = m0 & 8191;
#pragma unroll
        for (int i = 0; i < 32; i++) {
            int p = i * 512 + tid;
            int hm = p >> 6, n2 = (p & 63) << 1;
            float w0 = sf[n2 * 261 + hm], w1 = sf[(n2 + 1) * 261 + hm];
            size_t o = ((size_t)bidx * 1024 + n0 + hm) * 8192 + nb + n2;
            *(__half2*)(g_Sft + o) = __floats2half2_rn(w0, w1);
        }
    }
}

// ===== fp16 single-pass GEMM (y/out): CTA 128x256, 16 warps, warp 64x32 =====
constexpr int S1_A = 0, S1_B = 16384;
constexpr int BUF1 = 49152;
constexpr int GSMEM1 = 2 * BUF1;   // 96 KB

template<int EPI>   // 0 = plain store (K-split partials), 1 = bias + store
__global__ void __launch_bounds__(512, 1)
mma1_gemm(const __half* __restrict__ A, const __half* __restrict__ B,
          float* __restrict__ C, const float* __restrict__ bias,
          int Kdim, int lda, int ldb, int ldc,
          long long sA, long long sB, long long sC, long long sCk, int ksl)
{
    extern __shared__ __align__(128) char smem[];
    const int tid = threadIdx.x, wid = tid >> 5, lane = tid & 31;
    uint32_t sbase = smem_u32(smem);
    const long long zz = blockIdx.z;
    const long long batch = zz >> ksl;
    const long long kidx = zz & ((1 << ksl) - 1);
    A += batch * sA + kidx * (long long)Kdim;
    B += batch * sB + kidx * (long long)Kdim;
    C += batch * sC + kidx * sCk;
    const int m0 = blockIdx.y * 128, n0 = blockIdx.x * 256;

    auto issue = [&](int c) {
        const int kc = c << 6;
        uint32_t sb = sbase + (c & 1) * BUF1;
#pragma unroll
        for (int i = 0; i < 2; i++) {
            const int idx = (i << 9) + tid;
            const int row = idx >> 3, seg = idx & 7;
            uint32_t so = sb + S1_A + row * 128 + ((seg ^ (row & 7)) << 4);
            cp16(so, A + (long long)(m0 + row) * lda + kc + seg * 8);
        }
#pragma unroll
        for (int i = 0; i < 4; i++) {
            const int idx = (i << 9) + tid;
            const int row = idx >> 3, seg = idx & 7;
            uint32_t so = sb + S1_B + row * 128 + ((seg ^ (row & 7)) << 4);
            cp16(so, B + (long long)(n0 + row) * ldb + kc + seg * 8);
        }
        CP_COMMIT();
    };

    const int NC = Kdim >> 6;
    issue(0);

    const int wm = (wid & 1) * 64, wn = (wid >> 1) * 32;
    const int arow  = wm + (lane & 15);
    const int akseg = lane >> 4;
    const int r7a   = arow & 7;
    const int brin  = ((lane >> 4) << 3) + (lane & 7);
    const int bkseg = (lane >> 3) & 1;
    const int r7b   = lane & 7;

    float acc[4][4][4];
#pragma unroll
    for (int a = 0; a < 4; a++)
#pragma unroll
        for (int b = 0; b < 4; b++)
#pragma unroll
            for (int q = 0; q < 4; q++) acc[a][b][q] = 0.f;

    for (int c = 0; c < NC; c++) {
        if (c + 1 < NC) { issue(c + 1); CP_WAIT1(); } else { CP_WAIT0(); }
        __syncthreads();
        uint32_t sb = sbase + (c & 1) * BUF1;
#pragma unroll
        for (int ks = 0; ks < 4; ks++) {
            const int ks2 = ks * 2;
            uint32_t ah[4][4], bh[2][4];
#pragma unroll
            for (int mt = 0; mt < 4; mt++) {
                uint32_t ao = sb + S1_A + (arow + mt * 16) * 128
                            + (uint32_t)((((ks2 + akseg) ^ r7a)) << 4);
                ldsm4(ah[mt], ao);
            }
#pragma unroll
            for (int p = 0; p < 2; p++) {
                const int row = wn + p * 16 + brin;
                uint32_t bo = sb + S1_B + row * 128
                            + (uint32_t)((((ks2 + bkseg) ^ r7b)) << 4);
                ldsm4(bh[p], bo);
            }
#pragma unroll
            for (int mt = 0; mt < 4; mt++)
#pragma unroll
                for (int nt = 0; nt < 4; nt++) {
                    const int p = nt >> 1, hb = (nt & 1) * 2;
                    mma16816h(acc[mt][nt], ah[mt], bh[p][hb], bh[p][hb + 1]);
                }
        }
        __syncthreads();
    }

    const int rr = lane >> 2, cc = (lane & 3) * 2;
#pragma unroll
    for (int mt = 0; mt < 4; mt++) {
        const long long m = m0 + wm + mt * 16 + rr;
#pragma unroll
        for (int nt = 0; nt < 4; nt++) {
            const int n = n0 + wn + nt * 8 + cc;
            float bx = 0.f, by = 0.f;
            if (EPI == 1) {
                float2 b2 = *(const float2*)(bias + n);
                bx = b2.x; by = b2.y;
            }
            float2 v0 = make_float2(acc[mt][nt][0] + bx, acc[mt][nt][1] + by);
            float2 v1 = make_float2(acc[mt][nt][2] + bx, acc[mt][nt][3] + by);
            *(float2*)(C + m * ldc + n)       = v0;
            *(float2*)(C + (m + 8) * ldc + n) = v1;
        }
    }
}

// ============ temperature GEMM (bf16 split, unchanged, 256 thr) ============
constexpr int TG_AH = 0, TG_AL = 16384;
constexpr int TG_BUF = 32768;
constexpr int TG_BH = 65536, TG_BL = 98304;
constexpr int TGSMEM = 131072;

__global__ void __launch_bounds__(256, 1)
k_tempmma(const __nv_bfloat16* __restrict__ xh, const __nv_bfloat16* __restrict__ xl,
          const float* __restrict__ b_temp)
{
    extern __shared__ __align__(128) char smem[];
    const int tid = threadIdx.x, wid = tid >> 5, lane = tid & 31;
    uint32_t sbase = smem_u32(smem);
    const int m0 = blockIdx.x * 128;

#pragma unroll
    for (int q = 0; q < 8; q++) {
        int i = q * 256 + tid;
        int c = i >> 7, r = (i >> 3) & 15, seg = i & 7;
        uint32_t so = sbase + TG_BH + c * 2048 + r * 128 + ((seg ^ (r & 7)) << 4);
        cp16(so, g_wth + r * 1024 + c * 64 + seg * 8);
        cp16(so + (TG_BL - TG_BH), g_wtl + r * 1024 + c * 64 + seg * 8);
    }

    auto issueA = [&](int c) {
        uint32_t sb = sbase + (c & 1) * TG_BUF;
        const int kc = c << 6;
#pragma unroll
        for (int q = 0; q < 4; q++) {
            int i = q * 256 + tid;
            int row = i >> 3, seg = i & 7;
            uint32_t so = sb + row * 128 + ((seg ^ (row & 7)) << 4);
            cp16(so,                   xh + (long long)(m0 + row) * 1024 + kc + seg * 8);
            cp16(so + (TG_AL - TG_AH), xl + (long long)(m0 + row) * 1024 + kc + seg * 8);
        }
        CP_COMMIT();
    };
    issueA(0);

    const int wm = wid * 16;
    const int arow  = wm + (lane & 15);
    const int akseg = lane >> 4;
    const int r7a   = arow & 7;
    const int brow  = ((lane >> 4) << 3) + (lane & 7);
    const int bkseg = (lane >> 3) & 1;
    const int r7b   = brow & 7;

    float acc[2][4];
#pragma unroll
    for (int nt = 0; nt < 2; nt++)
#pragma unroll
        for (int q = 0; q < 4; q++) acc[nt][q] = 0.f;

    for (int c = 0; c < 16; c++) {
        if (c + 1 < 16) { issueA(c + 1); CP_WAIT1(); } else { CP_WAIT0(); }
        __syncthreads();
        uint32_t sa = sbase + (c & 1) * TG_BUF;
        uint32_t sbb = sbase + TG_BH + c * 2048;
#pragma unroll
        for (int ks = 0; ks < 4; ks++) {
            const int ks2 = ks * 2;
            uint32_t ah[4], alr[4], bh[4], bl[4];
            uint32_t ao = sa + arow * 128 + (uint32_t)((((ks2 + akseg) ^ r7a)) << 4);
            ldsm4(ah, ao);
            ldsm4(alr, ao + (TG_AL - TG_AH));
            uint32_t bo = sbb + brow * 128 + (uint32_t)((((ks2 + bkseg) ^ r7b)) << 4);
            ldsm4(bh, bo);
            ldsm4(bl, bo + (TG_BL - TG_BH));
#pragma unroll
            for (int nt = 0; nt < 2; nt++) {
                const int hb = nt * 2;
                mma16816(acc[nt], ah,  bh[hb], bh[hb + 1]);
                mma16816(acc[nt], ah,  bl[hb], bl[hb + 1]);
                mma16816(acc[nt], alr, bh[hb], bh[hb + 1]);
            }
        }
        __syncthreads();
    }

    const int rr = lane >> 2, cc = (lane & 3) * 2;
    const long long r0 = m0 + wm + rr, r1 = r0 + 8;
#pragma unroll
    for (int nt = 0; nt < 2; nt++) {
        int head = nt * 8 + cc;
        float b0 = b_temp[head], b1 = b_temp[head + 1];
        float v[4] = {acc[nt][0] + b0, acc[nt][1] + b1,
                      acc[nt][2] + b0, acc[nt][3] + b1};
#pragma unroll
        for (int q = 0; q < 4; q++) {
            float s = v[q];
            v[q] = 0.5f + fmaxf(s, 0.f) + log1pf(expf(-fabsf(s)));
        }
        g_T[r0 * 16 + head]     = v[0];
        g_T[r0 * 16 + head + 1] = v[1];
        g_T[r1 * 16 + head]     = v[2];
        g_T[r1 * 16 + head + 1] = v[3];
    }
}

// ============ fused prologue: convx | prep | wsplit | zero ============
__global__ void __launch_bounds__(256)
k_aux(const float* __restrict__ x, const float* __restrict__ xq,
      const float* __restrict__ w_kv, const float* __restrict__ b_kv,
      const float* __restrict__ w_temp)
{
    __shared__ float xs[64][67];
    const int bid = blockIdx.x;
    const int t = threadIdx.x;

    if (bid < 8192) {
        const int jt = bid & 15, nt = bid >> 4;
#pragma unroll
        for (int q = 0; q < 4; q++) {
            int lin = q * 256 + t;
            int row = lin >> 4, c4 = (lin & 15) << 2;
            float4 v = *(const float4*)(x + ((size_t)nt * 64 + row) * 1024 + jt * 64 + c4);
            xs[row][c4 + 0] = v.x; xs[row][c4 + 1] = v.y;
            xs[row][c4 + 2] = v.z; xs[row][c4 + 3] = v.w;
        }
        __syncthreads();
#pragma unroll
        for (int q = 0; q < 8; q++) {
            int lin = q * 256 + t;
            int row = lin >> 5, col = (lin & 31) << 1;
            float w0 = xs[row][col], w1 = xs[row][col + 1];
            __nv_bfloat16 h0, l0, h1, l1;
            split2(w0, h0, l0); split2(w1, h1, l1);
            size_t o = ((size_t)nt * 64 + row) * 1024 + jt * 64 + col;
            *(__nv_bfloat162*)(g_xh + o) = __nv_bfloat162(h0, h1);
            *(__nv_bfloat162*)(g_xl + o) = __nv_bfloat162(l0, l1);
        }
        const int b = (nt * 64) >> 13, nn0 = (nt * 64) & 8191;
#pragma unroll
        for (int q = 0; q < 8; q++) {
            int lin = q * 256 + t;
            int j = lin >> 5, n2 = (lin & 31) << 1;
            size_t o = ((size_t)(b * 1024 + jt * 64 + j)) * 8192 + nn0 + n2;
            *(__half2*)(g_xtf + o) = __floats2half2_rn(xs[n2][j], xs[n2 + 1][j]);
        }
    } else if (bid < 12288) {
        int idx = (bid - 8192) * 256 + t;
        int j = idx >> 10, hm = idx & 1023;
        int hbase = (hm >> 6) << 6;
        const float* xr = xq + (size_t)hm * 64;
        const float* wr = w_kv + (size_t)j * 2048 + hbase;
        float acc = 0.f;
#pragma unroll 8
        for (int d = 0; d < 64; d++) acc += xr[d] * wr[d];
        __nv_bfloat16 h, l; split2(acc, h, l);
        g_Ath[(size_t)hm * 1024 + j] = h;
        g_Atl[(size_t)hm * 1024 + j] = l;
        if (j == 0) {
            const float* br = b_kv + hbase;
            float cc = 0.f;
            for (int d = 0; d < 64; d++) cc += xr[d] * br[d];
            g_c[hm] = cc;
        }
    } else if (bid < 12352) {
        int idx = (bid - 12288) * 256 + t;
        int h = idx >> 10, j = idx & 1023;
        __nv_bfloat16 hh, ll;
        split2(w_temp[j * 16 + h], hh, ll);
        g_wth[idx] = hh;
        g_wtl[idx] = ll;
    } else {
        int i = (bid - 12352) * 256 + t;
        if (i < cB * cHM) g_norm[i] = 0.f;
    }
}

// ============ reduce 8 y-partials into partial 0 ============
__global__ void __launch_bounds__(256)
k_yred()
{
    constexpr size_t YPS4 = (size_t)cB * cHM * cH / 4;
    size_t i = (size_t)blockIdx.x * 256 + threadIdx.x;
    float4* base = (float4*)g_yp;
    float4 s = base[i];
#pragma unroll
    for (int p = 1; p < 8; p++) {
        float4 v = base[p * YPS4 + i];
        s.x += v.x; s.y += v.y; s.z += v.z; s.w += v.w;
    }
    base[i] = s;
}

// slice_token from reduced y (partial 0)
__global__ void __launch_bounds__(256)
k_st(const float* __restrict__ w_kv, const float* __restrict__ b_kv)
{
    int z = blockIdx.x;
    int b = z >> 4, h = z & 15;
    const float* Yb = g_yp + ((size_t)b * 1024 + h * 64) * 1024;
    const float* Wv = w_kv + 1024 + h * 64;
    __shared__ float As[16][64];
    __shared__ float Bs[16][64];
    int t = threadIdx.x;
    int tyy = t >> 4, txx = t & 15;
    float acc[4][4] = {};
    for (int k0 = 0; k0 < 1024; k0 += 16) {
        {
            int m = t >> 2, k4 = (t & 3) << 2;
            float4 v = *(const float4*)(Yb + (size_t)m * 1024 + k0 + k4);
            As[k4 + 0][m] = v.x; As[k4 + 1][m] = v.y;
            As[k4 + 2][m] = v.z; As[k4 + 3][m] = v.w;
        }
        {
            int k = t >> 4, n4 = (t & 15) << 2;
            *(float4*)&Bs[k][n4] = *(const float4*)(Wv + (size_t)(k0 + k) * 2048 + n4);
        }
        __syncthreads();
#pragma unroll
        for (int kk = 0; kk < 16; kk++) {
            float4 a  = *(const float4*)&As[kk][tyy * 4];
            float4 bb = *(const float4*)&Bs[kk][txx * 4];
            float av[4] = {a.x, a.y, a.z, a.w};
            float bv[4] = {bb.x, bb.y, bb.z, bb.w};
#pragma unroll
            for (int i = 0; i < 4; i++)
#pragma unroll
                for (int jj = 0; jj < 4; jj++) acc[i][jj] += av[i] * bv[jj];
        }
        __syncthreads();
    }
#pragma unroll
    for (int i = 0; i < 4; i++) {
        int m = tyy * 4 + i;
        float nrm = g_norm[b * 1024 + h * 64 + m];
        float inv = 1.0f / (nrm + 1e-5f);
#pragma unroll
        for (int jj = 0; jj < 4; jj++) {
            int d = txx * 4 + jj;
            float bvv = b_kv[1024 + h * 64 + d];
            g_st[((size_t)z * 64 + m) * 64 + d] = (acc[i][jj] + nrm * bvv) * inv;
        }
    }
}

__global__ void __launch_bounds__(64)
k_qkv(const float* __restrict__ qkv_proj)
{
    int z = blockIdx.x;
    int h = (z >> 6) & 15;
    int d = threadIdx.x;
    __shared__ float st[64];
    __shared__ float ex[64];
    st[d] = g_st[(size_t)z * 64 + d];
    __syncthreads();
    const float* P = qkv_proj + (size_t)h * 64 * 192;
    float q = 0.f, k = 0.f, v = 0.f;
#pragma unroll 8
    for (int j = 0; j < 64; j++) {
        float s = st[j];
        const float* pr = P + j * 192;
        q += s * pr[d]; k += s * pr[64 + d]; v += s * pr[128 + d];
    }
    float dot = q * k * 0.125f;
    ex[d] = dot;
    __syncthreads();
    float mx = -1e30f;
    for (int j = 0; j < 64; j++) mx = fmaxf(mx, ex[j]);
    __syncthreads();
    float e = expf(dot - mx);
    ex[d] = e;
    __syncthreads();
    float sum = 0.f;
    for (int j = 0; j < 64; j++) sum += ex[j];
    g_ost[(size_t)z * 64 + d] = (e / sum) * v;
}

__global__ void __launch_bounds__(256)
k_zmat(const float* __restrict__ w_out)
{
    int z = blockIdx.y, jc = blockIdx.x;
    int b = z >> 4, h = z & 15;
    __shared__ float As[64][64];
    __shared__ float Bs[64][64];
    int t = threadIdx.x;
#pragma unroll
    for (int r = 0; r < 4; r++) {
        int lin = t + r * 256;
        int row = lin >> 4;
        int c4  = (lin & 15) << 2;
        float4 v = *(const float4*)(g_ost + ((size_t)z * 64 + row) * 64 + c4);
        As[c4 + 0][row] = v.x; As[c4 + 1][row] = v.y;
        As[c4 + 2][row] = v.z; As[c4 + 3][row] = v.w;
        *(float4*)&Bs[row][c4] =
            *(const float4*)(w_out + (size_t)(h * 64 + row) * 1024 + jc * 64 + c4);
    }
    __syncthreads();
    int tyy = t >> 4, txx = t & 15;
    float acc[4][4] = {};
#pragma unroll
    for (int kk = 0; kk < 64; kk++) {
        float4 a  = *(const float4*)&As[kk][tyy * 4];
        float4 bb = *(const float4*)&Bs[kk][txx * 4];
        float av[4] = {a.x, a.y, a.z, a.w};
        float bv[4] = {bb.x, bb.y, bb.z, bb.w};
#pragma unroll
        for (int i = 0; i < 4; i++)
#pragma unroll
            for (int jj = 0; jj < 4; jj++) acc[i][jj] += av[i] * bv[jj];
    }
#pragma unroll
    for (int i = 0; i < 4; i++) {
        int hm = h * 64 + tyy * 4 + i;
#pragma unroll
        for (int jj = 0; jj < 4; jj++) {
            int j = jc * 64 + txx * 4 + jj;
            g_Ztf[((size_t)b * 1024 + j) * 1024 + hm] = __float2half(acc[i][jj]);
        }
    }
}

// ---------------------------------------------------------------------------
extern "C" void kernel_launch(void* const* d_in, const int* in_sizes, int n_in,
                              void* d_out, int out_size)
{
    (void)in_sizes; (void)n_in; (void)out_size;
    const float* x      = (const float*)d_in[0];
    const float* w_kv   = (const float*)d_in[2];
    const float* b_kv   = (const float*)d_in[3];
    const float* w_temp = (const float*)d_in[4];
    const float* b_temp = (const float*)d_in[5];
    const float* xq     = (const float*)d_in[6];
    const float* qkv_p  = (const float*)d_in[7];
    const float* w_out  = (const float*)d_in[8];
    const float* b_out  = (const float*)d_in[9];
    float* out = (float*)d_out;

    float *pc, *pyp;
    __nv_bfloat16 *pxh, *pxl, *pAth, *pAtl;
    __half *pxtf, *pSf, *pSft, *pZtf;
    cudaGetSymbolAddress((void**)&pc,  g_c);
    cudaGetSymbolAddress((void**)&pyp, g_yp);
    cudaGetSymbolAddress((void**)&pxh, g_xh);   cudaGetSymbolAddress((void**)&pxl, g_xl);
    cudaGetSymbolAddress((void**)&pxtf, g_xtf);
    cudaGetSymbolAddress((void**)&pSf, g_Sf);   cudaGetSymbolAddress((void**)&pSft, g_Sft);
    cudaGetSymbolAddress((void**)&pAth, g_Ath); cudaGetSymbolAddress((void**)&pAtl, g_Atl);
    cudaGetSymbolAddress((void**)&pZtf, g_Ztf);

    cudaFuncSetAttribute(mma_scores,   cudaFuncAttributeMaxDynamicSharedMemorySize, GSMEM);
    cudaFuncSetAttribute(mma1_gemm<0>, cudaFuncAttributeMaxDynamicSharedMemorySize, GSMEM1);
    cudaFuncSetAttribute(mma1_gemm<1>, cudaFuncAttributeMaxDynamicSharedMemorySize, GSMEM1);
    cudaFuncSetAttribute(k_tempmma,    cudaFuncAttributeMaxDynamicSharedMemorySize, TGSMEM);

    // fused prologue: convx + prep + wsplit + zero
    k_aux<<<12368, 256>>>(x, xq, w_kv, b_kv, w_temp);
    k_tempmma<<<256, 256, TGSMEM>>>(pxh, pxl, b_temp);
    // scores (bf16 3-term, 512 thr) + fused softmax/norm/fp16 stores
    mma_scores<<<dim3(4, 256, 1), 512, GSMEM>>>(pxh, pxl, pAth, pAtl, pc);
    // y[b] = S[b]^T @ x[b] (fp16 single-pass, 512 thr), K-split x8
    mma1_gemm<0><<<dim3(4, 8, cB * 8), 512, GSMEM1>>>(
        pSft, pxtf, pyp, nullptr,
        1024, 8192, 8192, 1024,
        (long long)cHM * cN, (long long)cH * cN,
        (long long)cHM * cH, (long long)cB * cHM * cH, 3);
    k_yred<<<4096, 256>>>();
    k_st<<<cB * cNH, 256>>>(w_kv, b_kv);
    k_qkv<<<cB * cNH * 64, 64>>>(qkv_p);
    k_zmat<<<dim3(16, cB * cNH), 256>>>(w_out);
    // out[b] = S[b] @ Zt[b]^T + b_out (fp16 single-pass, 512 thr)
    mma1_gemm<1><<<dim3(4, 64, cB), 512, GSMEM1>>>(
        pSf, pZtf, out, b_out,
        1024, 1024, 1024, 1024,
        (long long)cN * cHM, (long long)cH * cHM,
        (long long)cN * cH, 0, 0);
}

// round 15
// speedup vs baseline: 1.9631x; 1.1322x over previous
#include <cuda_runtime.h>
#include <cuda_bf16.h>
#include <cuda_fp16.h>
#include <math.h>
#include <stdint.h>

constexpr int cB = 4, cN = 8192, cH = 1024, cNH = 16, cHM = 1024;

// ---------------- scratch (device globals) ----------------
__device__ __half g_xfh[(size_t)cB * cN * cH];   // x fp16 hi
__device__ __half g_xfl[(size_t)cB * cN * cH];   // x fp16 lo (x - hi)
__device__ __half g_xtf[(size_t)cB * cH * cN];   // x^T fp16 (y-GEMM B)
__device__ __half g_Sf [(size_t)cB * cN * cHM];  // S fp16 (out-GEMM A)
__device__ __half g_Sft[(size_t)cB * cHM * cN];  // S^T fp16 (y-GEMM A)
__device__ __half g_Atf[cHM * cH];               // At fp16 [hm][j]
__device__ __half g_Ztf[(size_t)cB * cH * cHM];  // Z^T fp16 (out-GEMM B)
__device__ __half g_wtf[cNH * cH];               // w_temp^T fp16 [16][1024]
__device__ float g_c[cHM];
__device__ float g_T[cB * cN * cNH];
__device__ float g_norm[cB * cHM];
__device__ float g_yp[(size_t)8 * cB * cHM * cH];
__device__ float g_st[cB * cNH * 64 * 64];
__device__ float g_ost[cB * cNH * 64 * 64];

// ---------------- helpers ----------------
__device__ __forceinline__ uint32_t smem_u32(const void* p) {
    uint32_t a;
    asm("{ .reg .u64 t; cvta.to.shared.u64 t, %1; cvt.u32.u64 %0, t; }" : "=r"(a) : "l"(p));
    return a;
}
__device__ __forceinline__ void cp16(uint32_t s, const void* g) {
    asm volatile("cp.async.cg.shared.global [%0], [%1], 16;" :: "r"(s), "l"(g));
}
#define CP_COMMIT() asm volatile("cp.async.commit_group;" ::: "memory")
#define CP_WAIT1()  asm volatile("cp.async.wait_group 1;" ::: "memory")
#define CP_WAIT0()  asm volatile("cp.async.wait_group 0;" ::: "memory")

__device__ __forceinline__ void ldsm4(uint32_t* r, uint32_t a) {
    asm volatile("ldmatrix.sync.aligned.m8n8.x4.shared.b16 {%0,%1,%2,%3}, [%4];"
        : "=r"(r[0]), "=r"(r[1]), "=r"(r[2]), "=r"(r[3]) : "r"(a));
}
__device__ __forceinline__ void mma16816h(float* d, const uint32_t* a,
                                          uint32_t b0, uint32_t b1) {
    asm volatile("mma.sync.aligned.m16n8k16.row.col.f32.f16.f16.f32 "
        "{%0,%1,%2,%3}, {%4,%5,%6,%7}, {%8,%9}, {%0,%1,%2,%3};"
        : "+f"(d[0]), "+f"(d[1]), "+f"(d[2]), "+f"(d[3])
        : "r"(a[0]), "r"(a[1]), "r"(a[2]), "r"(a[3]), "r"(b0), "r"(b1));
}
__device__ __forceinline__ void split2h(float v, __half& h, __half& l) {
    h = __float2half(v);
    l = __float2half(v - __half2float(h));
}

// ===== fp16 2-term GEMM (scores): CTA 128x256, 16 warps, warp 64x32, Kc=64 ==
// A = x (fp16 hi+lo), B = At (fp16 single). S = A_h*B + A_l*B.
constexpr int T_AH = 0, T_AL = 16384, T_B = 32768;
constexpr int BUFS = 65536;            // 16K + 16K + 32K
constexpr int GSMEMS = 133632;         // max(2*BUFS, 128*261*4 epilogue)

__global__ void __launch_bounds__(512, 1)
mma_scores(const __half* __restrict__ Ah, const __half* __restrict__ Al,
           const __half* __restrict__ Bf, const float* __restrict__ bias)
{
    extern __shared__ __align__(128) char smem[];
    const int tid = threadIdx.x, wid = tid >> 5, lane = tid & 31;
    uint32_t sbase = smem_u32(smem);
    const int m0 = blockIdx.y * 128, n0 = blockIdx.x * 256;

    auto issue = [&](int c) {
        const int kc = c << 6;
        uint32_t sb = sbase + (c & 1) * BUFS;
#pragma unroll
        for (int i = 0; i < 2; i++) {            // A hi/lo: 1024 cp16 pairs
            const int idx = (i << 9) + tid;
            const int row = idx >> 3, seg = idx & 7;
            uint32_t so = sb + row * 128 + ((seg ^ (row & 7)) << 4);
            long long go = (long long)(m0 + row) * 1024 + kc + seg * 8;
            cp16(so + T_AH, Ah + go);
            cp16(so + T_AL, Al + go);
        }
#pragma unroll
        for (int i = 0; i < 4; i++) {            // B: 2048 cp16
            const int idx = (i << 9) + tid;
            const int row = idx >> 3, seg = idx & 7;
            uint32_t so = sb + T_B + row * 128 + ((seg ^ (row & 7)) << 4);
            cp16(so, Bf + (long long)(n0 + row) * 1024 + kc + seg * 8);
        }
        CP_COMMIT();
    };

    issue(0);

    const int wm = (wid & 1) * 64, wn = (wid >> 1) * 32;
    const int arow  = wm + (lane & 15);
    const int akseg = lane >> 4;
    const int r7a   = arow & 7;
    const int brin  = ((lane >> 4) << 3) + (lane & 7);
    const int bkseg = (lane >> 3) & 1;
    const int r7b   = lane & 7;

    float acc[4][4][4];
#pragma unroll
    for (int a = 0; a < 4; a++)
#pragma unroll
        for (int b = 0; b < 4; b++)
#pragma unroll
            for (int q = 0; q < 4; q++) acc[a][b][q] = 0.f;

    for (int c = 0; c < 16; c++) {
        if (c + 1 < 16) { issue(c + 1); CP_WAIT1(); } else { CP_WAIT0(); }
        __syncthreads();
        uint32_t sb = sbase + (c & 1) * BUFS;
#pragma unroll
        for (int ks = 0; ks < 4; ks++) {
            const int ks2 = ks * 2;
            uint32_t ah[4][4], alr[4][4], bh[2][4];
#pragma unroll
            for (int mt = 0; mt < 4; mt++) {
                uint32_t ao = sb + T_AH + (arow + mt * 16) * 128
                            + (uint32_t)((((ks2 + akseg) ^ r7a)) << 4);
                ldsm4(ah[mt], ao);
                ldsm4(alr[mt], ao + (T_AL - T_AH));
            }
#pragma unroll
            for (int p = 0; p < 2; p++) {
                const int row = wn + p * 16 + brin;
                uint32_t bo = sb + T_B + row * 128
                            + (uint32_t)((((ks2 + bkseg) ^ r7b)) << 4);
                ldsm4(bh[p], bo);
            }
#pragma unroll
            for (int mt = 0; mt < 4; mt++)
#pragma unroll
                for (int nt = 0; nt < 4; nt++) {
                    const int p = nt >> 1, hb = (nt & 1) * 2;
                    mma16816h(acc[mt][nt], ah[mt],  bh[p][hb], bh[p][hb + 1]);
                    mma16816h(acc[mt][nt], alr[mt], bh[p][hb], bh[p][hb + 1]);
                }
        }
        __syncthreads();
    }

    const int rr = lane >> 2, cc = (lane & 3) * 2;
    // ---- fused softmax over m + norm + fp16 dual-layout stores ----
    float* sf = (float*)smem;                 // 128 x 256, pitch 261
#pragma unroll
    for (int mt = 0; mt < 4; mt++) {
#pragma unroll
        for (int nt = 0; nt < 4; nt++) {
            int r = wm + mt * 16 + rr;
            int col = wn + nt * 8 + cc;
            float2 b2 = *(const float2*)(bias + n0 + col);
            sf[r * 261 + col]           = acc[mt][nt][0] + b2.x;
            sf[r * 261 + col + 1]       = acc[mt][nt][1] + b2.y;
            sf[(r + 8) * 261 + col]     = acc[mt][nt][2] + b2.x;
            sf[(r + 8) * 261 + col + 1] = acc[mt][nt][3] + b2.y;
        }
    }
    __syncthreads();
    {
        int row = tid & 127, hq = tid >> 7;
        size_t bn = (size_t)m0 + row;
        int headg = (n0 >> 6) + hq;
        float inv_t = 1.0f / g_T[bn * 16 + headg];
        float* rp = sf + row * 261 + hq * 64;
        float mx = -1e30f;
#pragma unroll 8
        for (int i = 0; i < 64; i++) mx = fmaxf(mx, rp[i]);
        float sum = 0.f;
#pragma unroll 8
        for (int i = 0; i < 64; i++) {
            float e = expf((rp[i] - mx) * inv_t);
            rp[i] = e; sum += e;
        }
        float inv = 1.0f / sum;
#pragma unroll 8
        for (int i = 0; i < 64; i++) rp[i] *= inv;
    }
    __syncthreads();
    const int bidx = m0 >> 13;
    if (tid < 256) {
        float s = 0.f;
#pragma unroll 8
        for (int i = 0; i < 128; i++) s += sf[i * 261 + tid];
        atomicAdd(&g_norm[bidx * 1024 + n0 + tid], s);
    }
#pragma unroll
    for (int i = 0; i < 32; i++) {
        int p = i * 512 + tid;
        int row = p >> 7, col = (p & 127) << 1;
        float w0 = sf[row * 261 + col], w1 = sf[row * 261 + col + 1];
        size_t o = ((size_t)m0 + row) * 1024 + n0 + col;
        *(__half2*)(g_Sf + o) = __floats2half2_rn(w0, w1);
    }
    {
        int nb = m0 & 8191;
#pragma unroll
        for (int i = 0; i < 32; i++) {
            int p = i * 512 + tid;
            int hm = p >> 6, n2 = (p & 63) << 1;
            float w0 = sf[n2 * 261 + hm], w1 = sf[(n2 + 1) * 261 + hm];
            size_t o = ((size_t)bidx * 1024 + n0 + hm) * 8192 + nb + n2;
            *(__half2*)(g_Sft + o) = __floats2half2_rn(w0, w1);
        }
    }
}

// ===== fp16 single-pass GEMM (y/out): CTA 128x256, 16 warps, warp 64x32 =====
constexpr int S1_A = 0, S1_B = 16384;
constexpr int BUF1 = 49152;
constexpr int GSMEM1 = 2 * BUF1;   // 96 KB

template<int EPI>   // 0 = plain store (K-split partials), 1 = bias + store
__global__ void __launch_bounds__(512, 1)
mma1_gemm(const __half* __restrict__ A, const __half* __restrict__ B,
          float* __restrict__ C, const float* __restrict__ bias,
          int Kdim, int lda, int ldb, int ldc,
          long long sA, long long sB, long long sC, long long sCk, int ksl)
{
    extern __shared__ __align__(128) char smem[];
    const int tid = threadIdx.x, wid = tid >> 5, lane = tid & 31;
    uint32_t sbase = smem_u32(smem);
    const long long zz = blockIdx.z;
    const long long batch = zz >> ksl;
    const long long kidx = zz & ((1 << ksl) - 1);
    A += batch * sA + kidx * (long long)Kdim;
    B += batch * sB + kidx * (long long)Kdim;
    C += batch * sC + kidx * sCk;
    const int m0 = blockIdx.y * 128, n0 = blockIdx.x * 256;

    auto issue = [&](int c) {
        const int kc = c << 6;
        uint32_t sb = sbase + (c & 1) * BUF1;
#pragma unroll
        for (int i = 0; i < 2; i++) {
            const int idx = (i << 9) + tid;
            const int row = idx >> 3, seg = idx & 7;
            uint32_t so = sb + S1_A + row * 128 + ((seg ^ (row & 7)) << 4);
            cp16(so, A + (long long)(m0 + row) * lda + kc + seg * 8);
        }
#pragma unroll
        for (int i = 0; i < 4; i++) {
            const int idx = (i << 9) + tid;
            const int row = idx >> 3, seg = idx & 7;
            uint32_t so = sb + S1_B + row * 128 + ((seg ^ (row & 7)) << 4);
            cp16(so, B + (long long)(n0 + row) * ldb + kc + seg * 8);
        }
        CP_COMMIT();
    };

    const int NC = Kdim >> 6;
    issue(0);

    const int wm = (wid & 1) * 64, wn = (wid >> 1) * 32;
    const int arow  = wm + (lane & 15);
    const int akseg = lane >> 4;
    const int r7a   = arow & 7;
    const int brin  = ((lane >> 4) << 3) + (lane & 7);
    const int bkseg = (lane >> 3) & 1;
    const int r7b   = lane & 7;

    float acc[4][4][4];
#pragma unroll
    for (int a = 0; a < 4; a++)
#pragma unroll
        for (int b = 0; b < 4; b++)
#pragma unroll
            for (int q = 0; q < 4; q++) acc[a][b][q] = 0.f;

    for (int c = 0; c < NC; c++) {
        if (c + 1 < NC) { issue(c + 1); CP_WAIT1(); } else { CP_WAIT0(); }
        __syncthreads();
        uint32_t sb = sbase + (c & 1) * BUF1;
#pragma unroll
        for (int ks = 0; ks < 4; ks++) {
            const int ks2 = ks * 2;
            uint32_t ah[4][4], bh[2][4];
#pragma unroll
            for (int mt = 0; mt < 4; mt++) {
                uint32_t ao = sb + S1_A + (arow + mt * 16) * 128
                            + (uint32_t)((((ks2 + akseg) ^ r7a)) << 4);
                ldsm4(ah[mt], ao);
            }
#pragma unroll
            for (int p = 0; p < 2; p++) {
                const int row = wn + p * 16 + brin;
                uint32_t bo = sb + S1_B + row * 128
                            + (uint32_t)((((ks2 + bkseg) ^ r7b)) << 4);
                ldsm4(bh[p], bo);
            }
#pragma unroll
            for (int mt = 0; mt < 4; mt++)
#pragma unroll
                for (int nt = 0; nt < 4; nt++) {
                    const int p = nt >> 1, hb = (nt & 1) * 2;
                    mma16816h(acc[mt][nt], ah[mt], bh[p][hb], bh[p][hb + 1]);
                }
        }
        __syncthreads();
    }

    const int rr = lane >> 2, cc = (lane & 3) * 2;
#pragma unroll
    for (int mt = 0; mt < 4; mt++) {
        const long long m = m0 + wm + mt * 16 + rr;
#pragma unroll
        for (int nt = 0; nt < 4; nt++) {
            const int n = n0 + wn + nt * 8 + cc;
            float bx = 0.f, by = 0.f;
            if (EPI == 1) {
                float2 b2 = *(const float2*)(bias + n);
                bx = b2.x; by = b2.y;
            }
            float2 v0 = make_float2(acc[mt][nt][0] + bx, acc[mt][nt][1] + by);
            float2 v1 = make_float2(acc[mt][nt][2] + bx, acc[mt][nt][3] + by);
            *(float2*)(C + m * ldc + n)       = v0;
            *(float2*)(C + (m + 8) * ldc + n) = v1;
        }
    }
}

// ============ temperature GEMM: fp16 2-term ============
constexpr int TG_AH = 0, TG_AL = 16384;
constexpr int TG_BUF = 32768;
constexpr int TG_B = 65536;
constexpr int TGSMEM = 98304;

__global__ void __launch_bounds__(256, 1)
k_tempmma(const __half* __restrict__ xh, const __half* __restrict__ xl,
          const float* __restrict__ b_temp)
{
    extern __shared__ __align__(128) char smem[];
    const int tid = threadIdx.x, wid = tid >> 5, lane = tid & 31;
    uint32_t sbase = smem_u32(smem);
    const int m0 = blockIdx.x * 128;

#pragma unroll
    for (int q = 0; q < 8; q++) {
        int i = q * 256 + tid;
        int c = i >> 7, r = (i >> 3) & 15, seg = i & 7;
        uint32_t so = sbase + TG_B + c * 2048 + r * 128 + ((seg ^ (r & 7)) << 4);
        cp16(so, g_wtf + r * 1024 + c * 64 + seg * 8);
    }

    auto issueA = [&](int c) {
        uint32_t sb = sbase + (c & 1) * TG_BUF;
        const int kc = c << 6;
#pragma unroll
        for (int q = 0; q < 4; q++) {
            int i = q * 256 + tid;
            int row = i >> 3, seg = i & 7;
            uint32_t so = sb + row * 128 + ((seg ^ (row & 7)) << 4);
            cp16(so,                   xh + (long long)(m0 + row) * 1024 + kc + seg * 8);
            cp16(so + (TG_AL - TG_AH), xl + (long long)(m0 + row) * 1024 + kc + seg * 8);
        }
        CP_COMMIT();
    };
    issueA(0);

    const int wm = wid * 16;
    const int arow  = wm + (lane & 15);
    const int akseg = lane >> 4;
    const int r7a   = arow & 7;
    const int brow  = ((lane >> 4) << 3) + (lane & 7);
    const int bkseg = (lane >> 3) & 1;
    const int r7b   = brow & 7;

    float acc[2][4];
#pragma unroll
    for (int nt = 0; nt < 2; nt++)
#pragma unroll
        for (int q = 0; q < 4; q++) acc[nt][q] = 0.f;

    for (int c = 0; c < 16; c++) {
        if (c + 1 < 16) { issueA(c + 1); CP_WAIT1(); } else { CP_WAIT0(); }
        __syncthreads();
        uint32_t sa = sbase + (c & 1) * TG_BUF;
        uint32_t sbb = sbase + TG_B + c * 2048;
#pragma unroll
        for (int ks = 0; ks < 4; ks++) {
            const int ks2 = ks * 2;
            uint32_t ah[4], alr[4], bh[4];
            uint32_t ao = sa + arow * 128 + (uint32_t)((((ks2 + akseg) ^ r7a)) << 4);
            ldsm4(ah, ao);
            ldsm4(alr, ao + (TG_AL - TG_AH));
            uint32_t bo = sbb + brow * 128 + (uint32_t)((((ks2 + bkseg) ^ r7b)) << 4);
            ldsm4(bh, bo);
#pragma unroll
            for (int nt = 0; nt < 2; nt++) {
                const int hb = nt * 2;
                mma16816h(acc[nt], ah,  bh[hb], bh[hb + 1]);
                mma16816h(acc[nt], alr, bh[hb], bh[hb + 1]);
            }
        }
        __syncthreads();
    }

    const int rr = lane >> 2, cc = (lane & 3) * 2;
    const long long r0 = m0 + wm + rr, r1 = r0 + 8;
#pragma unroll
    for (int nt = 0; nt < 2; nt++) {
        int head = nt * 8 + cc;
        float b0 = b_temp[head], b1 = b_temp[head + 1];
        float v[4] = {acc[nt][0] + b0, acc[nt][1] + b1,
                      acc[nt][2] + b0, acc[nt][3] + b1};
#pragma unroll
        for (int q = 0; q < 4; q++) {
            float s = v[q];
            v[q] = 0.5f + fmaxf(s, 0.f) + log1pf(expf(-fabsf(s)));
        }
        g_T[r0 * 16 + head]     = v[0];
        g_T[r0 * 16 + head + 1] = v[1];
        g_T[r1 * 16 + head]     = v[2];
        g_T[r1 * 16 + head + 1] = v[3];
    }
}

// ============ fused prologue: convx | prep | wsplit | zero ============
__global__ void __launch_bounds__(256)
k_aux(const float* __restrict__ x, const float* __restrict__ xq,
      const float* __restrict__ w_kv, const float* __restrict__ b_kv,
      const float* __restrict__ w_temp)
{
    __shared__ float xs[64][67];
    const int bid = blockIdx.x;
    const int t = threadIdx.x;

    if (bid < 8192) {
        const int jt = bid & 15, nt = bid >> 4;
#pragma unroll
        for (int q = 0; q < 4; q++) {
            int lin = q * 256 + t;
            int row = lin >> 4, c4 = (lin & 15) << 2;
            float4 v = *(const float4*)(x + ((size_t)nt * 64 + row) * 1024 + jt * 64 + c4);
            xs[row][c4 + 0] = v.x; xs[row][c4 + 1] = v.y;
            xs[row][c4 + 2] = v.z; xs[row][c4 + 3] = v.w;
        }
        __syncthreads();
#pragma unroll
        for (int q = 0; q < 8; q++) {
            int lin = q * 256 + t;
            int row = lin >> 5, col = (lin & 31) << 1;
            float w0 = xs[row][col], w1 = xs[row][col + 1];
            __half h0, l0, h1, l1;
            split2h(w0, h0, l0); split2h(w1, h1, l1);
            size_t o = ((size_t)nt * 64 + row) * 1024 + jt * 64 + col;
            *(__half2*)(g_xfh + o) = __halves2half2(h0, h1);
            *(__half2*)(g_xfl + o) = __halves2half2(l0, l1);
        }
        const int b = (nt * 64) >> 13, nn0 = (nt * 64) & 8191;
#pragma unroll
        for (int q = 0; q < 8; q++) {
            int lin = q * 256 + t;
            int j = lin >> 5, n2 = (lin & 31) << 1;
            size_t o = ((size_t)(b * 1024 + jt * 64 + j)) * 8192 + nn0 + n2;
            *(__half2*)(g_xtf + o) = __floats2half2_rn(xs[n2][j], xs[n2 + 1][j]);
        }
    } else if (bid < 12288) {
        int idx = (bid - 8192) * 256 + t;
        int j = idx >> 10, hm = idx & 1023;
        int hbase = (hm >> 6) << 6;
        const float* xr = xq + (size_t)hm * 64;
        const float* wr = w_kv + (size_t)j * 2048 + hbase;
        float acc = 0.f;
#pragma unroll 8
        for (int d = 0; d < 64; d++) acc += xr[d] * wr[d];
        g_Atf[(size_t)hm * 1024 + j] = __float2half(acc);
        if (j == 0) {
            const float* br = b_kv + hbase;
            float cc = 0.f;
            for (int d = 0; d < 64; d++) cc += xr[d] * br[d];
            g_c[hm] = cc;
        }
    } else if (bid < 12352) {
        int idx = (bid - 12288) * 256 + t;
        int h = idx >> 10, j = idx & 1023;
        g_wtf[idx] = __float2half(w_temp[j * 16 + h]);
    } else {
        int i = (bid - 12352) * 256 + t;
        if (i < cB * cHM) g_norm[i] = 0.f;
    }
}

// ============ reduce 8 y-partials into partial 0 ============
__global__ void __launch_bounds__(256)
k_yred()
{
    constexpr size_t YPS4 = (size_t)cB * cHM * cH / 4;
    size_t i = (size_t)blockIdx.x * 256 + threadIdx.x;
    float4* base = (float4*)g_yp;
    float4 s = base[i];
#pragma unroll
    for (int p = 1; p < 8; p++) {
        float4 v = base[p * YPS4 + i];
        s.x += v.x; s.y += v.y; s.z += v.z; s.w += v.w;
    }
    base[i] = s;
}

// slice_token from reduced y (partial 0)
__global__ void __launch_bounds__(256)
k_st(const float* __restrict__ w_kv, const float* __restrict__ b_kv)
{
    int z = blockIdx.x;
    int b = z >> 4, h = z & 15;
    const float* Yb = g_yp + ((size_t)b * 1024 + h * 64) * 1024;
    const float* Wv = w_kv + 1024 + h * 64;
    __shared__ float As[16][64];
    __shared__ float Bs[16][64];
    int t = threadIdx.x;
    int tyy = t >> 4, txx = t & 15;
    float acc[4][4] = {};
    for (int k0 = 0; k0 < 1024; k0 += 16) {
        {
            int m = t >> 2, k4 = (t & 3) << 2;
            float4 v = *(const float4*)(Yb + (size_t)m * 1024 + k0 + k4);
            As[k4 + 0][m] = v.x; As[k4 + 1][m] = v.y;
            As[k4 + 2][m] = v.z; As[k4 + 3][m] = v.w;
        }
        {
            int k = t >> 4, n4 = (t & 15) << 2;
            *(float4*)&Bs[k][n4] = *(const float4*)(Wv + (size_t)(k0 + k) * 2048 + n4);
        }
        __syncthreads();
#pragma unroll
        for (int kk = 0; kk < 16; kk++) {
            float4 a  = *(const float4*)&As[kk][tyy * 4];
            float4 bb = *(const float4*)&Bs[kk][txx * 4];
            float av[4] = {a.x, a.y, a.z, a.w};
            float bv[4] = {bb.x, bb.y, bb.z, bb.w};
#pragma unroll
            for (int i = 0; i < 4; i++)
#pragma unroll
                for (int jj = 0; jj < 4; jj++) acc[i][jj] += av[i] * bv[jj];
        }
        __syncthreads();
    }
#pragma unroll
    for (int i = 0; i < 4; i++) {
        int m = tyy * 4 + i;
        float nrm = g_norm[b * 1024 + h * 64 + m];
        float inv = 1.0f / (nrm + 1e-5f);
#pragma unroll
        for (int jj = 0; jj < 4; jj++) {
            int d = txx * 4 + jj;
            float bvv = b_kv[1024 + h * 64 + d];
            g_st[((size_t)z * 64 + m) * 64 + d] = (acc[i][jj] + nrm * bvv) * inv;
        }
    }
}

__global__ void __launch_bounds__(64)
k_qkv(const float* __restrict__ qkv_proj)
{
    int z = blockIdx.x;
    int h = (z >> 6) & 15;
    int d = threadIdx.x;
    __shared__ float st[64];
    __shared__ float ex[64];
    st[d] = g_st[(size_t)z * 64 + d];
    __syncthreads();
    const float* P = qkv_proj + (size_t)h * 64 * 192;
    float q = 0.f, k = 0.f, v = 0.f;
#pragma unroll 8
    for (int j = 0; j < 64; j++) {
        float s = st[j];
        const float* pr = P + j * 192;
        q += s * pr[d]; k += s * pr[64 + d]; v += s * pr[128 + d];
    }
    float dot = q * k * 0.125f;
    ex[d] = dot;
    __syncthreads();
    float mx = -1e30f;
    for (int j = 0; j < 64; j++) mx = fmaxf(mx, ex[j]);
    __syncthreads();
    float e = expf(dot - mx);
    ex[d] = e;
    __syncthreads();
    float sum = 0.f;
    for (int j = 0; j < 64; j++) sum += ex[j];
    g_ost[(size_t)z * 64 + d] = (e / sum) * v;
}

__global__ void __launch_bounds__(256)
k_zmat(const float* __restrict__ w_out)
{
    int z = blockIdx.y, jc = blockIdx.x;
    int b = z >> 4, h = z & 15;
    __shared__ float As[64][64];
    __shared__ float Bs[64][64];
    int t = threadIdx.x;
#pragma unroll
    for (int r = 0; r < 4; r++) {
        int lin = t + r * 256;
        int row = lin >> 4;
        int c4  = (lin & 15) << 2;
        float4 v = *(const float4*)(g_ost + ((size_t)z * 64 + row) * 64 + c4);
        As[c4 + 0][row] = v.x; As[c4 + 1][row] = v.y;
        As[c4 + 2][row] = v.z; As[c4 + 3][row] = v.w;
        *(float4*)&Bs[row][c4] =
            *(const float4*)(w_out + (size_t)(h * 64 + row) * 1024 + jc * 64 + c4);
    }
    __syncthreads();
    int tyy = t >> 4, txx = t & 15;
    float acc[4][4] = {};
#pragma unroll
    for (int kk = 0; kk < 64; kk++) {
        float4 a  = *(const float4*)&As[kk][tyy * 4];
        float4 bb = *(const float4*)&Bs[kk][txx * 4];
        float av[4] = {a.x, a.y, a.z, a.w};
        float bv[4] = {bb.x, bb.y, bb.z, bb.w};
#pragma unroll
        for (int i = 0; i < 4; i++)
#pragma unroll
            for (int jj = 0; jj < 4; jj++) acc[i][jj] += av[i] * bv[jj];
    }
#pragma unroll
    for (int i = 0; i < 4; i++) {
        int hm = h * 64 + tyy * 4 + i;
#pragma unroll
        for (int jj = 0; jj < 4; jj++) {
            int j = jc * 64 + txx * 4 + jj;
            g_Ztf[((size_t)b * 1024 + j) * 1024 + hm] = __float2half(acc[i][jj]);
        }
    }
}

// ---------------------------------------------------------------------------
extern "C" void kernel_launch(void* const* d_in, const int* in_sizes, int n_in,
                              void* d_out, int out_size)
{
    (void)in_sizes; (void)n_in; (void)out_size;
    const float* x      = (const float*)d_in[0];
    const float* w_kv   = (const float*)d_in[2];
    const float* b_kv   = (const float*)d_in[3];
    const float* w_temp = (const float*)d_in[4];
    const float* b_temp = (const float*)d_in[5];
    const float* xq     = (const float*)d_in[6];
    const float* qkv_p  = (const float*)d_in[7];
    const float* w_out  = (const float*)d_in[8];
    const float* b_out  = (const float*)d_in[9];
    float* out = (float*)d_out;

    float *pc, *pyp;
    __half *pxfh, *pxfl, *pxtf, *pSf, *pSft, *pAtf, *pZtf;
    cudaGetSymbolAddress((void**)&pc,  g_c);
    cudaGetSymbolAddress((void**)&pyp, g_yp);
    cudaGetSymbolAddress((void**)&pxfh, g_xfh); cudaGetSymbolAddress((void**)&pxfl, g_xfl);
    cudaGetSymbolAddress((void**)&pxtf, g_xtf);
    cudaGetSymbolAddress((void**)&pSf, g_Sf);   cudaGetSymbolAddress((void**)&pSft, g_Sft);
    cudaGetSymbolAddress((void**)&pAtf, g_Atf);
    cudaGetSymbolAddress((void**)&pZtf, g_Ztf);

    cudaFuncSetAttribute(mma_scores,   cudaFuncAttributeMaxDynamicSharedMemorySize, GSMEMS);
    cudaFuncSetAttribute(mma1_gemm<0>, cudaFuncAttributeMaxDynamicSharedMemorySize, GSMEM1);
    cudaFuncSetAttribute(mma1_gemm<1>, cudaFuncAttributeMaxDynamicSharedMemorySize, GSMEM1);
    cudaFuncSetAttribute(k_tempmma,    cudaFuncAttributeMaxDynamicSharedMemorySize, TGSMEM);

    // fused prologue: convx + prep + wsplit + zero
    k_aux<<<12368, 256>>>(x, xq, w_kv, b_kv, w_temp);
    k_tempmma<<<256, 256, TGSMEM>>>(pxfh, pxfl, b_temp);
    // scores (fp16 2-term) + fused softmax/norm/fp16 stores
    mma_scores<<<dim3(4, 256, 1), 512, GSMEMS>>>(pxfh, pxfl, pAtf, pc);
    // y[b] = S[b]^T @ x[b] (fp16 single-pass), K-split x8
    mma1_gemm<0><<<dim3(4, 8, cB * 8), 512, GSMEM1>>>(
        pSft, pxtf, pyp, nullptr,
        1024, 8192, 8192, 1024,
        (long long)cHM * cN, (long long)cH * cN,
        (long long)cHM * cH, (long long)cB * cHM * cH, 3);
    k_yred<<<4096, 256>>>();
    k_st<<<cB * cNH, 256>>>(w_kv, b_kv);
    k_qkv<<<cB * cNH * 64, 64>>>(qkv_p);
    k_zmat<<<dim3(16, cB * cNH), 256>>>(w_out);
    // out[b] = S[b] @ Zt[b]^T + b_out (fp16 single-pass)
    mma1_gemm<1><<<dim3(4, 64, cB), 512, GSMEM1>>>(
        pSf, pZtf, out, b_out,
        1024, 1024, 1024, 1024,
        (long long)cN * cHM, (long long)cH * cHM,
        (long long)cN * cH, 0, 0);
}

// round 16
// speedup vs baseline: 2.2336x; 1.1378x over previous
#include <cuda_runtime.h>
#include <cuda_fp16.h>
#include <math.h>
#include <stdint.h>

constexpr int cB = 4, cN = 8192, cH = 1024, cNH = 16, cHM = 1024;

// ---------------- scratch (device globals) ----------------
__device__ __half g_xfh[(size_t)cB * cN * cH];   // x fp16 (row-major)
__device__ __half g_xtf[(size_t)cB * cH * cN];   // x^T fp16 (y-GEMM B)
__device__ __half g_Sf [(size_t)cB * cN * cHM];  // S fp16 (out-GEMM A)
__device__ __half g_Sft[(size_t)cB * cHM * cN];  // S^T fp16 (y-GEMM A)
__device__ __half g_Atf[cHM * cH];               // At fp16 [hm][j]
__device__ __half g_Ztf[(size_t)cB * cH * cHM];  // Z^T fp16 (out-GEMM B)
__device__ __half g_wtf[cNH * cH];               // w_temp^T fp16 [16][1024]
__device__ float g_c[cHM];
__device__ float g_T[cB * cN * cNH];
__device__ float g_norm[cB * cHM];
__device__ float g_yp[(size_t)8 * cB * cHM * cH];
__device__ float g_st[cB * cNH * 64 * 64];
__device__ float g_ost[cB * cNH * 64 * 64];

// ---------------- helpers ----------------
__device__ __forceinline__ uint32_t smem_u32(const void* p) {
    uint32_t a;
    asm("{ .reg .u64 t; cvta.to.shared.u64 t, %1; cvt.u32.u64 %0, t; }" : "=r"(a) : "l"(p));
    return a;
}
__device__ __forceinline__ void cp16(uint32_t s, const void* g) {
    asm volatile("cp.async.cg.shared.global [%0], [%1], 16;" :: "r"(s), "l"(g));
}
#define CP_COMMIT() asm volatile("cp.async.commit_group;" ::: "memory")
#define CP_WAIT1()  asm volatile("cp.async.wait_group 1;" ::: "memory")
#define CP_WAIT0()  asm volatile("cp.async.wait_group 0;" ::: "memory")

__device__ __forceinline__ void ldsm4(uint32_t* r, uint32_t a) {
    asm volatile("ldmatrix.sync.aligned.m8n8.x4.shared.b16 {%0,%1,%2,%3}, [%4];"
        : "=r"(r[0]), "=r"(r[1]), "=r"(r[2]), "=r"(r[3]) : "r"(a));
}
__device__ __forceinline__ void mma16816h(float* d, const uint32_t* a,
                                          uint32_t b0, uint32_t b1) {
    asm volatile("mma.sync.aligned.m16n8k16.row.col.f32.f16.f16.f32 "
        "{%0,%1,%2,%3}, {%4,%5,%6,%7}, {%8,%9}, {%0,%1,%2,%3};"
        : "+f"(d[0]), "+f"(d[1]), "+f"(d[2]), "+f"(d[3])
        : "r"(a[0]), "r"(a[1]), "r"(a[2]), "r"(a[3]), "r"(b0), "r"(b1));
}

// ===== fp16 1-pass GEMM (scores): CTA 128x256, 16 warps, warp 64x32, Kc=64 ==
constexpr int T_A = 0, T_B = 16384;
constexpr int BUFS = 49152;            // 16K A + 32K B
constexpr int GSMEMS = 133632;         // max(2*BUFS, 128*261*4 epilogue)

__global__ void __launch_bounds__(512, 1)
mma_scores(const __half* __restrict__ Af, const __half* __restrict__ Bf,
           const float* __restrict__ bias)
{
    extern __shared__ __align__(128) char smem[];
    const int tid = threadIdx.x, wid = tid >> 5, lane = tid & 31;
    uint32_t sbase = smem_u32(smem);
    const int m0 = blockIdx.y * 128, n0 = blockIdx.x * 256;

    auto issue = [&](int c) {
        const int kc = c << 6;
        uint32_t sb = sbase + (c & 1) * BUFS;
#pragma unroll
        for (int i = 0; i < 2; i++) {            // A: 1024 cp16
            const int idx = (i << 9) + tid;
            const int row = idx >> 3, seg = idx & 7;
            uint32_t so = sb + T_A + row * 128 + ((seg ^ (row & 7)) << 4);
            cp16(so, Af + (long long)(m0 + row) * 1024 + kc + seg * 8);
        }
#pragma unroll
        for (int i = 0; i < 4; i++) {            // B: 2048 cp16
            const int idx = (i << 9) + tid;
            const int row = idx >> 3, seg = idx & 7;
            uint32_t so = sb + T_B + row * 128 + ((seg ^ (row & 7)) << 4);
            cp16(so, Bf + (long long)(n0 + row) * 1024 + kc + seg * 8);
        }
        CP_COMMIT();
    };

    issue(0);

    const int wm = (wid & 1) * 64, wn = (wid >> 1) * 32;
    const int arow  = wm + (lane & 15);
    const int akseg = lane >> 4;
    const int r7a   = arow & 7;
    const int brin  = ((lane >> 4) << 3) + (lane & 7);
    const int bkseg = (lane >> 3) & 1;
    const int r7b   = lane & 7;

    float acc[4][4][4];
#pragma unroll
    for (int a = 0; a < 4; a++)
#pragma unroll
        for (int b = 0; b < 4; b++)
#pragma unroll
            for (int q = 0; q < 4; q++) acc[a][b][q] = 0.f;

    for (int c = 0; c < 16; c++) {
        if (c + 1 < 16) { issue(c + 1); CP_WAIT1(); } else { CP_WAIT0(); }
        __syncthreads();
        uint32_t sb = sbase + (c & 1) * BUFS;
#pragma unroll
        for (int ks = 0; ks < 4; ks++) {
            const int ks2 = ks * 2;
            uint32_t ah[4][4], bh[2][4];
#pragma unroll
            for (int mt = 0; mt < 4; mt++) {
                uint32_t ao = sb + T_A + (arow + mt * 16) * 128
                            + (uint32_t)((((ks2 + akseg) ^ r7a)) << 4);
                ldsm4(ah[mt], ao);
            }
#pragma unroll
            for (int p = 0; p < 2; p++) {
                const int row = wn + p * 16 + brin;
                uint32_t bo = sb + T_B + row * 128
                            + (uint32_t)((((ks2 + bkseg) ^ r7b)) << 4);
                ldsm4(bh[p], bo);
            }
#pragma unroll
            for (int mt = 0; mt < 4; mt++)
#pragma unroll
                for (int nt = 0; nt < 4; nt++) {
                    const int p = nt >> 1, hb = (nt & 1) * 2;
                    mma16816h(acc[mt][nt], ah[mt], bh[p][hb], bh[p][hb + 1]);
                }
        }
        __syncthreads();
    }

    const int rr = lane >> 2, cc = (lane & 3) * 2;
    // ---- fused softmax over m + norm + fp16 dual-layout stores ----
    float* sf = (float*)smem;                 // 128 x 256, pitch 261
#pragma unroll
    for (int mt = 0; mt < 4; mt++) {
#pragma unroll
        for (int nt = 0; nt < 4; nt++) {
            int r = wm + mt * 16 + rr;
            int col = wn + nt * 8 + cc;
            float2 b2 = *(const float2*)(bias + n0 + col);
            sf[r * 261 + col]           = acc[mt][nt][0] + b2.x;
            sf[r * 261 + col + 1]       = acc[mt][nt][1] + b2.y;
            sf[(r + 8) * 261 + col]     = acc[mt][nt][2] + b2.x;
            sf[(r + 8) * 261 + col + 1] = acc[mt][nt][3] + b2.y;
        }
    }
    __syncthreads();
    {
        int row = tid & 127, hq = tid >> 7;
        size_t bn = (size_t)m0 + row;
        int headg = (n0 >> 6) + hq;
        float inv_t = 1.0f / g_T[bn * 16 + headg];
        float* rp = sf + row * 261 + hq * 64;
        float mx = -1e30f;
#pragma unroll 8
        for (int i = 0; i < 64; i++) mx = fmaxf(mx, rp[i]);
        float sum = 0.f;
#pragma unroll 8
        for (int i = 0; i < 64; i++) {
            float e = expf((rp[i] - mx) * inv_t);
            rp[i] = e; sum += e;
        }
        float inv = 1.0f / sum;
#pragma unroll 8
        for (int i = 0; i < 64; i++) rp[i] *= inv;
    }
    __syncthreads();
    const int bidx = m0 >> 13;
    if (tid < 256) {
        float s = 0.f;
#pragma unroll 8
        for (int i = 0; i < 128; i++) s += sf[i * 261 + tid];
        atomicAdd(&g_norm[bidx * 1024 + n0 + tid], s);
    }
#pragma unroll
    for (int i = 0; i < 32; i++) {
        int p = i * 512 + tid;
        int row = p >> 7, col = (p & 127) << 1;
        float w0 = sf[row * 261 + col], w1 = sf[row * 261 + col + 1];
        size_t o = ((size_t)m0 + row) * 1024 + n0 + col;
        *(__half2*)(g_Sf + o) = __floats2half2_rn(w0, w1);
    }
    {
        int nb = m0 & 8191;
#pragma unroll
        for (int i = 0; i < 32; i++) {
            int p = i * 512 + tid;
            int hm = p >> 6, n2 = (p & 63) << 1;
            float w0 = sf[n2 * 261 + hm], w1 = sf[(n2 + 1) * 261 + hm];
            size_t o = ((size_t)bidx * 1024 + n0 + hm) * 8192 + nb + n2;
            *(__half2*)(g_Sft + o) = __floats2half2_rn(w0, w1);
        }
    }
}

// ===== fp16 single-pass GEMM (y/out): CTA 128x256, 16 warps, warp 64x32 =====
constexpr int S1_A = 0, S1_B = 16384;
constexpr int BUF1 = 49152;
constexpr int GSMEM1 = 2 * BUF1;   // 96 KB

template<int EPI>   // 0 = plain store (K-split partials), 1 = bias + store
__global__ void __launch_bounds__(512, 1)
mma1_gemm(const __half* __restrict__ A, const __half* __restrict__ B,
          float* __restrict__ C, const float* __restrict__ bias,
          int Kdim, int lda, int ldb, int ldc,
          long long sA, long long sB, long long sC, long long sCk, int ksl)
{
    extern __shared__ __align__(128) char smem[];
    const int tid = threadIdx.x, wid = tid >> 5, lane = tid & 31;
    uint32_t sbase = smem_u32(smem);
    const long long zz = blockIdx.z;
    const long long batch = zz >> ksl;
    const long long kidx = zz & ((1 << ksl) - 1);
    A += batch * sA + kidx * (long long)Kdim;
    B += batch * sB + kidx * (long long)Kdim;
    C += batch * sC + kidx * sCk;
    const int m0 = blockIdx.y * 128, n0 = blockIdx.x * 256;

    auto issue = [&](int c) {
        const int kc = c << 6;
        uint32_t sb = sbase + (c & 1) * BUF1;
#pragma unroll
        for (int i = 0; i < 2; i++) {
            const int idx = (i << 9) + tid;
            const int row = idx >> 3, seg = idx & 7;
            uint32_t so = sb + S1_A + row * 128 + ((seg ^ (row & 7)) << 4);
            cp16(so, A + (long long)(m0 + row) * lda + kc + seg * 8);
        }
#pragma unroll
        for (int i = 0; i < 4; i++) {
            const int idx = (i << 9) + tid;
            const int row = idx >> 3, seg = idx & 7;
            uint32_t so = sb + S1_B + row * 128 + ((seg ^ (row & 7)) << 4);
            cp16(so, B + (long long)(n0 + row) * ldb + kc + seg * 8);
        }
        CP_COMMIT();
    };

    const int NC = Kdim >> 6;
    issue(0);

    const int wm = (wid & 1) * 64, wn = (wid >> 1) * 32;
    const int arow  = wm + (lane & 15);
    const int akseg = lane >> 4;
    const int r7a   = arow & 7;
    const int brin  = ((lane >> 4) << 3) + (lane & 7);
    const int bkseg = (lane >> 3) & 1;
    const int r7b   = lane & 7;

    float acc[4][4][4];
#pragma unroll
    for (int a = 0; a < 4; a++)
#pragma unroll
        for (int b = 0; b < 4; b++)
#pragma unroll
            for (int q = 0; q < 4; q++) acc[a][b][q] = 0.f;

    for (int c = 0; c < NC; c++) {
        if (c + 1 < NC) { issue(c + 1); CP_WAIT1(); } else { CP_WAIT0(); }
        __syncthreads();
        uint32_t sb = sbase + (c & 1) * BUF1;
#pragma unroll
        for (int ks = 0; ks < 4; ks++) {
            const int ks2 = ks * 2;
            uint32_t ah[4][4], bh[2][4];
#pragma unroll
            for (int mt = 0; mt < 4; mt++) {
                uint32_t ao = sb + S1_A + (arow + mt * 16) * 128
                            + (uint32_t)((((ks2 + akseg) ^ r7a)) << 4);
                ldsm4(ah[mt], ao);
            }
#pragma unroll
            for (int p = 0; p < 2; p++) {
                const int row = wn + p * 16 + brin;
                uint32_t bo = sb + S1_B + row * 128
                            + (uint32_t)((((ks2 + bkseg) ^ r7b)) << 4);
                ldsm4(bh[p], bo);
            }
#pragma unroll
            for (int mt = 0; mt < 4; mt++)
#pragma unroll
                for (int nt = 0; nt < 4; nt++) {
                    const int p = nt >> 1, hb = (nt & 1) * 2;
                    mma16816h(acc[mt][nt], ah[mt], bh[p][hb], bh[p][hb + 1]);
                }
        }
        __syncthreads();
    }

    const int rr = lane >> 2, cc = (lane & 3) * 2;
#pragma unroll
    for (int mt = 0; mt < 4; mt++) {
        const long long m = m0 + wm + mt * 16 + rr;
#pragma unroll
        for (int nt = 0; nt < 4; nt++) {
            const int n = n0 + wn + nt * 8 + cc;
            float bx = 0.f, by = 0.f;
            if (EPI == 1) {
                float2 b2 = *(const float2*)(bias + n);
                bx = b2.x; by = b2.y;
            }
            float2 v0 = make_float2(acc[mt][nt][0] + bx, acc[mt][nt][1] + by);
            float2 v1 = make_float2(acc[mt][nt][2] + bx, acc[mt][nt][3] + by);
            *(float2*)(C + m * ldc + n)       = v0;
            *(float2*)(C + (m + 8) * ldc + n) = v1;
        }
    }
}

// ============ temperature GEMM: fp16 single-pass ============
constexpr int TG_A = 0;
constexpr int TG_BUF = 16384;
constexpr int TG_B = 32768;
constexpr int TGSMEM = 65536;

__global__ void __launch_bounds__(256, 1)
k_tempmma(const __half* __restrict__ xf, const float* __restrict__ b_temp)
{
    extern __shared__ __align__(128) char smem[];
    const int tid = threadIdx.x, wid = tid >> 5, lane = tid & 31;
    uint32_t sbase = smem_u32(smem);
    const int m0 = blockIdx.x * 128;

#pragma unroll
    for (int q = 0; q < 8; q++) {
        int i = q * 256 + tid;
        int c = i >> 7, r = (i >> 3) & 15, seg = i & 7;
        uint32_t so = sbase + TG_B + c * 2048 + r * 128 + ((seg ^ (r & 7)) << 4);
        cp16(so, g_wtf + r * 1024 + c * 64 + seg * 8);
    }

    auto issueA = [&](int c) {
        uint32_t sb = sbase + (c & 1) * TG_BUF;
        const int kc = c << 6;
#pragma unroll
        for (int q = 0; q < 4; q++) {
            int i = q * 256 + tid;
            int row = i >> 3, seg = i & 7;
            uint32_t so = sb + row * 128 + ((seg ^ (row & 7)) << 4);
            cp16(so, xf + (long long)(m0 + row) * 1024 + kc + seg * 8);
        }
        CP_COMMIT();
    };
    issueA(0);

    const int wm = wid * 16;
    const int arow  = wm + (lane & 15);
    const int akseg = lane >> 4;
    const int r7a   = arow & 7;
    const int brow  = ((lane >> 4) << 3) + (lane & 7);
    const int bkseg = (lane >> 3) & 1;
    const int r7b   = brow & 7;

    float acc[2][4];
#pragma unroll
    for (int nt = 0; nt < 2; nt++)
#pragma unroll
        for (int q = 0; q < 4; q++) acc[nt][q] = 0.f;

    for (int c = 0; c < 16; c++) {
        if (c + 1 < 16) { issueA(c + 1); CP_WAIT1(); } else { CP_WAIT0(); }
        __syncthreads();
        uint32_t sa = sbase + (c & 1) * TG_BUF;
        uint32_t sbb = sbase + TG_B + c * 2048;
#pragma unroll
        for (int ks = 0; ks < 4; ks++) {
            const int ks2 = ks * 2;
            uint32_t ah[4], bh[4];
            uint32_t ao = sa + arow * 128 + (uint32_t)((((ks2 + akseg) ^ r7a)) << 4);
            ldsm4(ah, ao);
            uint32_t bo = sbb + brow * 128 + (uint32_t)((((ks2 + bkseg) ^ r7b)) << 4);
            ldsm4(bh, bo);
#pragma unroll
            for (int nt = 0; nt < 2; nt++) {
                const int hb = nt * 2;
                mma16816h(acc[nt], ah, bh[hb], bh[hb + 1]);
            }
        }
        __syncthreads();
    }

    const int rr = lane >> 2, cc = (lane & 3) * 2;
    const long long r0 = m0 + wm + rr, r1 = r0 + 8;
#pragma unroll
    for (int nt = 0; nt < 2; nt++) {
        int head = nt * 8 + cc;
        float b0 = b_temp[head], b1 = b_temp[head + 1];
        float v[4] = {acc[nt][0] + b0, acc[nt][1] + b1,
                      acc[nt][2] + b0, acc[nt][3] + b1};
#pragma unroll
        for (int q = 0; q < 4; q++) {
            float s = v[q];
            v[q] = 0.5f + fmaxf(s, 0.f) + log1pf(expf(-fabsf(s)));
        }
        g_T[r0 * 16 + head]     = v[0];
        g_T[r0 * 16 + head + 1] = v[1];
        g_T[r1 * 16 + head]     = v[2];
        g_T[r1 * 16 + head + 1] = v[3];
    }
}

// ============ fused prologue: convx | prep | wsplit | zero ============
__global__ void __launch_bounds__(256)
k_aux(const float* __restrict__ x, const float* __restrict__ xq,
      const float* __restrict__ w_kv, const float* __restrict__ b_kv,
      const float* __restrict__ w_temp)
{
    __shared__ float xs[64][67];
    const int bid = blockIdx.x;
    const int t = threadIdx.x;

    if (bid < 8192) {
        const int jt = bid & 15, nt = bid >> 4;
#pragma unroll
        for (int q = 0; q < 4; q++) {
            int lin = q * 256 + t;
            int row = lin >> 4, c4 = (lin & 15) << 2;
            float4 v = *(const float4*)(x + ((size_t)nt * 64 + row) * 1024 + jt * 64 + c4);
            xs[row][c4 + 0] = v.x; xs[row][c4 + 1] = v.y;
            xs[row][c4 + 2] = v.z; xs[row][c4 + 3] = v.w;
        }
        __syncthreads();
#pragma unroll
        for (int q = 0; q < 8; q++) {
            int lin = q * 256 + t;
            int row = lin >> 5, col = (lin & 31) << 1;
            size_t o = ((size_t)nt * 64 + row) * 1024 + jt * 64 + col;
            *(__half2*)(g_xfh + o) = __floats2half2_rn(xs[row][col], xs[row][col + 1]);
        }
        const int b = (nt * 64) >> 13, nn0 = (nt * 64) & 8191;
#pragma unroll
        for (int q = 0; q < 8; q++) {
            int lin = q * 256 + t;
            int j = lin >> 5, n2 = (lin & 31) << 1;
            size_t o = ((size_t)(b * 1024 + jt * 64 + j)) * 8192 + nn0 + n2;
            *(__half2*)(g_xtf + o) = __floats2half2_rn(xs[n2][j], xs[n2 + 1][j]);
        }
    } else if (bid < 12288) {
        int idx = (bid - 8192) * 256 + t;
        int j = idx >> 10, hm = idx & 1023;
        int hbase = (hm >> 6) << 6;
        const float* xr = xq + (size_t)hm * 64;
        const float* wr = w_kv + (size_t)j * 2048 + hbase;
        float acc = 0.f;
#pragma unroll 8
        for (int d = 0; d < 64; d++) acc += xr[d] * wr[d];
        g_Atf[(size_t)hm * 1024 + j] = __float2half(acc);
        if (j == 0) {
            const float* br = b_kv + hbase;
            float cc = 0.f;
            for (int d = 0; d < 64; d++) cc += xr[d] * br[d];
            g_c[hm] = cc;
        }
    } else if (bid < 12352) {
        int idx = (bid - 12288) * 256 + t;
        int h = idx >> 10, j = idx & 1023;
        g_wtf[idx] = __float2half(w_temp[j * 16 + h]);
    } else {
        int i = (bid - 12352) * 256 + t;
        if (i < cB * cHM) g_norm[i] = 0.f;
    }
}

// ============ reduce 8 y-partials into partial 0 ============
__global__ void __launch_bounds__(256)
k_yred()
{
    constexpr size_t YPS4 = (size_t)cB * cHM * cH / 4;
    size_t i = (size_t)blockIdx.x * 256 + threadIdx.x;
    float4* base = (float4*)g_yp;
    float4 s = base[i];
#pragma unroll
    for (int p = 1; p < 8; p++) {
        float4 v = base[p * YPS4 + i];
        s.x += v.x; s.y += v.y; s.z += v.z; s.w += v.w;
    }
    base[i] = s;
}

// slice_token from reduced y (partial 0)
__global__ void __launch_bounds__(256)
k_st(const float* __restrict__ w_kv, const float* __restrict__ b_kv)
{
    int z = blockIdx.x;
    int b = z >> 4, h = z & 15;
    const float* Yb = g_yp + ((size_t)b * 1024 + h * 64) * 1024;
    const float* Wv = w_kv + 1024 + h * 64;
    __shared__ float As[16][64];
    __shared__ float Bs[16][64];
    int t = threadIdx.x;
    int tyy = t >> 4, txx = t & 15;
    float acc[4][4] = {};
    for (int k0 = 0; k0 < 1024; k0 += 16) {
        {
            int m = t >> 2, k4 = (t & 3) << 2;
            float4 v = *(const float4*)(Yb + (size_t)m * 1024 + k0 + k4);
            As[k4 + 0][m] = v.x; As[k4 + 1][m] = v.y;
            As[k4 + 2][m] = v.z; As[k4 + 3][m] = v.w;
        }
        {
            int k = t >> 4, n4 = (t & 15) << 2;
            *(float4*)&Bs[k][n4] = *(const float4*)(Wv + (size_t)(k0 + k) * 2048 + n4);
        }
        __syncthreads();
#pragma unroll
        for (int kk = 0; kk < 16; kk++) {
            float4 a  = *(const float4*)&As[kk][tyy * 4];
            float4 bb = *(const float4*)&Bs[kk][txx * 4];
            float av[4] = {a.x, a.y, a.z, a.w};
            float bv[4] = {bb.x, bb.y, bb.z, bb.w};
#pragma unroll
            for (int i = 0; i < 4; i++)
#pragma unroll
                for (int jj = 0; jj < 4; jj++) acc[i][jj] += av[i] * bv[jj];
        }
        __syncthreads();
    }
#pragma unroll
    for (int i = 0; i < 4; i++) {
        int m = tyy * 4 + i;
        float nrm = g_norm[b * 1024 + h * 64 + m];
        float inv = 1.0f / (nrm + 1e-5f);
#pragma unroll
        for (int jj = 0; jj < 4; jj++) {
            int d = txx * 4 + jj;
            float bvv = b_kv[1024 + h * 64 + d];
            g_st[((size_t)z * 64 + m) * 64 + d] = (acc[i][jj] + nrm * bvv) * inv;
        }
    }
}

__global__ void __launch_bounds__(64)
k_qkv(const float* __restrict__ qkv_proj)
{
    int z = blockIdx.x;
    int h = (z >> 6) & 15;
    int d = threadIdx.x;
    __shared__ float st[64];
    __shared__ float ex[64];
    st[d] = g_st[(size_t)z * 64 + d];
    __syncthreads();
    const float* P = qkv_proj + (size_t)h * 64 * 192;
    float q = 0.f, k = 0.f, v = 0.f;
#pragma unroll 8
    for (int j = 0; j < 64; j++) {
        float s = st[j];
        const float* pr = P + j * 192;
        q += s * pr[d]; k += s * pr[64 + d]; v += s * pr[128 + d];
    }
    float dot = q * k * 0.125f;
    ex[d] = dot;
    __syncthreads();
    float mx = -1e30f;
    for (int j = 0; j < 64; j++) mx = fmaxf(mx, ex[j]);
    __syncthreads();
    float e = expf(dot - mx);
    ex[d] = e;
    __syncthreads();
    float sum = 0.f;
    for (int j = 0; j < 64; j++) sum += ex[j];
    g_ost[(size_t)z * 64 + d] = (e / sum) * v;
}

__global__ void __launch_bounds__(256)
k_zmat(const float* __restrict__ w_out)
{
    int z = blockIdx.y, jc = blockIdx.x;
    int b = z >> 4, h = z & 15;
    __shared__ float As[64][64];
    __shared__ float Bs[64][64];
    int t = threadIdx.x;
#pragma unroll
    for (int r = 0; r < 4; r++) {
        int lin = t + r * 256;
        int row = lin >> 4;
        int c4  = (lin & 15) << 2;
        float4 v = *(const float4*)(g_ost + ((size_t)z * 64 + row) * 64 + c4);
        As[c4 + 0][row] = v.x; As[c4 + 1][row] = v.y;
        As[c4 + 2][row] = v.z; As[c4 + 3][row] = v.w;
        *(float4*)&Bs[row][c4] =
            *(const float4*)(w_out + (size_t)(h * 64 + row) * 1024 + jc * 64 + c4);
    }
    __syncthreads();
    int tyy = t >> 4, txx = t & 15;
    float acc[4][4] = {};
#pragma unroll
    for (int kk = 0; kk < 64; kk++) {
        float4 a  = *(const float4*)&As[kk][tyy * 4];
        float4 bb = *(const float4*)&Bs[kk][txx * 4];
        float av[4] = {a.x, a.y, a.z, a.w};
        float bv[4] = {bb.x, bb.y, bb.z, bb.w};
#pragma unroll
        for (int i = 0; i < 4; i++)
#pragma unroll
            for (int jj = 0; jj < 4; jj++) acc[i][jj] += av[i] * bv[jj];
    }
#pragma unroll
    for (int i = 0; i < 4; i++) {
        int hm = h * 64 + tyy * 4 + i;
#pragma unroll
        for (int jj = 0; jj < 4; jj++) {
            int j = jc * 64 + txx * 4 + jj;
            g_Ztf[((size_t)b * 1024 + j) * 1024 + hm] = __float2half(acc[i][jj]);
        }
    }
}

// ---------------------------------------------------------------------------
extern "C" void kernel_launch(void* const* d_in, const int* in_sizes, int n_in,
                              void* d_out, int out_size)
{
    (void)in_sizes; (void)n_in; (void)out_size;
    const float* x      = (const float*)d_in[0];
    const float* w_kv   = (const float*)d_in[2];
    const float* b_kv   = (const float*)d_in[3];
    const float* w_temp = (const float*)d_in[4];
    const float* b_temp = (const float*)d_in[5];
    const float* xq     = (const float*)d_in[6];
    const float* qkv_p  = (const float*)d_in[7];
    const float* w_out  = (const float*)d_in[8];
    const float* b_out  = (const float*)d_in[9];
    float* out = (float*)d_out;

    float *pc, *pyp;
    __half *pxfh, *pxtf, *pSf, *pSft, *pAtf, *pZtf;
    cudaGetSymbolAddress((void**)&pc,  g_c);
    cudaGetSymbolAddress((void**)&pyp, g_yp);
    cudaGetSymbolAddress((void**)&pxfh, g_xfh);
    cudaGetSymbolAddress((void**)&pxtf, g_xtf);
    cudaGetSymbolAddress((void**)&pSf, g_Sf);   cudaGetSymbolAddress((void**)&pSft, g_Sft);
    cudaGetSymbolAddress((void**)&pAtf, g_Atf);
    cudaGetSymbolAddress((void**)&pZtf, g_Ztf);

    cudaFuncSetAttribute(mma_scores,   cudaFuncAttributeMaxDynamicSharedMemorySize, GSMEMS);
    cudaFuncSetAttribute(mma1_gemm<0>, cudaFuncAttributeMaxDynamicSharedMemorySize, GSMEM1);
    cudaFuncSetAttribute(mma1_gemm<1>, cudaFuncAttributeMaxDynamicSharedMemorySize, GSMEM1);
    cudaFuncSetAttribute(k_tempmma,    cudaFuncAttributeMaxDynamicSharedMemorySize, TGSMEM);

    // fused prologue: convx + prep + wsplit + zero
    k_aux<<<12368, 256>>>(x, xq, w_kv, b_kv, w_temp);
    k_tempmma<<<256, 256, TGSMEM>>>(pxfh, b_temp);
    // scores (fp16 single-pass) + fused softmax/norm/fp16 stores
    mma_scores<<<dim3(4, 256, 1), 512, GSMEMS>>>(pxfh, pAtf, pc);
    // y[b] = S[b]^T @ x[b] (fp16 single-pass), K-split x8
    mma1_gemm<0><<<dim3(4, 8, cB * 8), 512, GSMEM1>>>(
        pSft, pxtf, pyp, nullptr,
        1024, 8192, 8192, 1024,
        (long long)cHM * cN, (long long)cH * cN,
        (long long)cHM * cH, (long long)cB * cHM * cH, 3);
    k_yred<<<4096, 256>>>();
    k_st<<<cB * cNH, 256>>>(w_kv, b_kv);
    k_qkv<<<cB * cNH * 64, 64>>>(qkv_p);
    k_zmat<<<dim3(16, cB * cNH), 256>>>(w_out);
    // out[b] = S[b] @ Zt[b]^T + b_out (fp16 single-pass)
    mma1_gemm<1><<<dim3(4, 64, cB), 512, GSMEM1>>>(
        pSf, pZtf, out, b_out,
        1024, 1024, 1024, 1024,
        (long long)cN * cHM, (long long)cH * cHM,
        (long long)cN * cH, 0, 0);
}